// round 10
// baseline (speedup 1.0000x reference)
#include <cuda_runtime.h>
#include <cuda_bf16.h>
#include <math.h>
#include <stdint.h>

#define N_NODES 50000
#define D_FEAT  364
#define D_OUT   150
#define N_PAIRS 8192
#define N_EDGES 200000
#define NEG_SLOPE 0.01f

#define AKP 192          // padded kp (k/2) per row for A (K padded to 384)
#define WB_NS 384        // padded n stride for converted W

// Scratch (no cudaMalloc allowed).
__device__ __align__(16) float g_h1 [(size_t)N_NODES * D_FEAT];
__device__ __align__(16) float g_h2 [(size_t)N_NODES * D_FEAT];
__device__ __align__(16) float g_z  [(size_t)2 * N_PAIRS * D_OUT];
// bf16-split A (agg) and W, packed bf16x2 along k (uint32 = {k even lo, k odd hi})
__device__ __align__(16) uint32_t g_agg_h[(size_t)N_NODES * AKP];
__device__ __align__(16) uint32_t g_agg_l[(size_t)N_NODES * AKP];
__device__ __align__(16) uint32_t g_wb_h [(size_t)AKP * WB_NS];   // [kp][n]
__device__ __align__(16) uint32_t g_wb_l [(size_t)AKP * WB_NS];

// CSR-by-dst scratch
__device__ int g_deg [N_NODES];
__device__ int g_off [N_NODES];
__device__ int g_pos [N_NODES];
__device__ int g_srcs[N_EDGES];

// ---------------------------------------------------------------------------
// bf16 split helpers
__device__ __forceinline__ void split1(float v, __nv_bfloat16& h, __nv_bfloat16& l) {
    h = __float2bfloat16_rn(v);
    l = __float2bfloat16_rn(v - __bfloat162float(h));
}
__device__ __forceinline__ uint32_t pack2(__nv_bfloat16 lo, __nv_bfloat16 hi) {
    __nv_bfloat162 p;
    p.x = lo; p.y = hi;
    return *reinterpret_cast<uint32_t*>(&p);
}

// ---------------------------------------------------------------------------
// CSR build
__global__ void csr_zero_kernel() {
    int i = blockIdx.x * blockDim.x + threadIdx.x;
    if (i < N_NODES) g_deg[i] = 0;
}
__global__ void csr_count_kernel(const int* __restrict__ dst) {
    int e = blockIdx.x * blockDim.x + threadIdx.x;
    if (e < N_EDGES) atomicAdd(&g_deg[dst[e]], 1);
}
__global__ void csr_scan_kernel() {
    __shared__ int warp_tot[32];
    __shared__ int carry_sh;
    int tid = threadIdx.x;
    int lane = tid & 31, w = tid >> 5;
    if (tid == 0) carry_sh = 0;
    __syncthreads();
    for (int base = 0; base < N_NODES; base += 1024) {
        int i = base + tid;
        int v = (i < N_NODES) ? g_deg[i] : 0;
        int s = v;
        #pragma unroll
        for (int o = 1; o < 32; o <<= 1) {
            int t = __shfl_up_sync(0xFFFFFFFFu, s, o);
            if (lane >= o) s += t;
        }
        if (lane == 31) warp_tot[w] = s;
        __syncthreads();
        if (w == 0) {
            int t = warp_tot[lane];
            int ss = t;
            #pragma unroll
            for (int o = 1; o < 32; o <<= 1) {
                int u = __shfl_up_sync(0xFFFFFFFFu, ss, o);
                if (lane >= o) ss += u;
            }
            warp_tot[lane] = ss - t;
        }
        __syncthreads();
        int incl = s + warp_tot[w];
        int off  = carry_sh + incl - v;
        if (i < N_NODES) { g_off[i] = off; g_pos[i] = off; }
        __syncthreads();
        if (tid == 1023) carry_sh += incl;
        __syncthreads();
    }
}
__global__ void csr_fill_kernel(const int* __restrict__ src,
                                const int* __restrict__ dst) {
    int e = blockIdx.x * blockDim.x + threadIdx.x;
    if (e >= N_EDGES) return;
    int idx = atomicAdd(&g_pos[dst[e]], 1);
    g_srcs[idx] = src[e];
}

// ---------------------------------------------------------------------------
// gather + bf16 split. Warp-preloaded src indices + 2x edge unroll for MLP.
__global__ void gather_kernel(const float* __restrict__ x_ext, int layer) {
    int node = (blockIdx.x * blockDim.x + threadIdx.x) >> 5;
    int lane = threadIdx.x & 31;
    if (node >= N_NODES) return;
    const float* __restrict__ x = (layer == 0) ? x_ext : g_h1;
    int off = g_off[node];
    int deg = g_deg[node];
    // preload first min(deg,32) src indices across lanes (no per-iter scalar load)
    int s_pre = (lane < deg) ? g_srcs[off + lane] : 0;

    const float4* xd = reinterpret_cast<const float4*>(x + (size_t)node * D_FEAT);
    bool has2 = lane < 27;   // lane+64 < 91 float4 per row
    float4 a0 = xd[lane];
    float4 a1 = xd[lane + 32];
    float4 a2 = has2 ? xd[lane + 64] : make_float4(0.f, 0.f, 0.f, 0.f);

    int dmin = deg < 32 ? deg : 32;
    int e = 0;
    for (; e + 2 <= dmin; e += 2) {
        int s0 = __shfl_sync(0xFFFFFFFFu, s_pre, e);
        int s1 = __shfl_sync(0xFFFFFFFFu, s_pre, e + 1);
        const float4* xs0 = reinterpret_cast<const float4*>(x + (size_t)s0 * D_FEAT);
        const float4* xs1 = reinterpret_cast<const float4*>(x + (size_t)s1 * D_FEAT);
        float4 u0 = xs0[lane],      w0 = xs1[lane];
        float4 u1 = xs0[lane + 32], w1 = xs1[lane + 32];
        float4 u2, w2;
        if (has2) { u2 = xs0[lane + 64]; w2 = xs1[lane + 64]; }
        a0.x += u0.x + w0.x; a0.y += u0.y + w0.y; a0.z += u0.z + w0.z; a0.w += u0.w + w0.w;
        a1.x += u1.x + w1.x; a1.y += u1.y + w1.y; a1.z += u1.z + w1.z; a1.w += u1.w + w1.w;
        if (has2) {
            a2.x += u2.x + w2.x; a2.y += u2.y + w2.y;
            a2.z += u2.z + w2.z; a2.w += u2.w + w2.w;
        }
    }
    for (; e < dmin; e++) {
        int s = __shfl_sync(0xFFFFFFFFu, s_pre, e);
        const float4* xs = reinterpret_cast<const float4*>(x + (size_t)s * D_FEAT);
        float4 v0 = xs[lane];
        float4 v1 = xs[lane + 32];
        a0.x += v0.x; a0.y += v0.y; a0.z += v0.z; a0.w += v0.w;
        a1.x += v1.x; a1.y += v1.y; a1.z += v1.z; a1.w += v1.w;
        if (has2) {
            float4 v2 = xs[lane + 64];
            a2.x += v2.x; a2.y += v2.y; a2.z += v2.z; a2.w += v2.w;
        }
    }
    for (; e < deg; e++) {   // rare (deg > 32)
        int s = g_srcs[off + e];
        const float4* xs = reinterpret_cast<const float4*>(x + (size_t)s * D_FEAT);
        float4 v0 = xs[lane];
        float4 v1 = xs[lane + 32];
        a0.x += v0.x; a0.y += v0.y; a0.z += v0.z; a0.w += v0.w;
        a1.x += v1.x; a1.y += v1.y; a1.z += v1.z; a1.w += v1.w;
        if (has2) {
            float4 v2 = xs[lane + 64];
            a2.x += v2.x; a2.y += v2.y; a2.z += v2.z; a2.w += v2.w;
        }
    }

    uint32_t* oh = g_agg_h + (size_t)node * AKP;
    uint32_t* ol = g_agg_l + (size_t)node * AKP;
    float4 chunks[3] = {a0, a1, a2};
    #pragma unroll
    for (int i = 0; i < 3; i++) {
        int k4 = lane + 32 * i;
        float4 v = chunks[i];
        bool valid = (i < 2) || has2;
        if (!valid) v = make_float4(0.f, 0.f, 0.f, 0.f);
        __nv_bfloat16 hx, lx, hy, ly, hz, lz, hw, lw;
        split1(v.x, hx, lx); split1(v.y, hy, ly);
        split1(v.z, hz, lz); split1(v.w, hw, lw);
        uint2 ph = make_uint2(pack2(hx, hy), pack2(hz, hw));
        uint2 pl = make_uint2(pack2(lx, ly), pack2(lz, lw));
        *reinterpret_cast<uint2*>(oh + 2 * k4) = ph;
        *reinterpret_cast<uint2*>(ol + 2 * k4) = pl;
    }
}

// ---------------------------------------------------------------------------
// convert W [K x N] fp32 -> g_wb_h/l
__global__ void convert_w_kernel(const float* __restrict__ W) {
    int idx = blockIdx.x * blockDim.x + threadIdx.x;
    int kp = idx / (WB_NS / 4);
    int nq = idx % (WB_NS / 4);
    if (kp >= AKP) return;
    int n0 = nq * 4;
    uint32_t oh[4], ol[4];
    #pragma unroll
    for (int j = 0; j < 4; j++) {
        int n = n0 + j;
        float v0 = 0.f, v1 = 0.f;
        if (2 * kp < D_FEAT && n < D_FEAT) {
            v0 = W[(size_t)(2 * kp) * D_FEAT + n];
            v1 = W[(size_t)(2 * kp + 1) * D_FEAT + n];
        }
        __nv_bfloat16 h0, l0, h1, l1;
        split1(v0, h0, l0);
        split1(v1, h1, l1);
        oh[j] = pack2(h0, h1);
        ol[j] = pack2(l0, l1);
    }
    size_t o = (size_t)kp * WB_NS + n0;
    *reinterpret_cast<uint4*>(g_wb_h + o) = make_uint4(oh[0], oh[1], oh[2], oh[3]);
    *reinterpret_cast<uint4*>(g_wb_l + o) = make_uint4(ol[0], ol[1], ol[2], ol[3]);
}

// ---------------------------------------------------------------------------
__device__ __forceinline__ void mma16(float d[4], const uint32_t a[4], const uint32_t b[2]) {
    asm volatile(
        "mma.sync.aligned.m16n8k16.row.col.f32.bf16.bf16.f32 "
        "{%0,%1,%2,%3}, {%4,%5,%6,%7}, {%8,%9}, {%0,%1,%2,%3};\n"
        : "+f"(d[0]), "+f"(d[1]), "+f"(d[2]), "+f"(d[3])
        : "r"(a[0]), "r"(a[1]), "r"(a[2]), "r"(a[3]), "r"(b[0]), "r"(b[1]));
}
__device__ __forceinline__ void ldsm_x4(uint32_t f[4], uint32_t saddr) {
    asm volatile(
        "ldmatrix.sync.aligned.m8n8.x4.shared.b16 {%0,%1,%2,%3}, [%4];"
        : "=r"(f[0]), "=r"(f[1]), "=r"(f[2]), "=r"(f[3])
        : "r"(saddr));
}

// ---------------------------------------------------------------------------
// node GEMM: bf16x3, pipelined double buffer, A frags via ldmatrix.
#define TC_BM 128
#define TC_BN 128
#define AS2 36
#define BS2 136
#define A_U32 (TC_BM * AS2)
#define B_U32 (16 * BS2)
#define STAGE_U32 (2 * A_U32 + 2 * B_U32)   // 13568
#define NUM_KT 12

__global__ __launch_bounds__(256) void gemm_nodes_tc(
        const float* __restrict__ bias, int out_sel) {
    const int M = N_NODES, N = D_FEAT;
    float* __restrict__ out = out_sel ? g_h2 : g_h1;

    extern __shared__ uint32_t smu[];
    uint32_t smem_base = (uint32_t)__cvta_generic_to_shared(smu);

    int bm = blockIdx.y * TC_BM;
    int bn = blockIdx.x * TC_BN;
    int tid = threadIdx.x;
    int lane = tid & 31;
    int wid = tid >> 5;
    int wm = (wid & 1) * 64;
    int wn = (wid >> 1) * 32;
    int r = lane >> 2;
    int c = lane & 3;

    // ldmatrix lane address components (A): row within 16-row tile + col half
    int lm_row = lane & 15;
    int lm_col = (lane >> 4) * 4;
    uint32_t a_lane_off = (uint32_t)(((wm + lm_row) * AS2 + lm_col) * 4);

    float acc[4][4][4];
    #pragma unroll
    for (int i = 0; i < 4; i++)
        #pragma unroll
        for (int j = 0; j < 4; j++)
            #pragma unroll
            for (int q = 0; q < 4; q++) acc[i][j][q] = 0.f;

    int a_row = tid >> 2;
    int a_q4  = tid & 3;
    int b_kp = tid >> 5;
    int b_n4 = tid & 31;

    uint4 apf_h[2], apf_l[2], bpf_h[2], bpf_l[2];

    auto load_tile = [&](int t) {
        int kp0 = t * 16;
        #pragma unroll
        for (int p = 0; p < 2; p++) {
            int gm = bm + p * 64 + a_row;
            if (gm < M) {
                size_t o = (size_t)gm * AKP + kp0 + a_q4 * 4;
                apf_h[p] = *reinterpret_cast<const uint4*>(g_agg_h + o);
                apf_l[p] = *reinterpret_cast<const uint4*>(g_agg_l + o);
            } else {
                apf_h[p] = make_uint4(0, 0, 0, 0);
                apf_l[p] = make_uint4(0, 0, 0, 0);
            }
        }
        #pragma unroll
        for (int p = 0; p < 2; p++) {
            size_t o = (size_t)(kp0 + p * 8 + b_kp) * WB_NS + bn + b_n4 * 4;
            bpf_h[p] = *reinterpret_cast<const uint4*>(g_wb_h + o);
            bpf_l[p] = *reinterpret_cast<const uint4*>(g_wb_l + o);
        }
    };
    auto store_tile = [&](int stage) {
        uint32_t* base = smu + stage * STAGE_U32;
        uint32_t* As_h = base;
        uint32_t* As_l = base + A_U32;
        uint32_t* Bs_h = base + 2 * A_U32;
        uint32_t* Bs_l = Bs_h + B_U32;
        #pragma unroll
        for (int p = 0; p < 2; p++) {
            int m = p * 64 + a_row;
            *reinterpret_cast<uint4*>(As_h + m * AS2 + a_q4 * 4) = apf_h[p];
            *reinterpret_cast<uint4*>(As_l + m * AS2 + a_q4 * 4) = apf_l[p];
        }
        #pragma unroll
        for (int p = 0; p < 2; p++) {
            int kp = p * 8 + b_kp;
            *reinterpret_cast<uint4*>(Bs_h + kp * BS2 + b_n4 * 4) = bpf_h[p];
            *reinterpret_cast<uint4*>(Bs_l + kp * BS2 + b_n4 * 4) = bpf_l[p];
        }
    };

    load_tile(0);
    store_tile(0);
    __syncthreads();

    for (int t = 0; t < NUM_KT; t++) {
        if (t + 1 < NUM_KT) load_tile(t + 1);

        {
            uint32_t stage_off = (uint32_t)((t & 1) * STAGE_U32 * 4);
            uint32_t ah_base = smem_base + stage_off + a_lane_off;
            uint32_t al_base = ah_base + (uint32_t)(A_U32 * 4);
            const uint32_t* base = smu + (t & 1) * STAGE_U32;
            const uint32_t* Bs_h = base + 2 * A_U32;
            const uint32_t* Bs_l = Bs_h + B_U32;

            #pragma unroll
            for (int kk = 0; kk < 2; kk++) {
                uint32_t ah[4][4], al[4][4], bh[4][2], bl[4][2];
                #pragma unroll
                for (int mt = 0; mt < 4; mt++) {
                    uint32_t moff = (uint32_t)((mt * 16 * AS2 + kk * 8) * 4);
                    ldsm_x4(ah[mt], ah_base + moff);
                    ldsm_x4(al[mt], al_base + moff);
                }
                #pragma unroll
                for (int nt = 0; nt < 4; nt++) {
                    int col = wn + nt * 8 + r;
                    const uint32_t* qh = Bs_h + (kk * 8 + c) * BS2 + col;
                    const uint32_t* ql = Bs_l + (kk * 8 + c) * BS2 + col;
                    bh[nt][0] = qh[0];
                    bh[nt][1] = qh[4 * BS2];
                    bl[nt][0] = ql[0];
                    bl[nt][1] = ql[4 * BS2];
                }
                #pragma unroll
                for (int mt = 0; mt < 4; mt++)
                    #pragma unroll
                    for (int nt = 0; nt < 4; nt++) {
                        mma16(acc[mt][nt], ah[mt], bh[nt]);
                        mma16(acc[mt][nt], al[mt], bh[nt]);
                        mma16(acc[mt][nt], ah[mt], bl[nt]);
                    }
            }
        }

        if (t + 1 < NUM_KT) store_tile((t + 1) & 1);
        __syncthreads();
    }

    #pragma unroll
    for (int mt = 0; mt < 4; mt++) {
        int gm0 = bm + wm + mt * 16 + r;
        #pragma unroll
        for (int nt = 0; nt < 4; nt++) {
            int gn = bn + wn + nt * 8 + 2 * c;
            if (gn >= N) continue;
            float b0 = bias[gn], b1 = bias[gn + 1];
            float v0 = acc[mt][nt][0] + b0;
            float v1 = acc[mt][nt][1] + b1;
            float v2 = acc[mt][nt][2] + b0;
            float v3 = acc[mt][nt][3] + b1;
            v0 = v0 > 0.f ? v0 : NEG_SLOPE * v0;
            v1 = v1 > 0.f ? v1 : NEG_SLOPE * v1;
            v2 = v2 > 0.f ? v2 : NEG_SLOPE * v2;
            v3 = v3 > 0.f ? v3 : NEG_SLOPE * v3;
            if (gm0 < M)
                *reinterpret_cast<float2*>(out + (size_t)gm0 * N + gn) = make_float2(v0, v1);
            if (gm0 + 8 < M)
                *reinterpret_cast<float2*>(out + (size_t)(gm0 + 8) * N + gn) = make_float2(v2, v3);
        }
    }
}

// ---------------------------------------------------------------------------
// tf32 helpers for pairs GEMM
__device__ __forceinline__ uint32_t f2tf32(float x) {
    uint32_t r;
    asm("cvt.rna.tf32.f32 %0, %1;" : "=r"(r) : "f"(x));
    return r;
}
__device__ __forceinline__ void split_tf32(float v, float& h, float& l) {
    h = __uint_as_float(f2tf32(v));
    l = __uint_as_float(f2tf32(v - h));
}
__device__ __forceinline__ void mma8(float d[4], const uint32_t a[4], const uint32_t b[2]) {
    asm volatile(
        "mma.sync.aligned.m16n8k8.row.col.f32.tf32.tf32.f32 "
        "{%0,%1,%2,%3}, {%4,%5,%6,%7}, {%8,%9}, {%0,%1,%2,%3};\n"
        : "+f"(d[0]), "+f"(d[1]), "+f"(d[2]), "+f"(d[3])
        : "r"(a[0]), "r"(a[1]), "r"(a[2]), "r"(a[3]), "r"(b[0]), "r"(b[1]));
}

// ---------------------------------------------------------------------------
// pairs GEMM (tf32x3)
#define P_BN 64
#define P_BK 32
#define PAS 36
#define PBS 72
#define P_A_FLOATS (TC_BM * PAS)
#define P_B_FLOATS (P_BK * PBS)
#define P_SMEM_FLOATS (2 * P_A_FLOATS + 2 * P_B_FLOATS)

__global__ __launch_bounds__(256) void gemm_pairs_tc(
        const int* __restrict__ v1, const int* __restrict__ v2,
        const float* __restrict__ W, const float* __restrict__ bias) {
    const int K = D_FEAT, N = D_OUT;

    extern __shared__ float smf[];
    float* As_h = smf;
    float* As_l = smf + P_A_FLOATS;
    float* Bs_h = smf + 2 * P_A_FLOATS;
    float* Bs_l = Bs_h + P_B_FLOATS;
    __shared__ int rows[TC_BM];

    int bm = blockIdx.y * TC_BM;
    int bn = blockIdx.x * P_BN;
    int tid = threadIdx.x;
    int lane = tid & 31;
    int wid = tid >> 5;
    int wm = (wid & 3) * 32;
    int wn = (wid >> 2) * 32;
    int r = lane >> 2;
    int c = lane & 3;

    if (tid < TC_BM) {
        int gm = bm + tid;
        rows[tid] = (gm < N_PAIRS) ? v1[gm] : v2[gm - N_PAIRS];
    }
    __syncthreads();

    float acc[2][4][4];
    #pragma unroll
    for (int i = 0; i < 2; i++)
        #pragma unroll
        for (int j = 0; j < 4; j++)
            #pragma unroll
            for (int q = 0; q < 4; q++) acc[i][j][q] = 0.f;

    int ak4 = tid & 7;
    int arl = tid >> 3;
    int bn4 = tid & 15;
    int bkr = tid >> 4;

    for (int k0 = 0; k0 < K; k0 += P_BK) {
        #pragma unroll
        for (int p = 0; p < 4; p++) {
            int m = p * 32 + arl;
            int node = rows[m];
            int gk = k0 + ak4 * 4;
            float4 v = (gk < K)
                ? *reinterpret_cast<const float4*>(g_h2 + (size_t)node * K + gk)
                : make_float4(0.f, 0.f, 0.f, 0.f);
            float4 h, l;
            split_tf32(v.x, h.x, l.x);
            split_tf32(v.y, h.y, l.y);
            split_tf32(v.z, h.z, l.z);
            split_tf32(v.w, h.w, l.w);
            *reinterpret_cast<float4*>(As_h + m * PAS + ak4 * 4) = h;
            *reinterpret_cast<float4*>(As_l + m * PAS + ak4 * 4) = l;
        }
        #pragma unroll
        for (int p = 0; p < 2; p++) {
            int kr = p * 16 + bkr;
            int gk = k0 + kr;
            int gn = bn + bn4 * 4;
            float4 v = make_float4(0.f, 0.f, 0.f, 0.f);
            if (gk < K) {
                const float* wrow = W + (size_t)gk * N;
                if (gn + 3 < N) {
                    float2 lo = *reinterpret_cast<const float2*>(wrow + gn);
                    float2 hi = *reinterpret_cast<const float2*>(wrow + gn + 2);
                    v = make_float4(lo.x, lo.y, hi.x, hi.y);
                } else {
                    #pragma unroll
                    for (int j = 0; j < 4; j++) {
                        int nn = gn + j;
                        reinterpret_cast<float*>(&v)[j] = (nn < N) ? wrow[nn] : 0.f;
                    }
                }
            }
            float4 h, l;
            split_tf32(v.x, h.x, l.x);
            split_tf32(v.y, h.y, l.y);
            split_tf32(v.z, h.z, l.z);
            split_tf32(v.w, h.w, l.w);
            *reinterpret_cast<float4*>(Bs_h + kr * PBS + bn4 * 4) = h;
            *reinterpret_cast<float4*>(Bs_l + kr * PBS + bn4 * 4) = l;
        }
        __syncthreads();

        #pragma unroll
        for (int kk = 0; kk < 4; kk++) {
            uint32_t ah[2][4], al[2][4], bh[4][2], bl[4][2];
            #pragma unroll
            for (int mt = 0; mt < 2; mt++) {
                int row = wm + mt * 16 + r;
                const float* ph = As_h + row * PAS + kk * 8 + c;
                const float* pl = As_l + row * PAS + kk * 8 + c;
                ah[mt][0] = __float_as_uint(ph[0]);
                ah[mt][1] = __float_as_uint(ph[8 * PAS]);
                ah[mt][2] = __float_as_uint(ph[4]);
                ah[mt][3] = __float_as_uint(ph[8 * PAS + 4]);
                al[mt][0] = __float_as_uint(pl[0]);
                al[mt][1] = __float_as_uint(pl[8 * PAS]);
                al[mt][2] = __float_as_uint(pl[4]);
                al[mt][3] = __float_as_uint(pl[8 * PAS + 4]);
            }
            #pragma unroll
            for (int nt = 0; nt < 4; nt++) {
                int col = wn + nt * 8 + r;
                const float* qh = Bs_h + (kk * 8 + c) * PBS + col;
                const float* ql = Bs_l + (kk * 8 + c) * PBS + col;
                bh[nt][0] = __float_as_uint(qh[0]);
                bh[nt][1] = __float_as_uint(qh[4 * PBS]);
                bl[nt][0] = __float_as_uint(ql[0]);
                bl[nt][1] = __float_as_uint(ql[4 * PBS]);
            }
            #pragma unroll
            for (int mt = 0; mt < 2; mt++)
                #pragma unroll
                for (int nt = 0; nt < 4; nt++) {
                    mma8(acc[mt][nt], ah[mt], bh[nt]);
                    mma8(acc[mt][nt], al[mt], bh[nt]);
                    mma8(acc[mt][nt], ah[mt], bl[nt]);
                }
        }
        __syncthreads();
    }

    #pragma unroll
    for (int mt = 0; mt < 2; mt++) {
        int gm0 = bm + wm + mt * 16 + r;
        #pragma unroll
        for (int nt = 0; nt < 4; nt++) {
            int gn = bn + wn + nt * 8 + 2 * c;
            if (gn >= N) continue;
            float b0 = bias[gn], b1 = bias[gn + 1];
            float v0 = acc[mt][nt][0] + b0;
            float v1 = acc[mt][nt][1] + b1;
            float v2 = acc[mt][nt][2] + b0;
            float v3 = acc[mt][nt][3] + b1;
            v0 = v0 > 0.f ? v0 : NEG_SLOPE * v0;
            v1 = v1 > 0.f ? v1 : NEG_SLOPE * v1;
            v2 = v2 > 0.f ? v2 : NEG_SLOPE * v2;
            v3 = v3 > 0.f ? v3 : NEG_SLOPE * v3;
            *reinterpret_cast<float2*>(g_z + (size_t)gm0 * N + gn) = make_float2(v0, v1);
            *reinterpret_cast<float2*>(g_z + (size_t)(gm0 + 8) * N + gn) = make_float2(v2, v3);
        }
    }
}

// ---------------------------------------------------------------------------
__global__ void normalize_kernel(float* __restrict__ out) {
    int row  = (blockIdx.x * blockDim.x + threadIdx.x) >> 5;
    int lane = threadIdx.x & 31;
    if (row >= 2 * N_PAIRS) return;
    const float* zr = g_z + (size_t)row * D_OUT;
    float ss = 0.f;
    for (int i = lane; i < D_OUT; i += 32) { float v = zr[i]; ss += v * v; }
    #pragma unroll
    for (int o = 16; o; o >>= 1) ss += __shfl_xor_sync(0xFFFFFFFFu, ss, o);
    float norm = sqrtf(ss);
    float inv = 1.f / fmaxf(norm, 1e-12f);
    for (int i = lane; i < D_OUT; i += 32) out[(size_t)row * D_OUT + i] = zr[i] * inv;
}

// ---------------------------------------------------------------------------
extern "C" void kernel_launch(void* const* d_in, const int* in_sizes, int n_in,
                              void* d_out, int out_size) {
    const float* features = (const float*)d_in[0];
    const int*   src      = (const int*)  d_in[1];
    const int*   dst      = (const int*)  d_in[2];
    const int*   v1       = (const int*)  d_in[3];
    const int*   v2       = (const int*)  d_in[4];
    const float* W1       = (const float*)d_in[5];
    const float* b1       = (const float*)d_in[6];
    const float* W2       = (const float*)d_in[7];
    const float* b2       = (const float*)d_in[8];
    const float* W3       = (const float*)d_in[9];
    const float* b3       = (const float*)d_in[10];
    float* out = (float*)d_out;
    (void)in_sizes; (void)n_in; (void)out_size;

    size_t tc_smem = (size_t)2 * STAGE_U32 * sizeof(uint32_t);      // 108544 B
    cudaFuncSetAttribute(gemm_nodes_tc, cudaFuncAttributeMaxDynamicSharedMemorySize,
                         (int)tc_smem);
    size_t p_smem = (size_t)P_SMEM_FLOATS * sizeof(float);
    cudaFuncSetAttribute(gemm_pairs_tc, cudaFuncAttributeMaxDynamicSharedMemorySize,
                         (int)p_smem);

    dim3 tc_grid((D_FEAT + TC_BN - 1) / TC_BN, (N_NODES + TC_BM - 1) / TC_BM);
    dim3 pairs_grid((D_OUT + P_BN - 1) / P_BN, (2 * N_PAIRS) / TC_BM);
    int gather_blocks = (N_NODES * 32 + 255) / 256;
    int convw_blocks = (AKP * (WB_NS / 4) + 255) / 256;

    // CSR by dst (reused for both layers)
    csr_zero_kernel<<<(N_NODES + 255) / 256, 256>>>();
    csr_count_kernel<<<(N_EDGES + 255) / 256, 256>>>(dst);
    csr_scan_kernel<<<1, 1024>>>();
    csr_fill_kernel<<<(N_EDGES + 255) / 256, 256>>>(src, dst);

    // layer 1
    convert_w_kernel<<<convw_blocks, 256>>>(W1);
    gather_kernel<<<gather_blocks, 256>>>(features, 0);
    gemm_nodes_tc<<<tc_grid, 256, tc_smem>>>(b1, /*out_sel=*/0);

    // layer 2
    convert_w_kernel<<<convw_blocks, 256>>>(W2);
    gather_kernel<<<gather_blocks, 256>>>(nullptr, 1);
    gemm_nodes_tc<<<tc_grid, 256, tc_smem>>>(b2, /*out_sel=*/1);

    // pair projection + normalize
    gemm_pairs_tc<<<pairs_grid, 256, p_smem>>>(v1, v2, W3, b3);
    normalize_kernel<<<(2 * N_PAIRS * 32 + 255) / 256, 256>>>(out);
}

// round 11
// speedup vs baseline: 1.1281x; 1.1281x over previous
#include <cuda_runtime.h>
#include <cuda_bf16.h>
#include <math.h>
#include <stdint.h>

#define N_NODES 50000
#define D_FEAT  364
#define D_OUT   150
#define N_PAIRS 8192
#define N_EDGES 200000
#define NEG_SLOPE 0.01f

#define AKP 192          // padded kp (k/2) per row for A (K padded to 384)
#define WB_NS 384        // padded n stride for converted W

// Scratch (no cudaMalloc allowed).
__device__ __align__(16) float g_h1 [(size_t)N_NODES * D_FEAT];
__device__ __align__(16) float g_h2 [(size_t)N_NODES * D_FEAT];
__device__ __align__(16) float g_z  [(size_t)2 * N_PAIRS * D_OUT];
__device__ __align__(16) uint32_t g_agg_h[(size_t)N_NODES * AKP];
__device__ __align__(16) uint32_t g_agg_l[(size_t)N_NODES * AKP];
__device__ __align__(16) uint32_t g_wb_h [(size_t)AKP * WB_NS];
__device__ __align__(16) uint32_t g_wb_l [(size_t)AKP * WB_NS];

// CSR-by-dst scratch
__device__ int g_deg [N_NODES];
__device__ int g_off [N_NODES];
__device__ int g_pos [N_NODES];
__device__ int g_srcs[N_EDGES];

// ---------------------------------------------------------------------------
__device__ __forceinline__ void split1(float v, __nv_bfloat16& h, __nv_bfloat16& l) {
    h = __float2bfloat16_rn(v);
    l = __float2bfloat16_rn(v - __bfloat162float(h));
}
__device__ __forceinline__ uint32_t pack2(__nv_bfloat16 lo, __nv_bfloat16 hi) {
    __nv_bfloat162 p;
    p.x = lo; p.y = hi;
    return *reinterpret_cast<uint32_t*>(&p);
}

// ---------------------------------------------------------------------------
// CSR build
__global__ void csr_zero_kernel() {
    int i = blockIdx.x * blockDim.x + threadIdx.x;
    if (i < N_NODES) g_deg[i] = 0;
}
__global__ void csr_count_kernel(const int* __restrict__ dst) {
    int e = blockIdx.x * blockDim.x + threadIdx.x;
    if (e < N_EDGES) atomicAdd(&g_deg[dst[e]], 1);
}
__global__ void csr_scan_kernel() {
    __shared__ int warp_tot[32];
    __shared__ int carry_sh;
    int tid = threadIdx.x;
    int lane = tid & 31, w = tid >> 5;
    if (tid == 0) carry_sh = 0;
    __syncthreads();
    for (int base = 0; base < N_NODES; base += 1024) {
        int i = base + tid;
        int v = (i < N_NODES) ? g_deg[i] : 0;
        int s = v;
        #pragma unroll
        for (int o = 1; o < 32; o <<= 1) {
            int t = __shfl_up_sync(0xFFFFFFFFu, s, o);
            if (lane >= o) s += t;
        }
        if (lane == 31) warp_tot[w] = s;
        __syncthreads();
        if (w == 0) {
            int t = warp_tot[lane];
            int ss = t;
            #pragma unroll
            for (int o = 1; o < 32; o <<= 1) {
                int u = __shfl_up_sync(0xFFFFFFFFu, ss, o);
                if (lane >= o) ss += u;
            }
            warp_tot[lane] = ss - t;
        }
        __syncthreads();
        int incl = s + warp_tot[w];
        int off  = carry_sh + incl - v;
        if (i < N_NODES) { g_off[i] = off; g_pos[i] = off; }
        __syncthreads();
        if (tid == 1023) carry_sh += incl;
        __syncthreads();
    }
}
__global__ void csr_fill_kernel(const int* __restrict__ src,
                                const int* __restrict__ dst) {
    int e = blockIdx.x * blockDim.x + threadIdx.x;
    if (e >= N_EDGES) return;
    int idx = atomicAdd(&g_pos[dst[e]], 1);
    g_srcs[idx] = src[e];
}

// ---------------------------------------------------------------------------
// gather + bf16 split: TWO warps per node (feature dim split 46/45 float4).
__global__ void gather_kernel(const float* __restrict__ x_ext, int layer) {
    int gw = (blockIdx.x * blockDim.x + threadIdx.x) >> 5;
    int lane = threadIdx.x & 31;
    int node = gw >> 1;
    int half = gw & 1;
    if (node >= N_NODES) return;
    const float* __restrict__ x = (layer == 0) ? x_ext : g_h1;
    int off = g_off[node];
    int deg = g_deg[node];

    int base4 = half * 46;               // half0: [0,46), half1: [46,91)
    int cnt   = half ? 45 : 46;
    int i0 = base4 + lane;               // always < base4+32 <= 78 < 91: valid data
    int i1 = base4 + 32 + lane;
    bool p1 = (32 + lane) < cnt;         // second chunk valid

    const float4* xd = reinterpret_cast<const float4*>(x + (size_t)node * D_FEAT);
    float4 a0 = xd[i0];
    float4 a1 = p1 ? xd[i1] : make_float4(0.f, 0.f, 0.f, 0.f);

    for (int e = 0; e < deg; e++) {
        int s = g_srcs[off + e];
        const float4* xs = reinterpret_cast<const float4*>(x + (size_t)s * D_FEAT);
        float4 v0 = xs[i0];
        a0.x += v0.x; a0.y += v0.y; a0.z += v0.z; a0.w += v0.w;
        if (p1) {
            float4 v1 = xs[i1];
            a1.x += v1.x; a1.y += v1.y; a1.z += v1.z; a1.w += v1.w;
        }
    }

    uint32_t* oh = g_agg_h + (size_t)node * AKP;
    uint32_t* ol = g_agg_l + (size_t)node * AKP;
    {
        __nv_bfloat16 hx, lx, hy, ly, hz, lz, hw, lw;
        split1(a0.x, hx, lx); split1(a0.y, hy, ly);
        split1(a0.z, hz, lz); split1(a0.w, hw, lw);
        *reinterpret_cast<uint2*>(oh + 2 * i0) = make_uint2(pack2(hx, hy), pack2(hz, hw));
        *reinterpret_cast<uint2*>(ol + 2 * i0) = make_uint2(pack2(lx, ly), pack2(lz, lw));
    }
    if (p1) {
        __nv_bfloat16 hx, lx, hy, ly, hz, lz, hw, lw;
        split1(a1.x, hx, lx); split1(a1.y, hy, ly);
        split1(a1.z, hz, lz); split1(a1.w, hw, lw);
        *reinterpret_cast<uint2*>(oh + 2 * i1) = make_uint2(pack2(hx, hy), pack2(hz, hw));
        *reinterpret_cast<uint2*>(ol + 2 * i1) = make_uint2(pack2(lx, ly), pack2(lz, lw));
    }
    // zero-pad k4 = 91..95 (kp 182..191): half1 lanes 13..17 (i1 = 91..95)
    if (half && lane >= 13 && lane <= 17) {
        *reinterpret_cast<uint2*>(oh + 2 * i1) = make_uint2(0u, 0u);
        *reinterpret_cast<uint2*>(ol + 2 * i1) = make_uint2(0u, 0u);
    }
}

// ---------------------------------------------------------------------------
// convert W [K x N] fp32 -> g_wb_h/l
__global__ void convert_w_kernel(const float* __restrict__ W) {
    int idx = blockIdx.x * blockDim.x + threadIdx.x;
    int kp = idx / (WB_NS / 4);
    int nq = idx % (WB_NS / 4);
    if (kp >= AKP) return;
    int n0 = nq * 4;
    uint32_t oh[4], ol[4];
    #pragma unroll
    for (int j = 0; j < 4; j++) {
        int n = n0 + j;
        float v0 = 0.f, v1 = 0.f;
        if (2 * kp < D_FEAT && n < D_FEAT) {
            v0 = W[(size_t)(2 * kp) * D_FEAT + n];
            v1 = W[(size_t)(2 * kp + 1) * D_FEAT + n];
        }
        __nv_bfloat16 h0, l0, h1, l1;
        split1(v0, h0, l0);
        split1(v1, h1, l1);
        oh[j] = pack2(h0, h1);
        ol[j] = pack2(l0, l1);
    }
    size_t o = (size_t)kp * WB_NS + n0;
    *reinterpret_cast<uint4*>(g_wb_h + o) = make_uint4(oh[0], oh[1], oh[2], oh[3]);
    *reinterpret_cast<uint4*>(g_wb_l + o) = make_uint4(ol[0], ol[1], ol[2], ol[3]);
}

// ---------------------------------------------------------------------------
__device__ __forceinline__ void mma16(float d[4], const uint32_t a[4], const uint32_t b[2]) {
    asm volatile(
        "mma.sync.aligned.m16n8k16.row.col.f32.bf16.bf16.f32 "
        "{%0,%1,%2,%3}, {%4,%5,%6,%7}, {%8,%9}, {%0,%1,%2,%3};\n"
        : "+f"(d[0]), "+f"(d[1]), "+f"(d[2]), "+f"(d[3])
        : "r"(a[0]), "r"(a[1]), "r"(a[2]), "r"(a[3]), "r"(b[0]), "r"(b[1]));
}
__device__ __forceinline__ void cp_async16(uint32_t smem_addr, const void* gptr, int src_bytes) {
    asm volatile("cp.async.cg.shared.global [%0], [%1], 16, %2;"
                 :: "r"(smem_addr), "l"(gptr), "r"(src_bytes) : "memory");
}
__device__ __forceinline__ void cp_async_commit() {
    asm volatile("cp.async.commit_group;" ::: "memory");
}
__device__ __forceinline__ void cp_async_wait0() {
    asm volatile("cp.async.wait_group 0;" ::: "memory");
}

// ---------------------------------------------------------------------------
// node GEMM: bf16x3, cp.async double buffer, 2 CTAs/SM.
#define TC_BM 128
#define TC_BN 128
#define AS2 36
#define BS2 136
#define A_U32 (TC_BM * AS2)
#define B_U32 (16 * BS2)
#define STAGE_U32 (2 * A_U32 + 2 * B_U32)   // 13568
#define NUM_KT 12

__global__ __launch_bounds__(256, 2) void gemm_nodes_tc(
        const float* __restrict__ bias, int out_sel) {
    const int M = N_NODES, N = D_FEAT;
    float* __restrict__ out = out_sel ? g_h2 : g_h1;

    extern __shared__ uint32_t smu[];
    uint32_t smem_base = (uint32_t)__cvta_generic_to_shared(smu);

    int bm = blockIdx.y * TC_BM;
    int bn = blockIdx.x * TC_BN;
    int tid = threadIdx.x;
    int lane = tid & 31;
    int wid = tid >> 5;
    int wm = (wid & 1) * 64;
    int wn = (wid >> 1) * 32;
    int r = lane >> 2;
    int c = lane & 3;

    float acc[4][4][4];
    #pragma unroll
    for (int i = 0; i < 4; i++)
        #pragma unroll
        for (int j = 0; j < 4; j++)
            #pragma unroll
            for (int q = 0; q < 4; q++) acc[i][j][q] = 0.f;

    int a_row = tid >> 2;     // 0..63
    int a_q4  = tid & 3;
    int b_kp = tid >> 5;      // 0..7
    int b_n4 = tid & 31;

    // cp.async staging of one k-tile into stage s
    auto copy_tile = [&](int t, int stage) {
        int kp0 = t * 16;
        uint32_t sbase = smem_base + (uint32_t)(stage * STAGE_U32 * 4);
        uint32_t As_h = sbase;
        uint32_t As_l = sbase + (uint32_t)(A_U32 * 4);
        uint32_t Bs_h = sbase + (uint32_t)(2 * A_U32 * 4);
        uint32_t Bs_l = Bs_h + (uint32_t)(B_U32 * 4);
        #pragma unroll
        for (int p = 0; p < 2; p++) {
            int m = p * 64 + a_row;
            int gm = bm + m;
            int ok = (gm < M) ? 16 : 0;
            size_t go = (size_t)gm * AKP + kp0 + a_q4 * 4;
            uint32_t so = (uint32_t)((m * AS2 + a_q4 * 4) * 4);
            cp_async16(As_h + so, g_agg_h + go, ok);
            cp_async16(As_l + so, g_agg_l + go, ok);
        }
        #pragma unroll
        for (int p = 0; p < 2; p++) {
            int kp = p * 8 + b_kp;
            size_t go = (size_t)(kp0 + kp) * WB_NS + bn + b_n4 * 4;
            uint32_t so = (uint32_t)((kp * BS2 + b_n4 * 4) * 4);
            cp_async16(Bs_h + so, g_wb_h + go, 16);
            cp_async16(Bs_l + so, g_wb_l + go, 16);
        }
        cp_async_commit();
    };

    copy_tile(0, 0);
    cp_async_wait0();
    __syncthreads();

    for (int t = 0; t < NUM_KT; t++) {
        if (t + 1 < NUM_KT) copy_tile(t + 1, (t + 1) & 1);

        {
            const uint32_t* base = smu + (t & 1) * STAGE_U32;
            const uint32_t* As_h = base;
            const uint32_t* As_l = base + A_U32;
            const uint32_t* Bs_h = base + 2 * A_U32;
            const uint32_t* Bs_l = Bs_h + B_U32;

            #pragma unroll
            for (int kk = 0; kk < 2; kk++) {
                uint32_t ah[4][4], al[4][4], bh[4][2], bl[4][2];
                #pragma unroll
                for (int mt = 0; mt < 4; mt++) {
                    int row = wm + mt * 16 + r;
                    const uint32_t* ph = As_h + row * AS2 + kk * 8 + c;
                    const uint32_t* pl = As_l + row * AS2 + kk * 8 + c;
                    ah[mt][0] = ph[0];
                    ah[mt][1] = ph[8 * AS2];
                    ah[mt][2] = ph[4];
                    ah[mt][3] = ph[8 * AS2 + 4];
                    al[mt][0] = pl[0];
                    al[mt][1] = pl[8 * AS2];
                    al[mt][2] = pl[4];
                    al[mt][3] = pl[8 * AS2 + 4];
                }
                #pragma unroll
                for (int nt = 0; nt < 4; nt++) {
                    int col = wn + nt * 8 + r;
                    const uint32_t* qh = Bs_h + (kk * 8 + c) * BS2 + col;
                    const uint32_t* ql = Bs_l + (kk * 8 + c) * BS2 + col;
                    bh[nt][0] = qh[0];
                    bh[nt][1] = qh[4 * BS2];
                    bl[nt][0] = ql[0];
                    bl[nt][1] = ql[4 * BS2];
                }
                #pragma unroll
                for (int mt = 0; mt < 4; mt++)
                    #pragma unroll
                    for (int nt = 0; nt < 4; nt++) {
                        mma16(acc[mt][nt], ah[mt], bh[nt]);
                        mma16(acc[mt][nt], al[mt], bh[nt]);
                        mma16(acc[mt][nt], ah[mt], bl[nt]);
                    }
            }
        }

        if (t + 1 < NUM_KT) cp_async_wait0();
        __syncthreads();
    }

    #pragma unroll
    for (int mt = 0; mt < 4; mt++) {
        int gm0 = bm + wm + mt * 16 + r;
        #pragma unroll
        for (int nt = 0; nt < 4; nt++) {
            int gn = bn + wn + nt * 8 + 2 * c;
            if (gn >= N) continue;
            float b0 = bias[gn], b1 = bias[gn + 1];
            float v0 = acc[mt][nt][0] + b0;
            float v1 = acc[mt][nt][1] + b1;
            float v2 = acc[mt][nt][2] + b0;
            float v3 = acc[mt][nt][3] + b1;
            v0 = v0 > 0.f ? v0 : NEG_SLOPE * v0;
            v1 = v1 > 0.f ? v1 : NEG_SLOPE * v1;
            v2 = v2 > 0.f ? v2 : NEG_SLOPE * v2;
            v3 = v3 > 0.f ? v3 : NEG_SLOPE * v3;
            if (gm0 < M)
                *reinterpret_cast<float2*>(out + (size_t)gm0 * N + gn) = make_float2(v0, v1);
            if (gm0 + 8 < M)
                *reinterpret_cast<float2*>(out + (size_t)(gm0 + 8) * N + gn) = make_float2(v2, v3);
        }
    }
}

// ---------------------------------------------------------------------------
// tf32 helpers for pairs GEMM
__device__ __forceinline__ uint32_t f2tf32(float x) {
    uint32_t r;
    asm("cvt.rna.tf32.f32 %0, %1;" : "=r"(r) : "f"(x));
    return r;
}
__device__ __forceinline__ void split_tf32(float v, float& h, float& l) {
    h = __uint_as_float(f2tf32(v));
    l = __uint_as_float(f2tf32(v - h));
}
__device__ __forceinline__ void mma8(float d[4], const uint32_t a[4], const uint32_t b[2]) {
    asm volatile(
        "mma.sync.aligned.m16n8k8.row.col.f32.tf32.tf32.f32 "
        "{%0,%1,%2,%3}, {%4,%5,%6,%7}, {%8,%9}, {%0,%1,%2,%3};\n"
        : "+f"(d[0]), "+f"(d[1]), "+f"(d[2]), "+f"(d[3])
        : "r"(a[0]), "r"(a[1]), "r"(a[2]), "r"(a[3]), "r"(b[0]), "r"(b[1]));
}

// ---------------------------------------------------------------------------
// pairs GEMM (tf32x3)
#define P_BN 64
#define P_BK 32
#define PAS 36
#define PBS 72
#define P_A_FLOATS (TC_BM * PAS)
#define P_B_FLOATS (P_BK * PBS)
#define P_SMEM_FLOATS (2 * P_A_FLOATS + 2 * P_B_FLOATS)

__global__ __launch_bounds__(256) void gemm_pairs_tc(
        const int* __restrict__ v1, const int* __restrict__ v2,
        const float* __restrict__ W, const float* __restrict__ bias) {
    const int K = D_FEAT, N = D_OUT;

    extern __shared__ float smf[];
    float* As_h = smf;
    float* As_l = smf + P_A_FLOATS;
    float* Bs_h = smf + 2 * P_A_FLOATS;
    float* Bs_l = Bs_h + P_B_FLOATS;
    __shared__ int rows[TC_BM];

    int bm = blockIdx.y * TC_BM;
    int bn = blockIdx.x * P_BN;
    int tid = threadIdx.x;
    int lane = tid & 31;
    int wid = tid >> 5;
    int wm = (wid & 3) * 32;
    int wn = (wid >> 2) * 32;
    int r = lane >> 2;
    int c = lane & 3;

    if (tid < TC_BM) {
        int gm = bm + tid;
        rows[tid] = (gm < N_PAIRS) ? v1[gm] : v2[gm - N_PAIRS];
    }
    __syncthreads();

    float acc[2][4][4];
    #pragma unroll
    for (int i = 0; i < 2; i++)
        #pragma unroll
        for (int j = 0; j < 4; j++)
            #pragma unroll
            for (int q = 0; q < 4; q++) acc[i][j][q] = 0.f;

    int ak4 = tid & 7;
    int arl = tid >> 3;
    int bn4 = tid & 15;
    int bkr = tid >> 4;

    for (int k0 = 0; k0 < K; k0 += P_BK) {
        #pragma unroll
        for (int p = 0; p < 4; p++) {
            int m = p * 32 + arl;
            int node = rows[m];
            int gk = k0 + ak4 * 4;
            float4 v = (gk < K)
                ? *reinterpret_cast<const float4*>(g_h2 + (size_t)node * K + gk)
                : make_float4(0.f, 0.f, 0.f, 0.f);
            float4 h, l;
            split_tf32(v.x, h.x, l.x);
            split_tf32(v.y, h.y, l.y);
            split_tf32(v.z, h.z, l.z);
            split_tf32(v.w, h.w, l.w);
            *reinterpret_cast<float4*>(As_h + m * PAS + ak4 * 4) = h;
            *reinterpret_cast<float4*>(As_l + m * PAS + ak4 * 4) = l;
        }
        #pragma unroll
        for (int p = 0; p < 2; p++) {
            int kr = p * 16 + bkr;
            int gk = k0 + kr;
            int gn = bn + bn4 * 4;
            float4 v = make_float4(0.f, 0.f, 0.f, 0.f);
            if (gk < K) {
                const float* wrow = W + (size_t)gk * N;
                if (gn + 3 < N) {
                    float2 lo = *reinterpret_cast<const float2*>(wrow + gn);
                    float2 hi = *reinterpret_cast<const float2*>(wrow + gn + 2);
                    v = make_float4(lo.x, lo.y, hi.x, hi.y);
                } else {
                    #pragma unroll
                    for (int j = 0; j < 4; j++) {
                        int nn = gn + j;
                        reinterpret_cast<float*>(&v)[j] = (nn < N) ? wrow[nn] : 0.f;
                    }
                }
            }
            float4 h, l;
            split_tf32(v.x, h.x, l.x);
            split_tf32(v.y, h.y, l.y);
            split_tf32(v.z, h.z, l.z);
            split_tf32(v.w, h.w, l.w);
            *reinterpret_cast<float4*>(Bs_h + kr * PBS + bn4 * 4) = h;
            *reinterpret_cast<float4*>(Bs_l + kr * PBS + bn4 * 4) = l;
        }
        __syncthreads();

        #pragma unroll
        for (int kk = 0; kk < 4; kk++) {
            uint32_t ah[2][4], al[2][4], bh[4][2], bl[4][2];
            #pragma unroll
            for (int mt = 0; mt < 2; mt++) {
                int row = wm + mt * 16 + r;
                const float* ph = As_h + row * PAS + kk * 8 + c;
                const float* pl = As_l + row * PAS + kk * 8 + c;
                ah[mt][0] = __float_as_uint(ph[0]);
                ah[mt][1] = __float_as_uint(ph[8 * PAS]);
                ah[mt][2] = __float_as_uint(ph[4]);
                ah[mt][3] = __float_as_uint(ph[8 * PAS + 4]);
                al[mt][0] = __float_as_uint(pl[0]);
                al[mt][1] = __float_as_uint(pl[8 * PAS]);
                al[mt][2] = __float_as_uint(pl[4]);
                al[mt][3] = __float_as_uint(pl[8 * PAS + 4]);
            }
            #pragma unroll
            for (int nt = 0; nt < 4; nt++) {
                int col = wn + nt * 8 + r;
                const float* qh = Bs_h + (kk * 8 + c) * PBS + col;
                const float* ql = Bs_l + (kk * 8 + c) * PBS + col;
                bh[nt][0] = __float_as_uint(qh[0]);
                bh[nt][1] = __float_as_uint(qh[4 * PBS]);
                bl[nt][0] = __float_as_uint(ql[0]);
                bl[nt][1] = __float_as_uint(ql[4 * PBS]);
            }
            #pragma unroll
            for (int mt = 0; mt < 2; mt++)
                #pragma unroll
                for (int nt = 0; nt < 4; nt++) {
                    mma8(acc[mt][nt], ah[mt], bh[nt]);
                    mma8(acc[mt][nt], al[mt], bh[nt]);
                    mma8(acc[mt][nt], ah[mt], bl[nt]);
                }
        }
        __syncthreads();
    }

    #pragma unroll
    for (int mt = 0; mt < 2; mt++) {
        int gm0 = bm + wm + mt * 16 + r;
        #pragma unroll
        for (int nt = 0; nt < 4; nt++) {
            int gn = bn + wn + nt * 8 + 2 * c;
            if (gn >= N) continue;
            float b0 = bias[gn], b1 = bias[gn + 1];
            float v0 = acc[mt][nt][0] + b0;
            float v1 = acc[mt][nt][1] + b1;
            float v2 = acc[mt][nt][2] + b0;
            float v3 = acc[mt][nt][3] + b1;
            v0 = v0 > 0.f ? v0 : NEG_SLOPE * v0;
            v1 = v1 > 0.f ? v1 : NEG_SLOPE * v1;
            v2 = v2 > 0.f ? v2 : NEG_SLOPE * v2;
            v3 = v3 > 0.f ? v3 : NEG_SLOPE * v3;
            *reinterpret_cast<float2*>(g_z + (size_t)gm0 * N + gn) = make_float2(v0, v1);
            *reinterpret_cast<float2*>(g_z + (size_t)(gm0 + 8) * N + gn) = make_float2(v2, v3);
        }
    }
}

// ---------------------------------------------------------------------------
__global__ void normalize_kernel(float* __restrict__ out) {
    int row  = (blockIdx.x * blockDim.x + threadIdx.x) >> 5;
    int lane = threadIdx.x & 31;
    if (row >= 2 * N_PAIRS) return;
    const float* zr = g_z + (size_t)row * D_OUT;
    float ss = 0.f;
    for (int i = lane; i < D_OUT; i += 32) { float v = zr[i]; ss += v * v; }
    #pragma unroll
    for (int o = 16; o; o >>= 1) ss += __shfl_xor_sync(0xFFFFFFFFu, ss, o);
    float norm = sqrtf(ss);
    float inv = 1.f / fmaxf(norm, 1e-12f);
    for (int i = lane; i < D_OUT; i += 32) out[(size_t)row * D_OUT + i] = zr[i] * inv;
}

// ---------------------------------------------------------------------------
extern "C" void kernel_launch(void* const* d_in, const int* in_sizes, int n_in,
                              void* d_out, int out_size) {
    const float* features = (const float*)d_in[0];
    const int*   src      = (const int*)  d_in[1];
    const int*   dst      = (const int*)  d_in[2];
    const int*   v1       = (const int*)  d_in[3];
    const int*   v2       = (const int*)  d_in[4];
    const float* W1       = (const float*)d_in[5];
    const float* b1       = (const float*)d_in[6];
    const float* W2       = (const float*)d_in[7];
    const float* b2       = (const float*)d_in[8];
    const float* W3       = (const float*)d_in[9];
    const float* b3       = (const float*)d_in[10];
    float* out = (float*)d_out;
    (void)in_sizes; (void)n_in; (void)out_size;

    size_t tc_smem = (size_t)2 * STAGE_U32 * sizeof(uint32_t);      // 108544 B
    cudaFuncSetAttribute(gemm_nodes_tc, cudaFuncAttributeMaxDynamicSharedMemorySize,
                         (int)tc_smem);
    size_t p_smem = (size_t)P_SMEM_FLOATS * sizeof(float);
    cudaFuncSetAttribute(gemm_pairs_tc, cudaFuncAttributeMaxDynamicSharedMemorySize,
                         (int)p_smem);

    dim3 tc_grid((D_FEAT + TC_BN - 1) / TC_BN, (N_NODES + TC_BM - 1) / TC_BM);
    dim3 pairs_grid((D_OUT + P_BN - 1) / P_BN, (2 * N_PAIRS) / TC_BM);
    int gather_blocks = (N_NODES * 64 + 255) / 256;   // 2 warps per node
    int convw_blocks = (AKP * (WB_NS / 4) + 255) / 256;

    // CSR by dst (reused for both layers)
    csr_zero_kernel<<<(N_NODES + 255) / 256, 256>>>();
    csr_count_kernel<<<(N_EDGES + 255) / 256, 256>>>(dst);
    csr_scan_kernel<<<1, 1024>>>();
    csr_fill_kernel<<<(N_EDGES + 255) / 256, 256>>>(src, dst);

    // layer 1
    convert_w_kernel<<<convw_blocks, 256>>>(W1);
    gather_kernel<<<gather_blocks, 256>>>(features, 0);
    gemm_nodes_tc<<<tc_grid, 256, tc_smem>>>(b1, /*out_sel=*/0);

    // layer 2
    convert_w_kernel<<<convw_blocks, 256>>>(W2);
    gather_kernel<<<gather_blocks, 256>>>(nullptr, 1);
    gemm_nodes_tc<<<tc_grid, 256, tc_smem>>>(b2, /*out_sel=*/1);

    // pair projection + normalize
    gemm_pairs_tc<<<pairs_grid, 256, p_smem>>>(v1, v2, W3, b3);
    normalize_kernel<<<(2 * N_PAIRS * 32 + 255) / 256, 256>>>(out);
}

// round 12
// speedup vs baseline: 1.2970x; 1.1497x over previous
#include <cuda_runtime.h>
#include <cuda_bf16.h>
#include <math.h>
#include <stdint.h>

#define N_NODES 50000
#define D_FEAT  364
#define D_OUT   150
#define N_PAIRS 8192
#define N_EDGES 200000
#define NEG_SLOPE 0.01f

#define AKP 192          // padded kp (k/2) per row for A (K padded to 384)
#define WB_NS 384        // padded n stride for converted W

// Scratch (no cudaMalloc allowed).
__device__ __align__(16) float g_h1 [(size_t)N_NODES * D_FEAT];
__device__ __align__(16) float g_h2 [(size_t)2 * N_PAIRS * D_FEAT];   // compact
__device__ __align__(16) float g_z  [(size_t)2 * N_PAIRS * D_OUT];
__device__ __align__(16) uint32_t g_agg_h[(size_t)N_NODES * AKP];
__device__ __align__(16) uint32_t g_agg_l[(size_t)N_NODES * AKP];
__device__ __align__(16) uint32_t g_wb_h [(size_t)AKP * WB_NS];
__device__ __align__(16) uint32_t g_wb_l [(size_t)AKP * WB_NS];

// CSR-by-dst scratch
__device__ int g_deg [N_NODES];
__device__ int g_off [N_NODES];
__device__ int g_pos [N_NODES];
__device__ int g_srcs[N_EDGES];

// pair-node compaction
__device__ int g_mark  [N_NODES];
__device__ int g_newidx[N_NODES];
__device__ int g_list  [2 * N_PAIRS];
__device__ int g_count;

// ---------------------------------------------------------------------------
__device__ __forceinline__ void split1(float v, __nv_bfloat16& h, __nv_bfloat16& l) {
    h = __float2bfloat16_rn(v);
    l = __float2bfloat16_rn(v - __bfloat162float(h));
}
__device__ __forceinline__ uint32_t pack2(__nv_bfloat16 lo, __nv_bfloat16 hi) {
    __nv_bfloat162 p;
    p.x = lo; p.y = hi;
    return *reinterpret_cast<uint32_t*>(&p);
}

// ---------------------------------------------------------------------------
// CSR build
__global__ void csr_zero_kernel() {
    int i = blockIdx.x * blockDim.x + threadIdx.x;
    if (i < N_NODES) { g_deg[i] = 0; g_mark[i] = 0; }
}
__global__ void csr_count_kernel(const int* __restrict__ dst) {
    int e = blockIdx.x * blockDim.x + threadIdx.x;
    if (e < N_EDGES) atomicAdd(&g_deg[dst[e]], 1);
}
__global__ void mark_set_kernel(const int* __restrict__ v1,
                                const int* __restrict__ v2) {
    int i = blockIdx.x * blockDim.x + threadIdx.x;
    if (i < N_PAIRS) { g_mark[v1[i]] = 1; g_mark[v2[i]] = 1; }
}
// exclusive scan over arbitrary int array (single block, 1024 thr)
__global__ void csr_scan_kernel() {
    __shared__ int warp_tot[32];
    __shared__ int carry_sh;
    int tid = threadIdx.x;
    int lane = tid & 31, w = tid >> 5;
    if (tid == 0) carry_sh = 0;
    __syncthreads();
    for (int base = 0; base < N_NODES; base += 1024) {
        int i = base + tid;
        int v = (i < N_NODES) ? g_deg[i] : 0;
        int s = v;
        #pragma unroll
        for (int o = 1; o < 32; o <<= 1) {
            int t = __shfl_up_sync(0xFFFFFFFFu, s, o);
            if (lane >= o) s += t;
        }
        if (lane == 31) warp_tot[w] = s;
        __syncthreads();
        if (w == 0) {
            int t = warp_tot[lane];
            int ss = t;
            #pragma unroll
            for (int o = 1; o < 32; o <<= 1) {
                int u = __shfl_up_sync(0xFFFFFFFFu, ss, o);
                if (lane >= o) ss += u;
            }
            warp_tot[lane] = ss - t;
        }
        __syncthreads();
        int incl = s + warp_tot[w];
        int off  = carry_sh + incl - v;
        if (i < N_NODES) { g_off[i] = off; g_pos[i] = off; }
        __syncthreads();
        if (tid == 1023) carry_sh += incl;
        __syncthreads();
    }
}
// scan g_mark -> g_newidx, emit g_list, g_count (deterministic compaction)
__global__ void compact_scan_kernel() {
    __shared__ int warp_tot[32];
    __shared__ int carry_sh;
    int tid = threadIdx.x;
    int lane = tid & 31, w = tid >> 5;
    if (tid == 0) carry_sh = 0;
    __syncthreads();
    for (int base = 0; base < N_NODES; base += 1024) {
        int i = base + tid;
        int v = (i < N_NODES) ? g_mark[i] : 0;
        int s = v;
        #pragma unroll
        for (int o = 1; o < 32; o <<= 1) {
            int t = __shfl_up_sync(0xFFFFFFFFu, s, o);
            if (lane >= o) s += t;
        }
        if (lane == 31) warp_tot[w] = s;
        __syncthreads();
        if (w == 0) {
            int t = warp_tot[lane];
            int ss = t;
            #pragma unroll
            for (int o = 1; o < 32; o <<= 1) {
                int u = __shfl_up_sync(0xFFFFFFFFu, ss, o);
                if (lane >= o) ss += u;
            }
            warp_tot[lane] = ss - t;
        }
        __syncthreads();
        int incl = s + warp_tot[w];
        int off  = carry_sh + incl - v;
        if (i < N_NODES) {
            g_newidx[i] = off;
            if (v) g_list[off] = i;
        }
        __syncthreads();
        if (tid == 1023) carry_sh += incl;
        __syncthreads();
    }
    __syncthreads();
    if (tid == 0) g_count = carry_sh;
}
__global__ void csr_fill_kernel(const int* __restrict__ src,
                                const int* __restrict__ dst) {
    int e = blockIdx.x * blockDim.x + threadIdx.x;
    if (e >= N_EDGES) return;
    int idx = atomicAdd(&g_pos[dst[e]], 1);
    g_srcs[idx] = src[e];
}

// ---------------------------------------------------------------------------
// gather core: agg(outrow) = x[node] + sum_in x[src], bf16-split output.
// Two warps per output row (half = 0/1 covering 46/45 float4).
__device__ __forceinline__ void gather_one(const float* __restrict__ x,
                                           int node, int outrow,
                                           int half, int lane) {
    int off = g_off[node];
    int deg = g_deg[node];

    int base4 = half * 46;
    int cnt   = half ? 45 : 46;
    int i0 = base4 + lane;
    int i1 = base4 + 32 + lane;
    bool p1 = (32 + lane) < cnt;

    const float4* xd = reinterpret_cast<const float4*>(x + (size_t)node * D_FEAT);
    float4 a0 = xd[i0];
    float4 a1 = p1 ? xd[i1] : make_float4(0.f, 0.f, 0.f, 0.f);

    for (int e = 0; e < deg; e++) {
        int s = g_srcs[off + e];
        const float4* xs = reinterpret_cast<const float4*>(x + (size_t)s * D_FEAT);
        float4 v0 = xs[i0];
        a0.x += v0.x; a0.y += v0.y; a0.z += v0.z; a0.w += v0.w;
        if (p1) {
            float4 v1 = xs[i1];
            a1.x += v1.x; a1.y += v1.y; a1.z += v1.z; a1.w += v1.w;
        }
    }

    uint32_t* oh = g_agg_h + (size_t)outrow * AKP;
    uint32_t* ol = g_agg_l + (size_t)outrow * AKP;
    {
        __nv_bfloat16 hx, lx, hy, ly, hz, lz, hw, lw;
        split1(a0.x, hx, lx); split1(a0.y, hy, ly);
        split1(a0.z, hz, lz); split1(a0.w, hw, lw);
        *reinterpret_cast<uint2*>(oh + 2 * i0) = make_uint2(pack2(hx, hy), pack2(hz, hw));
        *reinterpret_cast<uint2*>(ol + 2 * i0) = make_uint2(pack2(lx, ly), pack2(lz, lw));
    }
    if (p1) {
        __nv_bfloat16 hx, lx, hy, ly, hz, lz, hw, lw;
        split1(a1.x, hx, lx); split1(a1.y, hy, ly);
        split1(a1.z, hz, lz); split1(a1.w, hw, lw);
        *reinterpret_cast<uint2*>(oh + 2 * i1) = make_uint2(pack2(hx, hy), pack2(hz, hw));
        *reinterpret_cast<uint2*>(ol + 2 * i1) = make_uint2(pack2(lx, ly), pack2(lz, lw));
    }
    if (half && lane >= 13 && lane <= 17) {   // zero-pad k4 91..95
        *reinterpret_cast<uint2*>(oh + 2 * i1) = make_uint2(0u, 0u);
        *reinterpret_cast<uint2*>(ol + 2 * i1) = make_uint2(0u, 0u);
    }
}

// layer 1: all nodes, outrow = node
__global__ void gather_kernel(const float* __restrict__ x_ext) {
    int gw = (blockIdx.x * blockDim.x + threadIdx.x) >> 5;
    int lane = threadIdx.x & 31;
    int node = gw >> 1;
    int half = gw & 1;
    if (node >= N_NODES) return;
    gather_one(x_ext, node, node, half, lane);
}
// layer 2: compact pair nodes only, x = g_h1
__global__ void gather2_kernel() {
    int gw = (blockIdx.x * blockDim.x + threadIdx.x) >> 5;
    int lane = threadIdx.x & 31;
    int i = gw >> 1;
    int half = gw & 1;
    if (i >= g_count) return;
    gather_one(g_h1, g_list[i], i, half, lane);
}

// ---------------------------------------------------------------------------
// convert W [K x N] fp32 -> g_wb_h/l
__global__ void convert_w_kernel(const float* __restrict__ W) {
    int idx = blockIdx.x * blockDim.x + threadIdx.x;
    int kp = idx / (WB_NS / 4);
    int nq = idx % (WB_NS / 4);
    if (kp >= AKP) return;
    int n0 = nq * 4;
    uint32_t oh[4], ol[4];
    #pragma unroll
    for (int j = 0; j < 4; j++) {
        int n = n0 + j;
        float v0 = 0.f, v1 = 0.f;
        if (2 * kp < D_FEAT && n < D_FEAT) {
            v0 = W[(size_t)(2 * kp) * D_FEAT + n];
            v1 = W[(size_t)(2 * kp + 1) * D_FEAT + n];
        }
        __nv_bfloat16 h0, l0, h1, l1;
        split1(v0, h0, l0);
        split1(v1, h1, l1);
        oh[j] = pack2(h0, h1);
        ol[j] = pack2(l0, l1);
    }
    size_t o = (size_t)kp * WB_NS + n0;
    *reinterpret_cast<uint4*>(g_wb_h + o) = make_uint4(oh[0], oh[1], oh[2], oh[3]);
    *reinterpret_cast<uint4*>(g_wb_l + o) = make_uint4(ol[0], ol[1], ol[2], ol[3]);
}

// ---------------------------------------------------------------------------
__device__ __forceinline__ void mma16(float d[4], const uint32_t a[4], const uint32_t b[2]) {
    asm volatile(
        "mma.sync.aligned.m16n8k16.row.col.f32.bf16.bf16.f32 "
        "{%0,%1,%2,%3}, {%4,%5,%6,%7}, {%8,%9}, {%0,%1,%2,%3};\n"
        : "+f"(d[0]), "+f"(d[1]), "+f"(d[2]), "+f"(d[3])
        : "r"(a[0]), "r"(a[1]), "r"(a[2]), "r"(a[3]), "r"(b[0]), "r"(b[1]));
}
__device__ __forceinline__ void cp_async16(uint32_t smem_addr, const void* gptr, int src_bytes) {
    asm volatile("cp.async.cg.shared.global [%0], [%1], 16, %2;"
                 :: "r"(smem_addr), "l"(gptr), "r"(src_bytes) : "memory");
}
__device__ __forceinline__ void cp_async_commit() {
    asm volatile("cp.async.commit_group;" ::: "memory");
}
__device__ __forceinline__ void cp_async_wait0() {
    asm volatile("cp.async.wait_group 0;" ::: "memory");
}

// ---------------------------------------------------------------------------
// node GEMM: bf16x3, cp.async double buffer, 2 CTAs/SM.
// m_mode 0: M = N_NODES, out = g_h1. m_mode 1: M = g_count (compact), out = g_h2.
#define TC_BM 128
#define TC_BN 128
#define AS2 36
#define BS2 136
#define A_U32 (TC_BM * AS2)
#define B_U32 (16 * BS2)
#define STAGE_U32 (2 * A_U32 + 2 * B_U32)   // 13568
#define NUM_KT 12

__global__ __launch_bounds__(256, 2) void gemm_nodes_tc(
        const float* __restrict__ bias, int m_mode) {
    const int N = D_FEAT;
    int M = m_mode ? g_count : N_NODES;
    float* __restrict__ out = m_mode ? g_h2 : g_h1;

    int bm = blockIdx.y * TC_BM;
    if (bm >= M) return;
    int bn = blockIdx.x * TC_BN;

    extern __shared__ uint32_t smu[];
    uint32_t smem_base = (uint32_t)__cvta_generic_to_shared(smu);

    int tid = threadIdx.x;
    int lane = tid & 31;
    int wid = tid >> 5;
    int wm = (wid & 1) * 64;
    int wn = (wid >> 1) * 32;
    int r = lane >> 2;
    int c = lane & 3;

    float acc[4][4][4];
    #pragma unroll
    for (int i = 0; i < 4; i++)
        #pragma unroll
        for (int j = 0; j < 4; j++)
            #pragma unroll
            for (int q = 0; q < 4; q++) acc[i][j][q] = 0.f;

    int a_row = tid >> 2;
    int a_q4  = tid & 3;
    int b_kp = tid >> 5;
    int b_n4 = tid & 31;

    auto copy_tile = [&](int t, int stage) {
        int kp0 = t * 16;
        uint32_t sbase = smem_base + (uint32_t)(stage * STAGE_U32 * 4);
        uint32_t As_h = sbase;
        uint32_t As_l = sbase + (uint32_t)(A_U32 * 4);
        uint32_t Bs_h = sbase + (uint32_t)(2 * A_U32 * 4);
        uint32_t Bs_l = Bs_h + (uint32_t)(B_U32 * 4);
        #pragma unroll
        for (int p = 0; p < 2; p++) {
            int m = p * 64 + a_row;
            int gm = bm + m;
            int ok = (gm < M) ? 16 : 0;
            size_t go = (size_t)gm * AKP + kp0 + a_q4 * 4;
            uint32_t so = (uint32_t)((m * AS2 + a_q4 * 4) * 4);
            cp_async16(As_h + so, g_agg_h + go, ok);
            cp_async16(As_l + so, g_agg_l + go, ok);
        }
        #pragma unroll
        for (int p = 0; p < 2; p++) {
            int kp = p * 8 + b_kp;
            size_t go = (size_t)(kp0 + kp) * WB_NS + bn + b_n4 * 4;
            uint32_t so = (uint32_t)((kp * BS2 + b_n4 * 4) * 4);
            cp_async16(Bs_h + so, g_wb_h + go, 16);
            cp_async16(Bs_l + so, g_wb_l + go, 16);
        }
        cp_async_commit();
    };

    copy_tile(0, 0);
    cp_async_wait0();
    __syncthreads();

    for (int t = 0; t < NUM_KT; t++) {
        if (t + 1 < NUM_KT) copy_tile(t + 1, (t + 1) & 1);

        {
            const uint32_t* base = smu + (t & 1) * STAGE_U32;
            const uint32_t* As_h = base;
            const uint32_t* As_l = base + A_U32;
            const uint32_t* Bs_h = base + 2 * A_U32;
            const uint32_t* Bs_l = Bs_h + B_U32;

            #pragma unroll
            for (int kk = 0; kk < 2; kk++) {
                uint32_t ah[4][4], al[4][4], bh[4][2], bl[4][2];
                #pragma unroll
                for (int mt = 0; mt < 4; mt++) {
                    int row = wm + mt * 16 + r;
                    const uint32_t* ph = As_h + row * AS2 + kk * 8 + c;
                    const uint32_t* pl = As_l + row * AS2 + kk * 8 + c;
                    ah[mt][0] = ph[0];
                    ah[mt][1] = ph[8 * AS2];
                    ah[mt][2] = ph[4];
                    ah[mt][3] = ph[8 * AS2 + 4];
                    al[mt][0] = pl[0];
                    al[mt][1] = pl[8 * AS2];
                    al[mt][2] = pl[4];
                    al[mt][3] = pl[8 * AS2 + 4];
                }
                #pragma unroll
                for (int nt = 0; nt < 4; nt++) {
                    int col = wn + nt * 8 + r;
                    const uint32_t* qh = Bs_h + (kk * 8 + c) * BS2 + col;
                    const uint32_t* ql = Bs_l + (kk * 8 + c) * BS2 + col;
                    bh[nt][0] = qh[0];
                    bh[nt][1] = qh[4 * BS2];
                    bl[nt][0] = ql[0];
                    bl[nt][1] = ql[4 * BS2];
                }
                #pragma unroll
                for (int mt = 0; mt < 4; mt++)
                    #pragma unroll
                    for (int nt = 0; nt < 4; nt++) {
                        mma16(acc[mt][nt], ah[mt], bh[nt]);
                        mma16(acc[mt][nt], al[mt], bh[nt]);
                        mma16(acc[mt][nt], ah[mt], bl[nt]);
                    }
            }
        }

        if (t + 1 < NUM_KT) cp_async_wait0();
        __syncthreads();
    }

    #pragma unroll
    for (int mt = 0; mt < 4; mt++) {
        int gm0 = bm + wm + mt * 16 + r;
        #pragma unroll
        for (int nt = 0; nt < 4; nt++) {
            int gn = bn + wn + nt * 8 + 2 * c;
            if (gn >= N) continue;
            float b0 = bias[gn], b1 = bias[gn + 1];
            float v0 = acc[mt][nt][0] + b0;
            float v1 = acc[mt][nt][1] + b1;
            float v2 = acc[mt][nt][2] + b0;
            float v3 = acc[mt][nt][3] + b1;
            v0 = v0 > 0.f ? v0 : NEG_SLOPE * v0;
            v1 = v1 > 0.f ? v1 : NEG_SLOPE * v1;
            v2 = v2 > 0.f ? v2 : NEG_SLOPE * v2;
            v3 = v3 > 0.f ? v3 : NEG_SLOPE * v3;
            if (gm0 < M)
                *reinterpret_cast<float2*>(out + (size_t)gm0 * N + gn) = make_float2(v0, v1);
            if (gm0 + 8 < M)
                *reinterpret_cast<float2*>(out + (size_t)(gm0 + 8) * N + gn) = make_float2(v2, v3);
        }
    }
}

// ---------------------------------------------------------------------------
// tf32 helpers for pairs GEMM
__device__ __forceinline__ uint32_t f2tf32(float x) {
    uint32_t r;
    asm("cvt.rna.tf32.f32 %0, %1;" : "=r"(r) : "f"(x));
    return r;
}
__device__ __forceinline__ void split_tf32(float v, float& h, float& l) {
    h = __uint_as_float(f2tf32(v));
    l = __uint_as_float(f2tf32(v - h));
}
__device__ __forceinline__ void mma8(float d[4], const uint32_t a[4], const uint32_t b[2]) {
    asm volatile(
        "mma.sync.aligned.m16n8k8.row.col.f32.tf32.tf32.f32 "
        "{%0,%1,%2,%3}, {%4,%5,%6,%7}, {%8,%9}, {%0,%1,%2,%3};\n"
        : "+f"(d[0]), "+f"(d[1]), "+f"(d[2]), "+f"(d[3])
        : "r"(a[0]), "r"(a[1]), "r"(a[2]), "r"(a[3]), "r"(b[0]), "r"(b[1]));
}

// ---------------------------------------------------------------------------
// pairs GEMM (tf32x3): g_z = lrelu(h2c[newidx[vcat]] @ W3 + b3)
#define P_BN 64
#define P_BK 32
#define PAS 36
#define PBS 72
#define P_A_FLOATS (TC_BM * PAS)
#define P_B_FLOATS (P_BK * PBS)
#define P_SMEM_FLOATS (2 * P_A_FLOATS + 2 * P_B_FLOATS)

__global__ __launch_bounds__(256) void gemm_pairs_tc(
        const int* __restrict__ v1, const int* __restrict__ v2,
        const float* __restrict__ W, const float* __restrict__ bias) {
    const int K = D_FEAT, N = D_OUT;

    extern __shared__ float smf[];
    float* As_h = smf;
    float* As_l = smf + P_A_FLOATS;
    float* Bs_h = smf + 2 * P_A_FLOATS;
    float* Bs_l = Bs_h + P_B_FLOATS;
    __shared__ int rows[TC_BM];

    int bm = blockIdx.y * TC_BM;
    int bn = blockIdx.x * P_BN;
    int tid = threadIdx.x;
    int lane = tid & 31;
    int wid = tid >> 5;
    int wm = (wid & 3) * 32;
    int wn = (wid >> 2) * 32;
    int r = lane >> 2;
    int c = lane & 3;

    if (tid < TC_BM) {
        int gm = bm + tid;
        int v = (gm < N_PAIRS) ? v1[gm] : v2[gm - N_PAIRS];
        rows[tid] = g_newidx[v];
    }
    __syncthreads();

    float acc[2][4][4];
    #pragma unroll
    for (int i = 0; i < 2; i++)
        #pragma unroll
        for (int j = 0; j < 4; j++)
            #pragma unroll
            for (int q = 0; q < 4; q++) acc[i][j][q] = 0.f;

    int ak4 = tid & 7;
    int arl = tid >> 3;
    int bn4 = tid & 15;
    int bkr = tid >> 4;

    for (int k0 = 0; k0 < K; k0 += P_BK) {
        #pragma unroll
        for (int p = 0; p < 4; p++) {
            int m = p * 32 + arl;
            int node = rows[m];
            int gk = k0 + ak4 * 4;
            float4 v = (gk < K)
                ? *reinterpret_cast<const float4*>(g_h2 + (size_t)node * K + gk)
                : make_float4(0.f, 0.f, 0.f, 0.f);
            float4 h, l;
            split_tf32(v.x, h.x, l.x);
            split_tf32(v.y, h.y, l.y);
            split_tf32(v.z, h.z, l.z);
            split_tf32(v.w, h.w, l.w);
            *reinterpret_cast<float4*>(As_h + m * PAS + ak4 * 4) = h;
            *reinterpret_cast<float4*>(As_l + m * PAS + ak4 * 4) = l;
        }
        #pragma unroll
        for (int p = 0; p < 2; p++) {
            int kr = p * 16 + bkr;
            int gk = k0 + kr;
            int gn = bn + bn4 * 4;
            float4 v = make_float4(0.f, 0.f, 0.f, 0.f);
            if (gk < K) {
                const float* wrow = W + (size_t)gk * N;
                if (gn + 3 < N) {
                    float2 lo = *reinterpret_cast<const float2*>(wrow + gn);
                    float2 hi = *reinterpret_cast<const float2*>(wrow + gn + 2);
                    v = make_float4(lo.x, lo.y, hi.x, hi.y);
                } else {
                    #pragma unroll
                    for (int j = 0; j < 4; j++) {
                        int nn = gn + j;
                        reinterpret_cast<float*>(&v)[j] = (nn < N) ? wrow[nn] : 0.f;
                    }
                }
            }
            float4 h, l;
            split_tf32(v.x, h.x, l.x);
            split_tf32(v.y, h.y, l.y);
            split_tf32(v.z, h.z, l.z);
            split_tf32(v.w, h.w, l.w);
            *reinterpret_cast<float4*>(Bs_h + kr * PBS + bn4 * 4) = h;
            *reinterpret_cast<float4*>(Bs_l + kr * PBS + bn4 * 4) = l;
        }
        __syncthreads();

        #pragma unroll
        for (int kk = 0; kk < 4; kk++) {
            uint32_t ah[2][4], al[2][4], bh[4][2], bl[4][2];
            #pragma unroll
            for (int mt = 0; mt < 2; mt++) {
                int row = wm + mt * 16 + r;
                const float* ph = As_h + row * PAS + kk * 8 + c;
                const float* pl = As_l + row * PAS + kk * 8 + c;
                ah[mt][0] = __float_as_uint(ph[0]);
                ah[mt][1] = __float_as_uint(ph[8 * PAS]);
                ah[mt][2] = __float_as_uint(ph[4]);
                ah[mt][3] = __float_as_uint(ph[8 * PAS + 4]);
                al[mt][0] = __float_as_uint(pl[0]);
                al[mt][1] = __float_as_uint(pl[8 * PAS]);
                al[mt][2] = __float_as_uint(pl[4]);
                al[mt][3] = __float_as_uint(pl[8 * PAS + 4]);
            }
            #pragma unroll
            for (int nt = 0; nt < 4; nt++) {
                int col = wn + nt * 8 + r;
                const float* qh = Bs_h + (kk * 8 + c) * PBS + col;
                const float* ql = Bs_l + (kk * 8 + c) * PBS + col;
                bh[nt][0] = __float_as_uint(qh[0]);
                bh[nt][1] = __float_as_uint(qh[4 * PBS]);
                bl[nt][0] = __float_as_uint(ql[0]);
                bl[nt][1] = __float_as_uint(ql[4 * PBS]);
            }
            #pragma unroll
            for (int mt = 0; mt < 2; mt++)
                #pragma unroll
                for (int nt = 0; nt < 4; nt++) {
                    mma8(acc[mt][nt], ah[mt], bh[nt]);
                    mma8(acc[mt][nt], al[mt], bh[nt]);
                    mma8(acc[mt][nt], ah[mt], bl[nt]);
                }
        }
        __syncthreads();
    }

    #pragma unroll
    for (int mt = 0; mt < 2; mt++) {
        int gm0 = bm + wm + mt * 16 + r;
        #pragma unroll
        for (int nt = 0; nt < 4; nt++) {
            int gn = bn + wn + nt * 8 + 2 * c;
            if (gn >= N) continue;
            float b0 = bias[gn], b1 = bias[gn + 1];
            float v0 = acc[mt][nt][0] + b0;
            float v1 = acc[mt][nt][1] + b1;
            float v2 = acc[mt][nt][2] + b0;
            float v3 = acc[mt][nt][3] + b1;
            v0 = v0 > 0.f ? v0 : NEG_SLOPE * v0;
            v1 = v1 > 0.f ? v1 : NEG_SLOPE * v1;
            v2 = v2 > 0.f ? v2 : NEG_SLOPE * v2;
            v3 = v3 > 0.f ? v3 : NEG_SLOPE * v3;
            *reinterpret_cast<float2*>(g_z + (size_t)gm0 * N + gn) = make_float2(v0, v1);
            *reinterpret_cast<float2*>(g_z + (size_t)(gm0 + 8) * N + gn) = make_float2(v2, v3);
        }
    }
}

// ---------------------------------------------------------------------------
__global__ void normalize_kernel(float* __restrict__ out) {
    int row  = (blockIdx.x * blockDim.x + threadIdx.x) >> 5;
    int lane = threadIdx.x & 31;
    if (row >= 2 * N_PAIRS) return;
    const float* zr = g_z + (size_t)row * D_OUT;
    float ss = 0.f;
    for (int i = lane; i < D_OUT; i += 32) { float v = zr[i]; ss += v * v; }
    #pragma unroll
    for (int o = 16; o; o >>= 1) ss += __shfl_xor_sync(0xFFFFFFFFu, ss, o);
    float norm = sqrtf(ss);
    float inv = 1.f / fmaxf(norm, 1e-12f);
    for (int i = lane; i < D_OUT; i += 32) out[(size_t)row * D_OUT + i] = zr[i] * inv;
}

// ---------------------------------------------------------------------------
extern "C" void kernel_launch(void* const* d_in, const int* in_sizes, int n_in,
                              void* d_out, int out_size) {
    const float* features = (const float*)d_in[0];
    const int*   src      = (const int*)  d_in[1];
    const int*   dst      = (const int*)  d_in[2];
    const int*   v1       = (const int*)  d_in[3];
    const int*   v2       = (const int*)  d_in[4];
    const float* W1       = (const float*)d_in[5];
    const float* b1       = (const float*)d_in[6];
    const float* W2       = (const float*)d_in[7];
    const float* b2       = (const float*)d_in[8];
    const float* W3       = (const float*)d_in[9];
    const float* b3       = (const float*)d_in[10];
    float* out = (float*)d_out;
    (void)in_sizes; (void)n_in; (void)out_size;

    size_t tc_smem = (size_t)2 * STAGE_U32 * sizeof(uint32_t);      // 108544 B
    cudaFuncSetAttribute(gemm_nodes_tc, cudaFuncAttributeMaxDynamicSharedMemorySize,
                         (int)tc_smem);
    size_t p_smem = (size_t)P_SMEM_FLOATS * sizeof(float);
    cudaFuncSetAttribute(gemm_pairs_tc, cudaFuncAttributeMaxDynamicSharedMemorySize,
                         (int)p_smem);

    dim3 tc_grid1((D_FEAT + TC_BN - 1) / TC_BN, (N_NODES + TC_BM - 1) / TC_BM);
    dim3 tc_grid2((D_FEAT + TC_BN - 1) / TC_BN, (2 * N_PAIRS) / TC_BM);  // 128 m-tiles max
    dim3 pairs_grid((D_OUT + P_BN - 1) / P_BN, (2 * N_PAIRS) / TC_BM);
    int gather1_blocks = (N_NODES * 64 + 255) / 256;
    int gather2_blocks = (2 * N_PAIRS * 64 + 255) / 256;
    int convw_blocks = (AKP * (WB_NS / 4) + 255) / 256;

    // CSR by dst + pair-node compaction
    csr_zero_kernel<<<(N_NODES + 255) / 256, 256>>>();
    csr_count_kernel<<<(N_EDGES + 255) / 256, 256>>>(dst);
    mark_set_kernel<<<(N_PAIRS + 255) / 256, 256>>>(v1, v2);
    csr_scan_kernel<<<1, 1024>>>();
    compact_scan_kernel<<<1, 1024>>>();
    csr_fill_kernel<<<(N_EDGES + 255) / 256, 256>>>(src, dst);

    // layer 1 (all nodes)
    convert_w_kernel<<<convw_blocks, 256>>>(W1);
    gather_kernel<<<gather1_blocks, 256>>>(features);
    gemm_nodes_tc<<<tc_grid1, 256, tc_smem>>>(b1, /*m_mode=*/0);

    // layer 2 (compact pair nodes only)
    convert_w_kernel<<<convw_blocks, 256>>>(W2);
    gather2_kernel<<<gather2_blocks, 256>>>();
    gemm_nodes_tc<<<tc_grid2, 256, tc_smem>>>(b2, /*m_mode=*/1);

    // pair projection + normalize
    gemm_pairs_tc<<<pairs_grid, 256, p_smem>>>(v1, v2, W3, b3);
    normalize_kernel<<<(2 * N_PAIRS * 32 + 255) / 256, 256>>>(out);
}

// round 13
// speedup vs baseline: 1.5370x; 1.1850x over previous
#include <cuda_runtime.h>
#include <cuda_bf16.h>
#include <math.h>
#include <stdint.h>

#define N_NODES 50000
#define D_FEAT  364
#define D_OUT   150
#define N_PAIRS 8192
#define N_EDGES 200000
#define NEG_SLOPE 0.01f

#define AKP 192
#define WB_NS 384

#define SCAN_B 256
#define SCAN_NB ((N_NODES + SCAN_B - 1) / SCAN_B)   // 196

// Scratch (no cudaMalloc allowed).
__device__ __align__(16) float g_h1 [(size_t)N_NODES * D_FEAT];
__device__ __align__(16) float g_h2 [(size_t)2 * N_PAIRS * D_FEAT];   // compact
__device__ __align__(16) float g_z  [(size_t)2 * N_PAIRS * D_OUT];
__device__ __align__(16) uint32_t g_agg_h[(size_t)N_NODES * AKP];
__device__ __align__(16) uint32_t g_agg_l[(size_t)N_NODES * AKP];
__device__ __align__(16) uint32_t g_wb_h [(size_t)AKP * WB_NS];
__device__ __align__(16) uint32_t g_wb_l [(size_t)AKP * WB_NS];

// CSR-by-dst scratch
__device__ int g_deg [N_NODES];
__device__ int g_off [N_NODES];
__device__ int g_pos [N_NODES];
__device__ int g_srcs[N_EDGES];

// pair-node compaction
__device__ int g_mark  [N_NODES];
__device__ int g_newidx[N_NODES];
__device__ int g_list  [2 * N_PAIRS];
__device__ int g_count;

// scan block sums
__device__ int g_bs_deg [SCAN_NB];
__device__ int g_bs_mark[SCAN_NB];

// ---------------------------------------------------------------------------
__device__ __forceinline__ void split1(float v, __nv_bfloat16& h, __nv_bfloat16& l) {
    h = __float2bfloat16_rn(v);
    l = __float2bfloat16_rn(v - __bfloat162float(h));
}
__device__ __forceinline__ uint32_t pack2(__nv_bfloat16 lo, __nv_bfloat16 hi) {
    __nv_bfloat162 p;
    p.x = lo; p.y = hi;
    return *reinterpret_cast<uint32_t*>(&p);
}

// ---------------------------------------------------------------------------
// CSR build + compaction, 3-phase grid scan
__global__ void csr_zero_kernel() {
    int i = blockIdx.x * blockDim.x + threadIdx.x;
    if (i < N_NODES) { g_deg[i] = 0; g_mark[i] = 0; }
}
__global__ void csr_count_kernel(const int* __restrict__ dst) {
    int e = blockIdx.x * blockDim.x + threadIdx.x;
    if (e < N_EDGES) atomicAdd(&g_deg[dst[e]], 1);
}
__global__ void mark_set_kernel(const int* __restrict__ v1,
                                const int* __restrict__ v2) {
    int i = blockIdx.x * blockDim.x + threadIdx.x;
    if (i < N_PAIRS) { g_mark[v1[i]] = 1; g_mark[v2[i]] = 1; }
}

// phase 1: per-block sums of deg and mark
__global__ void scan_partial_kernel() {
    __shared__ int wsum_d[8], wsum_m[8];
    int tid = threadIdx.x, lane = tid & 31, w = tid >> 5;
    int i = blockIdx.x * SCAN_B + tid;
    int vd = (i < N_NODES) ? g_deg[i] : 0;
    int vm = (i < N_NODES) ? g_mark[i] : 0;
    #pragma unroll
    for (int o = 16; o; o >>= 1) {
        vd += __shfl_xor_sync(0xFFFFFFFFu, vd, o);
        vm += __shfl_xor_sync(0xFFFFFFFFu, vm, o);
    }
    if (lane == 0) { wsum_d[w] = vd; wsum_m[w] = vm; }
    __syncthreads();
    if (tid == 0) {
        int sd = 0, sm = 0;
        #pragma unroll
        for (int j = 0; j < 8; j++) { sd += wsum_d[j]; sm += wsum_m[j]; }
        g_bs_deg[blockIdx.x] = sd;
        g_bs_mark[blockIdx.x] = sm;
    }
}

// phase 2: exclusive scan of block sums (single block, 256 thr covers 196)
__global__ void scan_blocksums_kernel() {
    __shared__ int wt_d[8], wt_m[8];
    int tid = threadIdx.x, lane = tid & 31, w = tid >> 5;
    int vd = (tid < SCAN_NB) ? g_bs_deg[tid] : 0;
    int vm = (tid < SCAN_NB) ? g_bs_mark[tid] : 0;
    int sd = vd, sm = vm;
    #pragma unroll
    for (int o = 1; o < 32; o <<= 1) {
        int td = __shfl_up_sync(0xFFFFFFFFu, sd, o);
        int tm = __shfl_up_sync(0xFFFFFFFFu, sm, o);
        if (lane >= o) { sd += td; sm += tm; }
    }
    if (lane == 31) { wt_d[w] = sd; wt_m[w] = sm; }
    __syncthreads();
    if (w == 0) {
        int td = (lane < 8) ? wt_d[lane] : 0;
        int tm = (lane < 8) ? wt_m[lane] : 0;
        int sd2 = td, sm2 = tm;
        #pragma unroll
        for (int o = 1; o < 8; o <<= 1) {
            int ud = __shfl_up_sync(0xFFFFFFFFu, sd2, o);
            int um = __shfl_up_sync(0xFFFFFFFFu, sm2, o);
            if (lane >= o) { sd2 += ud; sm2 += um; }
        }
        if (lane < 8) { wt_d[lane] = sd2 - td; wt_m[lane] = sm2 - tm; }
    }
    __syncthreads();
    if (tid < SCAN_NB) {
        g_bs_deg[tid]  = sd - vd + wt_d[w];   // exclusive
        g_bs_mark[tid] = sm - vm + wt_m[w];
    }
    if (tid == SCAN_NB - 1) g_count = sm + wt_m[w];   // inclusive total of mark
}

// phase 3: per-block exclusive scan + add block offset, emit outputs
__global__ void scan_final_kernel() {
    __shared__ int wt_d[8], wt_m[8];
    int tid = threadIdx.x, lane = tid & 31, w = tid >> 5;
    int i = blockIdx.x * SCAN_B + tid;
    int vd = (i < N_NODES) ? g_deg[i] : 0;
    int vm = (i < N_NODES) ? g_mark[i] : 0;
    int sd = vd, sm = vm;
    #pragma unroll
    for (int o = 1; o < 32; o <<= 1) {
        int td = __shfl_up_sync(0xFFFFFFFFu, sd, o);
        int tm = __shfl_up_sync(0xFFFFFFFFu, sm, o);
        if (lane >= o) { sd += td; sm += tm; }
    }
    if (lane == 31) { wt_d[w] = sd; wt_m[w] = sm; }
    __syncthreads();
    if (w == 0) {
        int td = (lane < 8) ? wt_d[lane] : 0;
        int tm = (lane < 8) ? wt_m[lane] : 0;
        int sd2 = td, sm2 = tm;
        #pragma unroll
        for (int o = 1; o < 8; o <<= 1) {
            int ud = __shfl_up_sync(0xFFFFFFFFu, sd2, o);
            int um = __shfl_up_sync(0xFFFFFFFFu, sm2, o);
            if (lane >= o) { sd2 += ud; sm2 += um; }
        }
        if (lane < 8) { wt_d[lane] = sd2 - td; wt_m[lane] = sm2 - tm; }
    }
    __syncthreads();
    if (i < N_NODES) {
        int off_d = g_bs_deg[blockIdx.x]  + sd - vd + wt_d[w];
        int off_m = g_bs_mark[blockIdx.x] + sm - vm + wt_m[w];
        g_off[i] = off_d;
        g_pos[i] = off_d;
        g_newidx[i] = off_m;
        if (vm) g_list[off_m] = i;
    }
}

__global__ void csr_fill_kernel(const int* __restrict__ src,
                                const int* __restrict__ dst) {
    int e = blockIdx.x * blockDim.x + threadIdx.x;
    if (e >= N_EDGES) return;
    int idx = atomicAdd(&g_pos[dst[e]], 1);
    g_srcs[idx] = src[e];
}

// ---------------------------------------------------------------------------
// gather core: agg(outrow) = x[node] + sum_in x[src], bf16-split output.
__device__ __forceinline__ void gather_one(const float* __restrict__ x,
                                           int node, int outrow,
                                           int half, int lane) {
    int off = g_off[node];
    int deg = g_deg[node];

    int base4 = half * 46;
    int cnt   = half ? 45 : 46;
    int i0 = base4 + lane;
    int i1 = base4 + 32 + lane;
    bool p1 = (32 + lane) < cnt;

    const float4* xd = reinterpret_cast<const float4*>(x + (size_t)node * D_FEAT);
    float4 a0 = xd[i0];
    float4 a1 = p1 ? xd[i1] : make_float4(0.f, 0.f, 0.f, 0.f);

    for (int e = 0; e < deg; e++) {
        int s = g_srcs[off + e];
        const float4* xs = reinterpret_cast<const float4*>(x + (size_t)s * D_FEAT);
        float4 v0 = xs[i0];
        a0.x += v0.x; a0.y += v0.y; a0.z += v0.z; a0.w += v0.w;
        if (p1) {
            float4 v1 = xs[i1];
            a1.x += v1.x; a1.y += v1.y; a1.z += v1.z; a1.w += v1.w;
        }
    }

    uint32_t* oh = g_agg_h + (size_t)outrow * AKP;
    uint32_t* ol = g_agg_l + (size_t)outrow * AKP;
    {
        __nv_bfloat16 hx, lx, hy, ly, hz, lz, hw, lw;
        split1(a0.x, hx, lx); split1(a0.y, hy, ly);
        split1(a0.z, hz, lz); split1(a0.w, hw, lw);
        *reinterpret_cast<uint2*>(oh + 2 * i0) = make_uint2(pack2(hx, hy), pack2(hz, hw));
        *reinterpret_cast<uint2*>(ol + 2 * i0) = make_uint2(pack2(lx, ly), pack2(lz, lw));
    }
    if (p1) {
        __nv_bfloat16 hx, lx, hy, ly, hz, lz, hw, lw;
        split1(a1.x, hx, lx); split1(a1.y, hy, ly);
        split1(a1.z, hz, lz); split1(a1.w, hw, lw);
        *reinterpret_cast<uint2*>(oh + 2 * i1) = make_uint2(pack2(hx, hy), pack2(hz, hw));
        *reinterpret_cast<uint2*>(ol + 2 * i1) = make_uint2(pack2(lx, ly), pack2(lz, lw));
    }
    if (half && lane >= 13 && lane <= 17) {   // zero-pad k4 91..95
        *reinterpret_cast<uint2*>(oh + 2 * i1) = make_uint2(0u, 0u);
        *reinterpret_cast<uint2*>(ol + 2 * i1) = make_uint2(0u, 0u);
    }
}

__global__ void gather_kernel(const float* __restrict__ x_ext) {
    int gw = (blockIdx.x * blockDim.x + threadIdx.x) >> 5;
    int lane = threadIdx.x & 31;
    int node = gw >> 1;
    int half = gw & 1;
    if (node >= N_NODES) return;
    gather_one(x_ext, node, node, half, lane);
}
__global__ void gather2_kernel() {
    int gw = (blockIdx.x * blockDim.x + threadIdx.x) >> 5;
    int lane = threadIdx.x & 31;
    int i = gw >> 1;
    int half = gw & 1;
    if (i >= g_count) return;
    gather_one(g_h1, g_list[i], i, half, lane);
}

// ---------------------------------------------------------------------------
// convert W [K x N] fp32 -> g_wb_h/l
__global__ void convert_w_kernel(const float* __restrict__ W) {
    int idx = blockIdx.x * blockDim.x + threadIdx.x;
    int kp = idx / (WB_NS / 4);
    int nq = idx % (WB_NS / 4);
    if (kp >= AKP) return;
    int n0 = nq * 4;
    uint32_t oh[4], ol[4];
    #pragma unroll
    for (int j = 0; j < 4; j++) {
        int n = n0 + j;
        float v0 = 0.f, v1 = 0.f;
        if (2 * kp < D_FEAT && n < D_FEAT) {
            v0 = W[(size_t)(2 * kp) * D_FEAT + n];
            v1 = W[(size_t)(2 * kp + 1) * D_FEAT + n];
        }
        __nv_bfloat16 h0, l0, h1, l1;
        split1(v0, h0, l0);
        split1(v1, h1, l1);
        oh[j] = pack2(h0, h1);
        ol[j] = pack2(l0, l1);
    }
    size_t o = (size_t)kp * WB_NS + n0;
    *reinterpret_cast<uint4*>(g_wb_h + o) = make_uint4(oh[0], oh[1], oh[2], oh[3]);
    *reinterpret_cast<uint4*>(g_wb_l + o) = make_uint4(ol[0], ol[1], ol[2], ol[3]);
}

// ---------------------------------------------------------------------------
__device__ __forceinline__ void mma16(float d[4], const uint32_t a[4], const uint32_t b[2]) {
    asm volatile(
        "mma.sync.aligned.m16n8k16.row.col.f32.bf16.bf16.f32 "
        "{%0,%1,%2,%3}, {%4,%5,%6,%7}, {%8,%9}, {%0,%1,%2,%3};\n"
        : "+f"(d[0]), "+f"(d[1]), "+f"(d[2]), "+f"(d[3])
        : "r"(a[0]), "r"(a[1]), "r"(a[2]), "r"(a[3]), "r"(b[0]), "r"(b[1]));
}
__device__ __forceinline__ void cp_async16(uint32_t smem_addr, const void* gptr, int src_bytes) {
    asm volatile("cp.async.cg.shared.global [%0], [%1], 16, %2;"
                 :: "r"(smem_addr), "l"(gptr), "r"(src_bytes) : "memory");
}
__device__ __forceinline__ void cp_async_commit() {
    asm volatile("cp.async.commit_group;" ::: "memory");
}
__device__ __forceinline__ void cp_async_wait0() {
    asm volatile("cp.async.wait_group 0;" ::: "memory");
}

// ---------------------------------------------------------------------------
// node GEMM: bf16x3, cp.async double buffer, 2 CTAs/SM.
#define TC_BM 128
#define TC_BN 128
#define AS2 36
#define BS2 136
#define A_U32 (TC_BM * AS2)
#define B_U32 (16 * BS2)
#define STAGE_U32 (2 * A_U32 + 2 * B_U32)   // 13568
#define NUM_KT 12

__global__ __launch_bounds__(256, 2) void gemm_nodes_tc(
        const float* __restrict__ bias, int m_mode) {
    const int N = D_FEAT;
    int M = m_mode ? g_count : N_NODES;
    float* __restrict__ out = m_mode ? g_h2 : g_h1;

    int bm = blockIdx.y * TC_BM;
    if (bm >= M) return;
    int bn = blockIdx.x * TC_BN;

    extern __shared__ uint32_t smu[];
    uint32_t smem_base = (uint32_t)__cvta_generic_to_shared(smu);

    int tid = threadIdx.x;
    int lane = tid & 31;
    int wid = tid >> 5;
    int wm = (wid & 1) * 64;
    int wn = (wid >> 1) * 32;
    int r = lane >> 2;
    int c = lane & 3;

    float acc[4][4][4];
    #pragma unroll
    for (int i = 0; i < 4; i++)
        #pragma unroll
        for (int j = 0; j < 4; j++)
            #pragma unroll
            for (int q = 0; q < 4; q++) acc[i][j][q] = 0.f;

    int a_row = tid >> 2;
    int a_q4  = tid & 3;
    int b_kp = tid >> 5;
    int b_n4 = tid & 31;

    auto copy_tile = [&](int t, int stage) {
        int kp0 = t * 16;
        uint32_t sbase = smem_base + (uint32_t)(stage * STAGE_U32 * 4);
        uint32_t As_h = sbase;
        uint32_t As_l = sbase + (uint32_t)(A_U32 * 4);
        uint32_t Bs_h = sbase + (uint32_t)(2 * A_U32 * 4);
        uint32_t Bs_l = Bs_h + (uint32_t)(B_U32 * 4);
        #pragma unroll
        for (int p = 0; p < 2; p++) {
            int m = p * 64 + a_row;
            int gm = bm + m;
            int ok = (gm < M) ? 16 : 0;
            size_t go = (size_t)gm * AKP + kp0 + a_q4 * 4;
            uint32_t so = (uint32_t)((m * AS2 + a_q4 * 4) * 4);
            cp_async16(As_h + so, g_agg_h + go, ok);
            cp_async16(As_l + so, g_agg_l + go, ok);
        }
        #pragma unroll
        for (int p = 0; p < 2; p++) {
            int kp = p * 8 + b_kp;
            size_t go = (size_t)(kp0 + kp) * WB_NS + bn + b_n4 * 4;
            uint32_t so = (uint32_t)((kp * BS2 + b_n4 * 4) * 4);
            cp_async16(Bs_h + so, g_wb_h + go, 16);
            cp_async16(Bs_l + so, g_wb_l + go, 16);
        }
        cp_async_commit();
    };

    copy_tile(0, 0);
    cp_async_wait0();
    __syncthreads();

    for (int t = 0; t < NUM_KT; t++) {
        if (t + 1 < NUM_KT) copy_tile(t + 1, (t + 1) & 1);

        {
            const uint32_t* base = smu + (t & 1) * STAGE_U32;
            const uint32_t* As_h = base;
            const uint32_t* As_l = base + A_U32;
            const uint32_t* Bs_h = base + 2 * A_U32;
            const uint32_t* Bs_l = Bs_h + B_U32;

            #pragma unroll
            for (int kk = 0; kk < 2; kk++) {
                uint32_t ah[4][4], al[4][4], bh[4][2], bl[4][2];
                #pragma unroll
                for (int mt = 0; mt < 4; mt++) {
                    int row = wm + mt * 16 + r;
                    const uint32_t* ph = As_h + row * AS2 + kk * 8 + c;
                    const uint32_t* pl = As_l + row * AS2 + kk * 8 + c;
                    ah[mt][0] = ph[0];
                    ah[mt][1] = ph[8 * AS2];
                    ah[mt][2] = ph[4];
                    ah[mt][3] = ph[8 * AS2 + 4];
                    al[mt][0] = pl[0];
                    al[mt][1] = pl[8 * AS2];
                    al[mt][2] = pl[4];
                    al[mt][3] = pl[8 * AS2 + 4];
                }
                #pragma unroll
                for (int nt = 0; nt < 4; nt++) {
                    int col = wn + nt * 8 + r;
                    const uint32_t* qh = Bs_h + (kk * 8 + c) * BS2 + col;
                    const uint32_t* ql = Bs_l + (kk * 8 + c) * BS2 + col;
                    bh[nt][0] = qh[0];
                    bh[nt][1] = qh[4 * BS2];
                    bl[nt][0] = ql[0];
                    bl[nt][1] = ql[4 * BS2];
                }
                #pragma unroll
                for (int mt = 0; mt < 4; mt++)
                    #pragma unroll
                    for (int nt = 0; nt < 4; nt++) {
                        mma16(acc[mt][nt], ah[mt], bh[nt]);
                        mma16(acc[mt][nt], al[mt], bh[nt]);
                        mma16(acc[mt][nt], ah[mt], bl[nt]);
                    }
            }
        }

        if (t + 1 < NUM_KT) cp_async_wait0();
        __syncthreads();
    }

    #pragma unroll
    for (int mt = 0; mt < 4; mt++) {
        int gm0 = bm + wm + mt * 16 + r;
        #pragma unroll
        for (int nt = 0; nt < 4; nt++) {
            int gn = bn + wn + nt * 8 + 2 * c;
            if (gn >= N) continue;
            float b0 = bias[gn], b1 = bias[gn + 1];
            float v0 = acc[mt][nt][0] + b0;
            float v1 = acc[mt][nt][1] + b1;
            float v2 = acc[mt][nt][2] + b0;
            float v3 = acc[mt][nt][3] + b1;
            v0 = v0 > 0.f ? v0 : NEG_SLOPE * v0;
            v1 = v1 > 0.f ? v1 : NEG_SLOPE * v1;
            v2 = v2 > 0.f ? v2 : NEG_SLOPE * v2;
            v3 = v3 > 0.f ? v3 : NEG_SLOPE * v3;
            if (gm0 < M)
                *reinterpret_cast<float2*>(out + (size_t)gm0 * N + gn) = make_float2(v0, v1);
            if (gm0 + 8 < M)
                *reinterpret_cast<float2*>(out + (size_t)(gm0 + 8) * N + gn) = make_float2(v2, v3);
        }
    }
}

// ---------------------------------------------------------------------------
// tf32 helpers for pairs GEMM
__device__ __forceinline__ uint32_t f2tf32(float x) {
    uint32_t r;
    asm("cvt.rna.tf32.f32 %0, %1;" : "=r"(r) : "f"(x));
    return r;
}
__device__ __forceinline__ void split_tf32(float v, float& h, float& l) {
    h = __uint_as_float(f2tf32(v));
    l = __uint_as_float(f2tf32(v - h));
}
__device__ __forceinline__ void mma8(float d[4], const uint32_t a[4], const uint32_t b[2]) {
    asm volatile(
        "mma.sync.aligned.m16n8k8.row.col.f32.tf32.tf32.f32 "
        "{%0,%1,%2,%3}, {%4,%5,%6,%7}, {%8,%9}, {%0,%1,%2,%3};\n"
        : "+f"(d[0]), "+f"(d[1]), "+f"(d[2]), "+f"(d[3])
        : "r"(a[0]), "r"(a[1]), "r"(a[2]), "r"(a[3]), "r"(b[0]), "r"(b[1]));
}

// ---------------------------------------------------------------------------
// pairs GEMM (tf32x3): g_z = lrelu(h2c[newidx[vcat]] @ W3 + b3)
#define P_BN 64
#define P_BK 32
#define PAS 36
#define PBS 72
#define P_A_FLOATS (TC_BM * PAS)
#define P_B_FLOATS (P_BK * PBS)
#define P_SMEM_FLOATS (2 * P_A_FLOATS + 2 * P_B_FLOATS)

__global__ __launch_bounds__(256) void gemm_pairs_tc(
        const int* __restrict__ v1, const int* __restrict__ v2,
        const float* __restrict__ W, const float* __restrict__ bias) {
    const int K = D_FEAT, N = D_OUT;

    extern __shared__ float smf[];
    float* As_h = smf;
    float* As_l = smf + P_A_FLOATS;
    float* Bs_h = smf + 2 * P_A_FLOATS;
    float* Bs_l = Bs_h + P_B_FLOATS;
    __shared__ int rows[TC_BM];

    int bm = blockIdx.y * TC_BM;
    int bn = blockIdx.x * P_BN;
    int tid = threadIdx.x;
    int lane = tid & 31;
    int wid = tid >> 5;
    int wm = (wid & 3) * 32;
    int wn = (wid >> 2) * 32;
    int r = lane >> 2;
    int c = lane & 3;

    if (tid < TC_BM) {
        int gm = bm + tid;
        int v = (gm < N_PAIRS) ? v1[gm] : v2[gm - N_PAIRS];
        rows[tid] = g_newidx[v];
    }
    __syncthreads();

    float acc[2][4][4];
    #pragma unroll
    for (int i = 0; i < 2; i++)
        #pragma unroll
        for (int j = 0; j < 4; j++)
            #pragma unroll
            for (int q = 0; q < 4; q++) acc[i][j][q] = 0.f;

    int ak4 = tid & 7;
    int arl = tid >> 3;
    int bn4 = tid & 15;
    int bkr = tid >> 4;

    for (int k0 = 0; k0 < K; k0 += P_BK) {
        #pragma unroll
        for (int p = 0; p < 4; p++) {
            int m = p * 32 + arl;
            int node = rows[m];
            int gk = k0 + ak4 * 4;
            float4 v = (gk < K)
                ? *reinterpret_cast<const float4*>(g_h2 + (size_t)node * K + gk)
                : make_float4(0.f, 0.f, 0.f, 0.f);
            float4 h, l;
            split_tf32(v.x, h.x, l.x);
            split_tf32(v.y, h.y, l.y);
            split_tf32(v.z, h.z, l.z);
            split_tf32(v.w, h.w, l.w);
            *reinterpret_cast<float4*>(As_h + m * PAS + ak4 * 4) = h;
            *reinterpret_cast<float4*>(As_l + m * PAS + ak4 * 4) = l;
        }
        #pragma unroll
        for (int p = 0; p < 2; p++) {
            int kr = p * 16 + bkr;
            int gk = k0 + kr;
            int gn = bn + bn4 * 4;
            float4 v = make_float4(0.f, 0.f, 0.f, 0.f);
            if (gk < K) {
                const float* wrow = W + (size_t)gk * N;
                if (gn + 3 < N) {
                    float2 lo = *reinterpret_cast<const float2*>(wrow + gn);
                    float2 hi = *reinterpret_cast<const float2*>(wrow + gn + 2);
                    v = make_float4(lo.x, lo.y, hi.x, hi.y);
                } else {
                    #pragma unroll
                    for (int j = 0; j < 4; j++) {
                        int nn = gn + j;
                        reinterpret_cast<float*>(&v)[j] = (nn < N) ? wrow[nn] : 0.f;
                    }
                }
            }
            float4 h, l;
            split_tf32(v.x, h.x, l.x);
            split_tf32(v.y, h.y, l.y);
            split_tf32(v.z, h.z, l.z);
            split_tf32(v.w, h.w, l.w);
            *reinterpret_cast<float4*>(Bs_h + kr * PBS + bn4 * 4) = h;
            *reinterpret_cast<float4*>(Bs_l + kr * PBS + bn4 * 4) = l;
        }
        __syncthreads();

        #pragma unroll
        for (int kk = 0; kk < 4; kk++) {
            uint32_t ah[2][4], al[2][4], bh[4][2], bl[4][2];
            #pragma unroll
            for (int mt = 0; mt < 2; mt++) {
                int row = wm + mt * 16 + r;
                const float* ph = As_h + row * PAS + kk * 8 + c;
                const float* pl = As_l + row * PAS + kk * 8 + c;
                ah[mt][0] = __float_as_uint(ph[0]);
                ah[mt][1] = __float_as_uint(ph[8 * PAS]);
                ah[mt][2] = __float_as_uint(ph[4]);
                ah[mt][3] = __float_as_uint(ph[8 * PAS + 4]);
                al[mt][0] = __float_as_uint(pl[0]);
                al[mt][1] = __float_as_uint(pl[8 * PAS]);
                al[mt][2] = __float_as_uint(pl[4]);
                al[mt][3] = __float_as_uint(pl[8 * PAS + 4]);
            }
            #pragma unroll
            for (int nt = 0; nt < 4; nt++) {
                int col = wn + nt * 8 + r;
                const float* qh = Bs_h + (kk * 8 + c) * PBS + col;
                const float* ql = Bs_l + (kk * 8 + c) * PBS + col;
                bh[nt][0] = __float_as_uint(qh[0]);
                bh[nt][1] = __float_as_uint(qh[4 * PBS]);
                bl[nt][0] = __float_as_uint(ql[0]);
                bl[nt][1] = __float_as_uint(ql[4 * PBS]);
            }
            #pragma unroll
            for (int mt = 0; mt < 2; mt++)
                #pragma unroll
                for (int nt = 0; nt < 4; nt++) {
                    mma8(acc[mt][nt], ah[mt], bh[nt]);
                    mma8(acc[mt][nt], al[mt], bh[nt]);
                    mma8(acc[mt][nt], ah[mt], bl[nt]);
                }
        }
        __syncthreads();
    }

    #pragma unroll
    for (int mt = 0; mt < 2; mt++) {
        int gm0 = bm + wm + mt * 16 + r;
        #pragma unroll
        for (int nt = 0; nt < 4; nt++) {
            int gn = bn + wn + nt * 8 + 2 * c;
            if (gn >= N) continue;
            float b0 = bias[gn], b1 = bias[gn + 1];
            float v0 = acc[mt][nt][0] + b0;
            float v1 = acc[mt][nt][1] + b1;
            float v2 = acc[mt][nt][2] + b0;
            float v3 = acc[mt][nt][3] + b1;
            v0 = v0 > 0.f ? v0 : NEG_SLOPE * v0;
            v1 = v1 > 0.f ? v1 : NEG_SLOPE * v1;
            v2 = v2 > 0.f ? v2 : NEG_SLOPE * v2;
            v3 = v3 > 0.f ? v3 : NEG_SLOPE * v3;
            *reinterpret_cast<float2*>(g_z + (size_t)gm0 * N + gn) = make_float2(v0, v1);
            *reinterpret_cast<float2*>(g_z + (size_t)(gm0 + 8) * N + gn) = make_float2(v2, v3);
        }
    }
}

// ---------------------------------------------------------------------------
__global__ void normalize_kernel(float* __restrict__ out) {
    int row  = (blockIdx.x * blockDim.x + threadIdx.x) >> 5;
    int lane = threadIdx.x & 31;
    if (row >= 2 * N_PAIRS) return;
    const float* zr = g_z + (size_t)row * D_OUT;
    float ss = 0.f;
    for (int i = lane; i < D_OUT; i += 32) { float v = zr[i]; ss += v * v; }
    #pragma unroll
    for (int o = 16; o; o >>= 1) ss += __shfl_xor_sync(0xFFFFFFFFu, ss, o);
    float norm = sqrtf(ss);
    float inv = 1.f / fmaxf(norm, 1e-12f);
    for (int i = lane; i < D_OUT; i += 32) out[(size_t)row * D_OUT + i] = zr[i] * inv;
}

// ---------------------------------------------------------------------------
extern "C" void kernel_launch(void* const* d_in, const int* in_sizes, int n_in,
                              void* d_out, int out_size) {
    const float* features = (const float*)d_in[0];
    const int*   src      = (const int*)  d_in[1];
    const int*   dst      = (const int*)  d_in[2];
    const int*   v1       = (const int*)  d_in[3];
    const int*   v2       = (const int*)  d_in[4];
    const float* W1       = (const float*)d_in[5];
    const float* b1       = (const float*)d_in[6];
    const float* W2       = (const float*)d_in[7];
    const float* b2       = (const float*)d_in[8];
    const float* W3       = (const float*)d_in[9];
    const float* b3       = (const float*)d_in[10];
    float* out = (float*)d_out;
    (void)in_sizes; (void)n_in; (void)out_size;

    size_t tc_smem = (size_t)2 * STAGE_U32 * sizeof(uint32_t);      // 108544 B
    cudaFuncSetAttribute(gemm_nodes_tc, cudaFuncAttributeMaxDynamicSharedMemorySize,
                         (int)tc_smem);
    size_t p_smem = (size_t)P_SMEM_FLOATS * sizeof(float);
    cudaFuncSetAttribute(gemm_pairs_tc, cudaFuncAttributeMaxDynamicSharedMemorySize,
                         (int)p_smem);

    dim3 tc_grid1((D_FEAT + TC_BN - 1) / TC_BN, (N_NODES + TC_BM - 1) / TC_BM);
    dim3 tc_grid2((D_FEAT + TC_BN - 1) / TC_BN, (2 * N_PAIRS) / TC_BM);
    dim3 pairs_grid((D_OUT + P_BN - 1) / P_BN, (2 * N_PAIRS) / TC_BM);
    int gather1_blocks = (N_NODES * 64 + 255) / 256;
    int gather2_blocks = (2 * N_PAIRS * 64 + 255) / 256;
    int convw_blocks = (AKP * (WB_NS / 4) + 255) / 256;

    // CSR by dst + pair-node compaction (3-phase grid scan)
    csr_zero_kernel<<<(N_NODES + 255) / 256, 256>>>();
    csr_count_kernel<<<(N_EDGES + 255) / 256, 256>>>(dst);
    mark_set_kernel<<<(N_PAIRS + 255) / 256, 256>>>(v1, v2);
    scan_partial_kernel<<<SCAN_NB, SCAN_B>>>();
    scan_blocksums_kernel<<<1, 256>>>();
    scan_final_kernel<<<SCAN_NB, SCAN_B>>>();
    csr_fill_kernel<<<(N_EDGES + 255) / 256, 256>>>(src, dst);

    // layer 1 (all nodes)
    convert_w_kernel<<<convw_blocks, 256>>>(W1);
    gather_kernel<<<gather1_blocks, 256>>>(features);
    gemm_nodes_tc<<<tc_grid1, 256, tc_smem>>>(b1, /*m_mode=*/0);

    // layer 2 (compact pair nodes only)
    convert_w_kernel<<<convw_blocks, 256>>>(W2);
    gather2_kernel<<<gather2_blocks, 256>>>();
    gemm_nodes_tc<<<tc_grid2, 256, tc_smem>>>(b2, /*m_mode=*/1);

    // pair projection + normalize
    gemm_pairs_tc<<<pairs_grid, 256, p_smem>>>(v1, v2, W3, b3);
    normalize_kernel<<<(2 * N_PAIRS * 32 + 255) / 256, 256>>>(out);
}

// round 14
// speedup vs baseline: 1.6242x; 1.0568x over previous
#include <cuda_runtime.h>
#include <cuda_bf16.h>
#include <math.h>
#include <stdint.h>

#define N_NODES 50000
#define D_FEAT  364
#define D_OUT   150
#define N_PAIRS 8192
#define N_EDGES 200000
#define NEG_SLOPE 0.01f

#define AKP 192
#define WB_NS 384

#define SCAN_B 256
#define SCAN_NB ((N_NODES + SCAN_B - 1) / SCAN_B)   // 196

// Scratch (no cudaMalloc allowed).
__device__ __align__(16) float g_h1 [(size_t)N_NODES * D_FEAT];
__device__ __align__(16) float g_z  [(size_t)2 * N_PAIRS * D_OUT];
__device__ __align__(16) uint32_t g_agg_h[(size_t)N_NODES * AKP];
__device__ __align__(16) uint32_t g_agg_l[(size_t)N_NODES * AKP];
__device__ __align__(16) uint32_t g_wb_h [(size_t)AKP * WB_NS];
__device__ __align__(16) uint32_t g_wb_l [(size_t)AKP * WB_NS];
// bf16-split compact h2 (written by gemm2 epilogue, read by pairs GEMM)
__device__ __align__(16) uint32_t g_p_h [(size_t)2 * N_PAIRS * AKP];
__device__ __align__(16) uint32_t g_p_l [(size_t)2 * N_PAIRS * AKP];

// CSR-by-dst scratch
__device__ int g_deg [N_NODES];
__device__ int g_off [N_NODES];
__device__ int g_pos [N_NODES];
__device__ int g_srcs[N_EDGES];

// pair-node compaction
__device__ int g_mark  [N_NODES];
__device__ int g_newidx[N_NODES];
__device__ int g_list  [2 * N_PAIRS];
__device__ int g_count;

// scan block sums
__device__ int g_bs_deg [SCAN_NB];
__device__ int g_bs_mark[SCAN_NB];

// ---------------------------------------------------------------------------
__device__ __forceinline__ void split1(float v, __nv_bfloat16& h, __nv_bfloat16& l) {
    h = __float2bfloat16_rn(v);
    l = __float2bfloat16_rn(v - __bfloat162float(h));
}
__device__ __forceinline__ uint32_t pack2(__nv_bfloat16 lo, __nv_bfloat16 hi) {
    __nv_bfloat162 p;
    p.x = lo; p.y = hi;
    return *reinterpret_cast<uint32_t*>(&p);
}

// ---------------------------------------------------------------------------
// CSR build + compaction, 3-phase grid scan
__global__ void csr_zero_kernel() {
    int i = blockIdx.x * blockDim.x + threadIdx.x;
    if (i < N_NODES) { g_deg[i] = 0; g_mark[i] = 0; }
}
__global__ void csr_count_kernel(const int* __restrict__ dst) {
    int e = blockIdx.x * blockDim.x + threadIdx.x;
    if (e < N_EDGES) atomicAdd(&g_deg[dst[e]], 1);
}
__global__ void mark_set_kernel(const int* __restrict__ v1,
                                const int* __restrict__ v2) {
    int i = blockIdx.x * blockDim.x + threadIdx.x;
    if (i < N_PAIRS) { g_mark[v1[i]] = 1; g_mark[v2[i]] = 1; }
}

__global__ void scan_partial_kernel() {
    __shared__ int wsum_d[8], wsum_m[8];
    int tid = threadIdx.x, lane = tid & 31, w = tid >> 5;
    int i = blockIdx.x * SCAN_B + tid;
    int vd = (i < N_NODES) ? g_deg[i] : 0;
    int vm = (i < N_NODES) ? g_mark[i] : 0;
    #pragma unroll
    for (int o = 16; o; o >>= 1) {
        vd += __shfl_xor_sync(0xFFFFFFFFu, vd, o);
        vm += __shfl_xor_sync(0xFFFFFFFFu, vm, o);
    }
    if (lane == 0) { wsum_d[w] = vd; wsum_m[w] = vm; }
    __syncthreads();
    if (tid == 0) {
        int sd = 0, sm = 0;
        #pragma unroll
        for (int j = 0; j < 8; j++) { sd += wsum_d[j]; sm += wsum_m[j]; }
        g_bs_deg[blockIdx.x] = sd;
        g_bs_mark[blockIdx.x] = sm;
    }
}

__global__ void scan_blocksums_kernel() {
    __shared__ int wt_d[8], wt_m[8];
    int tid = threadIdx.x, lane = tid & 31, w = tid >> 5;
    int vd = (tid < SCAN_NB) ? g_bs_deg[tid] : 0;
    int vm = (tid < SCAN_NB) ? g_bs_mark[tid] : 0;
    int sd = vd, sm = vm;
    #pragma unroll
    for (int o = 1; o < 32; o <<= 1) {
        int td = __shfl_up_sync(0xFFFFFFFFu, sd, o);
        int tm = __shfl_up_sync(0xFFFFFFFFu, sm, o);
        if (lane >= o) { sd += td; sm += tm; }
    }
    if (lane == 31) { wt_d[w] = sd; wt_m[w] = sm; }
    __syncthreads();
    if (w == 0) {
        int td = (lane < 8) ? wt_d[lane] : 0;
        int tm = (lane < 8) ? wt_m[lane] : 0;
        int sd2 = td, sm2 = tm;
        #pragma unroll
        for (int o = 1; o < 8; o <<= 1) {
            int ud = __shfl_up_sync(0xFFFFFFFFu, sd2, o);
            int um = __shfl_up_sync(0xFFFFFFFFu, sm2, o);
            if (lane >= o) { sd2 += ud; sm2 += um; }
        }
        if (lane < 8) { wt_d[lane] = sd2 - td; wt_m[lane] = sm2 - tm; }
    }
    __syncthreads();
    if (tid < SCAN_NB) {
        g_bs_deg[tid]  = sd - vd + wt_d[w];
        g_bs_mark[tid] = sm - vm + wt_m[w];
    }
    if (tid == SCAN_NB - 1) g_count = sm + wt_m[w];
}

__global__ void scan_final_kernel() {
    __shared__ int wt_d[8], wt_m[8];
    int tid = threadIdx.x, lane = tid & 31, w = tid >> 5;
    int i = blockIdx.x * SCAN_B + tid;
    int vd = (i < N_NODES) ? g_deg[i] : 0;
    int vm = (i < N_NODES) ? g_mark[i] : 0;
    int sd = vd, sm = vm;
    #pragma unroll
    for (int o = 1; o < 32; o <<= 1) {
        int td = __shfl_up_sync(0xFFFFFFFFu, sd, o);
        int tm = __shfl_up_sync(0xFFFFFFFFu, sm, o);
        if (lane >= o) { sd += td; sm += tm; }
    }
    if (lane == 31) { wt_d[w] = sd; wt_m[w] = sm; }
    __syncthreads();
    if (w == 0) {
        int td = (lane < 8) ? wt_d[lane] : 0;
        int tm = (lane < 8) ? wt_m[lane] : 0;
        int sd2 = td, sm2 = tm;
        #pragma unroll
        for (int o = 1; o < 8; o <<= 1) {
            int ud = __shfl_up_sync(0xFFFFFFFFu, sd2, o);
            int um = __shfl_up_sync(0xFFFFFFFFu, sm2, o);
            if (lane >= o) { sd2 += ud; sm2 += um; }
        }
        if (lane < 8) { wt_d[lane] = sd2 - td; wt_m[lane] = sm2 - tm; }
    }
    __syncthreads();
    if (i < N_NODES) {
        int off_d = g_bs_deg[blockIdx.x]  + sd - vd + wt_d[w];
        int off_m = g_bs_mark[blockIdx.x] + sm - vm + wt_m[w];
        g_off[i] = off_d;
        g_pos[i] = off_d;
        g_newidx[i] = off_m;
        if (vm) g_list[off_m] = i;
    }
}

__global__ void csr_fill_kernel(const int* __restrict__ src,
                                const int* __restrict__ dst) {
    int e = blockIdx.x * blockDim.x + threadIdx.x;
    if (e >= N_EDGES) return;
    int idx = atomicAdd(&g_pos[dst[e]], 1);
    g_srcs[idx] = src[e];
}

// ---------------------------------------------------------------------------
// gather core: agg(outrow) = x[node] + sum_in x[src], bf16-split output.
__device__ __forceinline__ void gather_one(const float* __restrict__ x,
                                           int node, int outrow,
                                           int half, int lane) {
    int off = g_off[node];
    int deg = g_deg[node];

    int base4 = half * 46;
    int cnt   = half ? 45 : 46;
    int i0 = base4 + lane;
    int i1 = base4 + 32 + lane;
    bool p1 = (32 + lane) < cnt;

    const float4* xd = reinterpret_cast<const float4*>(x + (size_t)node * D_FEAT);
    float4 a0 = xd[i0];
    float4 a1 = p1 ? xd[i1] : make_float4(0.f, 0.f, 0.f, 0.f);

    for (int e = 0; e < deg; e++) {
        int s = g_srcs[off + e];
        const float4* xs = reinterpret_cast<const float4*>(x + (size_t)s * D_FEAT);
        float4 v0 = xs[i0];
        a0.x += v0.x; a0.y += v0.y; a0.z += v0.z; a0.w += v0.w;
        if (p1) {
            float4 v1 = xs[i1];
            a1.x += v1.x; a1.y += v1.y; a1.z += v1.z; a1.w += v1.w;
        }
    }

    uint32_t* oh = g_agg_h + (size_t)outrow * AKP;
    uint32_t* ol = g_agg_l + (size_t)outrow * AKP;
    {
        __nv_bfloat16 hx, lx, hy, ly, hz, lz, hw, lw;
        split1(a0.x, hx, lx); split1(a0.y, hy, ly);
        split1(a0.z, hz, lz); split1(a0.w, hw, lw);
        *reinterpret_cast<uint2*>(oh + 2 * i0) = make_uint2(pack2(hx, hy), pack2(hz, hw));
        *reinterpret_cast<uint2*>(ol + 2 * i0) = make_uint2(pack2(lx, ly), pack2(lz, lw));
    }
    if (p1) {
        __nv_bfloat16 hx, lx, hy, ly, hz, lz, hw, lw;
        split1(a1.x, hx, lx); split1(a1.y, hy, ly);
        split1(a1.z, hz, lz); split1(a1.w, hw, lw);
        *reinterpret_cast<uint2*>(oh + 2 * i1) = make_uint2(pack2(hx, hy), pack2(hz, hw));
        *reinterpret_cast<uint2*>(ol + 2 * i1) = make_uint2(pack2(lx, ly), pack2(lz, lw));
    }
    if (half && lane >= 13 && lane <= 17) {   // zero-pad k4 91..95
        *reinterpret_cast<uint2*>(oh + 2 * i1) = make_uint2(0u, 0u);
        *reinterpret_cast<uint2*>(ol + 2 * i1) = make_uint2(0u, 0u);
    }
}

__global__ void gather_kernel(const float* __restrict__ x_ext) {
    int gw = (blockIdx.x * blockDim.x + threadIdx.x) >> 5;
    int lane = threadIdx.x & 31;
    int node = gw >> 1;
    int half = gw & 1;
    if (node >= N_NODES) return;
    gather_one(x_ext, node, node, half, lane);
}
__global__ void gather2_kernel() {
    int gw = (blockIdx.x * blockDim.x + threadIdx.x) >> 5;
    int lane = threadIdx.x & 31;
    int i = gw >> 1;
    int half = gw & 1;
    if (i >= g_count) return;
    gather_one(g_h1, g_list[i], i, half, lane);
}

// ---------------------------------------------------------------------------
// convert W [K x N] fp32 -> g_wb_h/l  ([kp][n] packed bf16x2, zero padded)
__global__ void convert_w_kernel(const float* __restrict__ W, int Ncols) {
    int idx = blockIdx.x * blockDim.x + threadIdx.x;
    int kp = idx / (WB_NS / 4);
    int nq = idx % (WB_NS / 4);
    if (kp >= AKP) return;
    int n0 = nq * 4;
    uint32_t oh[4], ol[4];
    #pragma unroll
    for (int j = 0; j < 4; j++) {
        int n = n0 + j;
        float v0 = 0.f, v1 = 0.f;
        if (2 * kp < D_FEAT && n < Ncols) {
            v0 = W[(size_t)(2 * kp) * Ncols + n];
            v1 = W[(size_t)(2 * kp + 1) * Ncols + n];
        }
        __nv_bfloat16 h0, l0, h1, l1;
        split1(v0, h0, l0);
        split1(v1, h1, l1);
        oh[j] = pack2(h0, h1);
        ol[j] = pack2(l0, l1);
    }
    size_t o = (size_t)kp * WB_NS + n0;
    *reinterpret_cast<uint4*>(g_wb_h + o) = make_uint4(oh[0], oh[1], oh[2], oh[3]);
    *reinterpret_cast<uint4*>(g_wb_l + o) = make_uint4(ol[0], ol[1], ol[2], ol[3]);
}

// ---------------------------------------------------------------------------
__device__ __forceinline__ void mma16(float d[4], const uint32_t a[4], const uint32_t b[2]) {
    asm volatile(
        "mma.sync.aligned.m16n8k16.row.col.f32.bf16.bf16.f32 "
        "{%0,%1,%2,%3}, {%4,%5,%6,%7}, {%8,%9}, {%0,%1,%2,%3};\n"
        : "+f"(d[0]), "+f"(d[1]), "+f"(d[2]), "+f"(d[3])
        : "r"(a[0]), "r"(a[1]), "r"(a[2]), "r"(a[3]), "r"(b[0]), "r"(b[1]));
}
__device__ __forceinline__ void cp_async16(uint32_t smem_addr, const void* gptr, int src_bytes) {
    asm volatile("cp.async.cg.shared.global [%0], [%1], 16, %2;"
                 :: "r"(smem_addr), "l"(gptr), "r"(src_bytes) : "memory");
}
__device__ __forceinline__ void cp_async_commit() {
    asm volatile("cp.async.commit_group;" ::: "memory");
}
__device__ __forceinline__ void cp_async_wait0() {
    asm volatile("cp.async.wait_group 0;" ::: "memory");
}

// ---------------------------------------------------------------------------
// node GEMM: bf16x3, cp.async double buffer, 2 CTAs/SM.
// m_mode 0: M=N_NODES, out fp32 g_h1. m_mode 1: M=g_count, out bf16-split g_p_h/l.
#define TC_BM 128
#define TC_BN 128
#define AS2 36
#define BS2 136
#define A_U32 (TC_BM * AS2)
#define B_U32 (16 * BS2)
#define STAGE_U32 (2 * A_U32 + 2 * B_U32)   // 13568
#define NUM_KT 12

__global__ __launch_bounds__(256, 2) void gemm_nodes_tc(
        const float* __restrict__ bias, int m_mode) {
    const int N = D_FEAT;
    int M = m_mode ? g_count : N_NODES;

    int bm = blockIdx.y * TC_BM;
    if (bm >= M) return;
    int bn = blockIdx.x * TC_BN;

    extern __shared__ uint32_t smu[];
    uint32_t smem_base = (uint32_t)__cvta_generic_to_shared(smu);

    int tid = threadIdx.x;
    int lane = tid & 31;
    int wid = tid >> 5;
    int wm = (wid & 1) * 64;
    int wn = (wid >> 1) * 32;
    int r = lane >> 2;
    int c = lane & 3;

    float acc[4][4][4];
    #pragma unroll
    for (int i = 0; i < 4; i++)
        #pragma unroll
        for (int j = 0; j < 4; j++)
            #pragma unroll
            for (int q = 0; q < 4; q++) acc[i][j][q] = 0.f;

    int a_row = tid >> 2;
    int a_q4  = tid & 3;
    int b_kp = tid >> 5;
    int b_n4 = tid & 31;

    auto copy_tile = [&](int t, int stage) {
        int kp0 = t * 16;
        uint32_t sbase = smem_base + (uint32_t)(stage * STAGE_U32 * 4);
        uint32_t As_h = sbase;
        uint32_t As_l = sbase + (uint32_t)(A_U32 * 4);
        uint32_t Bs_h = sbase + (uint32_t)(2 * A_U32 * 4);
        uint32_t Bs_l = Bs_h + (uint32_t)(B_U32 * 4);
        #pragma unroll
        for (int p = 0; p < 2; p++) {
            int m = p * 64 + a_row;
            int gm = bm + m;
            int ok = (gm < M) ? 16 : 0;
            size_t go = (size_t)gm * AKP + kp0 + a_q4 * 4;
            uint32_t so = (uint32_t)((m * AS2 + a_q4 * 4) * 4);
            cp_async16(As_h + so, g_agg_h + go, ok);
            cp_async16(As_l + so, g_agg_l + go, ok);
        }
        #pragma unroll
        for (int p = 0; p < 2; p++) {
            int kp = p * 8 + b_kp;
            size_t go = (size_t)(kp0 + kp) * WB_NS + bn + b_n4 * 4;
            uint32_t so = (uint32_t)((kp * BS2 + b_n4 * 4) * 4);
            cp_async16(Bs_h + so, g_wb_h + go, 16);
            cp_async16(Bs_l + so, g_wb_l + go, 16);
        }
        cp_async_commit();
    };

    copy_tile(0, 0);
    cp_async_wait0();
    __syncthreads();

    for (int t = 0; t < NUM_KT; t++) {
        if (t + 1 < NUM_KT) copy_tile(t + 1, (t + 1) & 1);

        {
            const uint32_t* base = smu + (t & 1) * STAGE_U32;
            const uint32_t* As_h = base;
            const uint32_t* As_l = base + A_U32;
            const uint32_t* Bs_h = base + 2 * A_U32;
            const uint32_t* Bs_l = Bs_h + B_U32;

            #pragma unroll
            for (int kk = 0; kk < 2; kk++) {
                uint32_t ah[4][4], al[4][4], bh[4][2], bl[4][2];
                #pragma unroll
                for (int mt = 0; mt < 4; mt++) {
                    int row = wm + mt * 16 + r;
                    const uint32_t* ph = As_h + row * AS2 + kk * 8 + c;
                    const uint32_t* pl = As_l + row * AS2 + kk * 8 + c;
                    ah[mt][0] = ph[0];
                    ah[mt][1] = ph[8 * AS2];
                    ah[mt][2] = ph[4];
                    ah[mt][3] = ph[8 * AS2 + 4];
                    al[mt][0] = pl[0];
                    al[mt][1] = pl[8 * AS2];
                    al[mt][2] = pl[4];
                    al[mt][3] = pl[8 * AS2 + 4];
                }
                #pragma unroll
                for (int nt = 0; nt < 4; nt++) {
                    int col = wn + nt * 8 + r;
                    const uint32_t* qh = Bs_h + (kk * 8 + c) * BS2 + col;
                    const uint32_t* ql = Bs_l + (kk * 8 + c) * BS2 + col;
                    bh[nt][0] = qh[0];
                    bh[nt][1] = qh[4 * BS2];
                    bl[nt][0] = ql[0];
                    bl[nt][1] = ql[4 * BS2];
                }
                #pragma unroll
                for (int mt = 0; mt < 4; mt++)
                    #pragma unroll
                    for (int nt = 0; nt < 4; nt++) {
                        mma16(acc[mt][nt], ah[mt], bh[nt]);
                        mma16(acc[mt][nt], al[mt], bh[nt]);
                        mma16(acc[mt][nt], ah[mt], bl[nt]);
                    }
            }
        }

        if (t + 1 < NUM_KT) cp_async_wait0();
        __syncthreads();
    }

    #pragma unroll
    for (int mt = 0; mt < 4; mt++) {
        int gm0 = bm + wm + mt * 16 + r;
        #pragma unroll
        for (int nt = 0; nt < 4; nt++) {
            int gn = bn + wn + nt * 8 + 2 * c;
            if (m_mode == 0) {
                if (gn >= N) continue;
                float b0 = bias[gn], b1 = bias[gn + 1];
                float v0 = acc[mt][nt][0] + b0;
                float v1 = acc[mt][nt][1] + b1;
                float v2 = acc[mt][nt][2] + b0;
                float v3 = acc[mt][nt][3] + b1;
                v0 = v0 > 0.f ? v0 : NEG_SLOPE * v0;
                v1 = v1 > 0.f ? v1 : NEG_SLOPE * v1;
                v2 = v2 > 0.f ? v2 : NEG_SLOPE * v2;
                v3 = v3 > 0.f ? v3 : NEG_SLOPE * v3;
                if (gm0 < M)
                    *reinterpret_cast<float2*>(g_h1 + (size_t)gm0 * N + gn) = make_float2(v0, v1);
                if (gm0 + 8 < M)
                    *reinterpret_cast<float2*>(g_h1 + (size_t)(gm0 + 8) * N + gn) = make_float2(v2, v3);
            } else {
                // bf16-split packed output (kp = gn/2). gn in [364,384): acc==0
                // (B n-pad is zero) -> emit zero pad for pairs GEMM's k-padding.
                bool valid = gn < N;
                float b0 = valid ? bias[gn] : 0.f;
                float b1 = valid ? bias[gn + 1] : 0.f;
                float v0 = valid ? acc[mt][nt][0] + b0 : 0.f;
                float v1 = valid ? acc[mt][nt][1] + b1 : 0.f;
                float v2 = valid ? acc[mt][nt][2] + b0 : 0.f;
                float v3 = valid ? acc[mt][nt][3] + b1 : 0.f;
                v0 = v0 > 0.f ? v0 : NEG_SLOPE * v0;
                v1 = v1 > 0.f ? v1 : NEG_SLOPE * v1;
                v2 = v2 > 0.f ? v2 : NEG_SLOPE * v2;
                v3 = v3 > 0.f ? v3 : NEG_SLOPE * v3;
                int kp = gn >> 1;
                if (gm0 < M) {
                    __nv_bfloat16 h0, l0, h1, l1;
                    split1(v0, h0, l0);
                    split1(v1, h1, l1);
                    g_p_h[(size_t)gm0 * AKP + kp] = pack2(h0, h1);
                    g_p_l[(size_t)gm0 * AKP + kp] = pack2(l0, l1);
                }
                if (gm0 + 8 < M) {
                    __nv_bfloat16 h2, l2, h3, l3;
                    split1(v2, h2, l2);
                    split1(v3, h3, l3);
                    g_p_h[(size_t)(gm0 + 8) * AKP + kp] = pack2(h2, h3);
                    g_p_l[(size_t)(gm0 + 8) * AKP + kp] = pack2(l2, l3);
                }
            }
        }
    }
}

// ---------------------------------------------------------------------------
// pairs GEMM: bf16x3, g_z = lrelu(p[rows] @ W3 + b3). Same structure as nodes.
__global__ __launch_bounds__(256, 2) void gemm_pairs_bf16(
        const int* __restrict__ v1, const int* __restrict__ v2,
        const float* __restrict__ bias) {
    const int N = D_OUT;   // 150
    const int M = 2 * N_PAIRS;

    int bm = blockIdx.y * TC_BM;
    int bn = blockIdx.x * TC_BN;

    extern __shared__ uint32_t smu[];
    uint32_t smem_base = (uint32_t)__cvta_generic_to_shared(smu);
    __shared__ int rows_sh[TC_BM];

    int tid = threadIdx.x;
    int lane = tid & 31;
    int wid = tid >> 5;
    int wm = (wid & 1) * 64;
    int wn = (wid >> 1) * 32;
    int r = lane >> 2;
    int c = lane & 3;

    if (tid < TC_BM) {
        int gm = bm + tid;    // M divisible by 128
        int v = (gm < N_PAIRS) ? v1[gm] : v2[gm - N_PAIRS];
        rows_sh[tid] = g_newidx[v];
    }
    __syncthreads();

    float acc[4][4][4];
    #pragma unroll
    for (int i = 0; i < 4; i++)
        #pragma unroll
        for (int j = 0; j < 4; j++)
            #pragma unroll
            for (int q = 0; q < 4; q++) acc[i][j][q] = 0.f;

    int a_row = tid >> 2;
    int a_q4  = tid & 3;
    int b_kp = tid >> 5;
    int b_n4 = tid & 31;

    auto copy_tile = [&](int t, int stage) {
        int kp0 = t * 16;
        uint32_t sbase = smem_base + (uint32_t)(stage * STAGE_U32 * 4);
        uint32_t As_h = sbase;
        uint32_t As_l = sbase + (uint32_t)(A_U32 * 4);
        uint32_t Bs_h = sbase + (uint32_t)(2 * A_U32 * 4);
        uint32_t Bs_l = Bs_h + (uint32_t)(B_U32 * 4);
        #pragma unroll
        for (int p = 0; p < 2; p++) {
            int m = p * 64 + a_row;
            int row = rows_sh[m];
            size_t go = (size_t)row * AKP + kp0 + a_q4 * 4;
            uint32_t so = (uint32_t)((m * AS2 + a_q4 * 4) * 4);
            cp_async16(As_h + so, g_p_h + go, 16);
            cp_async16(As_l + so, g_p_l + go, 16);
        }
        #pragma unroll
        for (int p = 0; p < 2; p++) {
            int kp = p * 8 + b_kp;
            size_t go = (size_t)(kp0 + kp) * WB_NS + bn + b_n4 * 4;
            uint32_t so = (uint32_t)((kp * BS2 + b_n4 * 4) * 4);
            cp_async16(Bs_h + so, g_wb_h + go, 16);
            cp_async16(Bs_l + so, g_wb_l + go, 16);
        }
        cp_async_commit();
    };

    copy_tile(0, 0);
    cp_async_wait0();
    __syncthreads();

    for (int t = 0; t < NUM_KT; t++) {
        if (t + 1 < NUM_KT) copy_tile(t + 1, (t + 1) & 1);

        {
            const uint32_t* base = smu + (t & 1) * STAGE_U32;
            const uint32_t* As_h = base;
            const uint32_t* As_l = base + A_U32;
            const uint32_t* Bs_h = base + 2 * A_U32;
            const uint32_t* Bs_l = Bs_h + B_U32;

            #pragma unroll
            for (int kk = 0; kk < 2; kk++) {
                uint32_t ah[4][4], al[4][4], bh[4][2], bl[4][2];
                #pragma unroll
                for (int mt = 0; mt < 4; mt++) {
                    int row = wm + mt * 16 + r;
                    const uint32_t* ph = As_h + row * AS2 + kk * 8 + c;
                    const uint32_t* pl = As_l + row * AS2 + kk * 8 + c;
                    ah[mt][0] = ph[0];
                    ah[mt][1] = ph[8 * AS2];
                    ah[mt][2] = ph[4];
                    ah[mt][3] = ph[8 * AS2 + 4];
                    al[mt][0] = pl[0];
                    al[mt][1] = pl[8 * AS2];
                    al[mt][2] = pl[4];
                    al[mt][3] = pl[8 * AS2 + 4];
                }
                #pragma unroll
                for (int nt = 0; nt < 4; nt++) {
                    int col = wn + nt * 8 + r;
                    const uint32_t* qh = Bs_h + (kk * 8 + c) * BS2 + col;
                    const uint32_t* ql = Bs_l + (kk * 8 + c) * BS2 + col;
                    bh[nt][0] = qh[0];
                    bh[nt][1] = qh[4 * BS2];
                    bl[nt][0] = ql[0];
                    bl[nt][1] = ql[4 * BS2];
                }
                #pragma unroll
                for (int mt = 0; mt < 4; mt++)
                    #pragma unroll
                    for (int nt = 0; nt < 4; nt++) {
                        mma16(acc[mt][nt], ah[mt], bh[nt]);
                        mma16(acc[mt][nt], al[mt], bh[nt]);
                        mma16(acc[mt][nt], ah[mt], bl[nt]);
                    }
            }
        }

        if (t + 1 < NUM_KT) cp_async_wait0();
        __syncthreads();
    }

    #pragma unroll
    for (int mt = 0; mt < 4; mt++) {
        int gm0 = bm + wm + mt * 16 + r;
        #pragma unroll
        for (int nt = 0; nt < 4; nt++) {
            int gn = bn + wn + nt * 8 + 2 * c;
            if (gn + 1 >= N) continue;
            float b0 = bias[gn], b1 = bias[gn + 1];
            float v0 = acc[mt][nt][0] + b0;
            float v1 = acc[mt][nt][1] + b1;
            float v2 = acc[mt][nt][2] + b0;
            float v3 = acc[mt][nt][3] + b1;
            v0 = v0 > 0.f ? v0 : NEG_SLOPE * v0;
            v1 = v1 > 0.f ? v1 : NEG_SLOPE * v1;
            v2 = v2 > 0.f ? v2 : NEG_SLOPE * v2;
            v3 = v3 > 0.f ? v3 : NEG_SLOPE * v3;
            *reinterpret_cast<float2*>(g_z + (size_t)gm0 * N + gn) = make_float2(v0, v1);
            *reinterpret_cast<float2*>(g_z + (size_t)(gm0 + 8) * N + gn) = make_float2(v2, v3);
        }
    }
    (void)M;
}

// ---------------------------------------------------------------------------
__global__ void normalize_kernel(float* __restrict__ out) {
    int row  = (blockIdx.x * blockDim.x + threadIdx.x) >> 5;
    int lane = threadIdx.x & 31;
    if (row >= 2 * N_PAIRS) return;
    const float* zr = g_z + (size_t)row * D_OUT;
    float ss = 0.f;
    for (int i = lane; i < D_OUT; i += 32) { float v = zr[i]; ss += v * v; }
    #pragma unroll
    for (int o = 16; o; o >>= 1) ss += __shfl_xor_sync(0xFFFFFFFFu, ss, o);
    float norm = sqrtf(ss);
    float inv = 1.f / fmaxf(norm, 1e-12f);
    for (int i = lane; i < D_OUT; i += 32) out[(size_t)row * D_OUT + i] = zr[i] * inv;
}

// ---------------------------------------------------------------------------
extern "C" void kernel_launch(void* const* d_in, const int* in_sizes, int n_in,
                              void* d_out, int out_size) {
    const float* features = (const float*)d_in[0];
    const int*   src      = (const int*)  d_in[1];
    const int*   dst      = (const int*)  d_in[2];
    const int*   v1       = (const int*)  d_in[3];
    const int*   v2       = (const int*)  d_in[4];
    const float* W1       = (const float*)d_in[5];
    const float* b1       = (const float*)d_in[6];
    const float* W2       = (const float*)d_in[7];
    const float* b2       = (const float*)d_in[8];
    const float* W3       = (const float*)d_in[9];
    const float* b3       = (const float*)d_in[10];
    float* out = (float*)d_out;
    (void)in_sizes; (void)n_in; (void)out_size;

    size_t tc_smem = (size_t)2 * STAGE_U32 * sizeof(uint32_t);      // 108544 B
    cudaFuncSetAttribute(gemm_nodes_tc, cudaFuncAttributeMaxDynamicSharedMemorySize,
                         (int)tc_smem);
    cudaFuncSetAttribute(gemm_pairs_bf16, cudaFuncAttributeMaxDynamicSharedMemorySize,
                         (int)tc_smem);

    dim3 tc_grid1((D_FEAT + TC_BN - 1) / TC_BN, (N_NODES + TC_BM - 1) / TC_BM);
    dim3 tc_grid2((D_FEAT + TC_BN - 1) / TC_BN, (2 * N_PAIRS) / TC_BM);
    dim3 pairs_grid((D_OUT + TC_BN - 1) / TC_BN, (2 * N_PAIRS) / TC_BM);
    int gather1_blocks = (N_NODES * 64 + 255) / 256;
    int gather2_blocks = (2 * N_PAIRS * 64 + 255) / 256;
    int convw_blocks = (AKP * (WB_NS / 4) + 255) / 256;

    // CSR by dst + pair-node compaction (3-phase grid scan)
    csr_zero_kernel<<<(N_NODES + 255) / 256, 256>>>();
    csr_count_kernel<<<(N_EDGES + 255) / 256, 256>>>(dst);
    mark_set_kernel<<<(N_PAIRS + 255) / 256, 256>>>(v1, v2);
    scan_partial_kernel<<<SCAN_NB, SCAN_B>>>();
    scan_blocksums_kernel<<<1, 256>>>();
    scan_final_kernel<<<SCAN_NB, SCAN_B>>>();
    csr_fill_kernel<<<(N_EDGES + 255) / 256, 256>>>(src, dst);

    // layer 1 (all nodes) -> fp32 h1
    convert_w_kernel<<<convw_blocks, 256>>>(W1, D_FEAT);
    gather_kernel<<<gather1_blocks, 256>>>(features);
    gemm_nodes_tc<<<tc_grid1, 256, tc_smem>>>(b1, /*m_mode=*/0);

    // layer 2 (compact pair nodes) -> bf16-split h2 (g_p_h/l)
    convert_w_kernel<<<convw_blocks, 256>>>(W2, D_FEAT);
    gather2_kernel<<<gather2_blocks, 256>>>();
    gemm_nodes_tc<<<tc_grid2, 256, tc_smem>>>(b2, /*m_mode=*/1);

    // pair projection (bf16) + normalize
    convert_w_kernel<<<convw_blocks, 256>>>(W3, D_OUT);
    gemm_pairs_bf16<<<pairs_grid, 256, tc_smem>>>(v1, v2, b3);
    normalize_kernel<<<(2 * N_PAIRS * 32 + 255) / 256, 256>>>(out);
}

// round 15
// speedup vs baseline: 1.7726x; 1.0914x over previous
#include <cuda_runtime.h>
#include <cuda_bf16.h>
#include <math.h>
#include <stdint.h>

#define N_NODES 50000
#define D_FEAT  364
#define D_OUT   150
#define N_PAIRS 8192
#define N_EDGES 200000
#define NEG_SLOPE 0.01f

#define AKP 192
#define WB_NS 384

#define SCAN_B 256
#define SCAN_NB ((N_NODES + SCAN_B - 1) / SCAN_B)   // 196

// Scratch (no cudaMalloc allowed).
__device__ __align__(16) float g_h1 [(size_t)N_NODES * D_FEAT];   // compact (needed set)
__device__ __align__(16) float g_z  [(size_t)2 * N_PAIRS * D_OUT];
__device__ __align__(16) uint32_t g_agg_h[(size_t)N_NODES * AKP];
__device__ __align__(16) uint32_t g_agg_l[(size_t)N_NODES * AKP];
__device__ __align__(16) uint32_t g_wb_h [(size_t)AKP * WB_NS];
__device__ __align__(16) uint32_t g_wb_l [(size_t)AKP * WB_NS];
// bf16-split compact h2 (written by gemm2 epilogue, read by pairs GEMM)
__device__ __align__(16) uint32_t g_p_h [(size_t)2 * N_PAIRS * AKP];
__device__ __align__(16) uint32_t g_p_l [(size_t)2 * N_PAIRS * AKP];

// CSR-by-dst scratch
__device__ int g_deg [N_NODES];
__device__ int g_off [N_NODES];
__device__ int g_pos [N_NODES];
__device__ int g_srcs[N_EDGES];

// pair-node compaction (mark) + needed-set compaction (need)
__device__ int g_mark  [N_NODES];
__device__ int g_newidx[N_NODES];
__device__ int g_list  [2 * N_PAIRS];
__device__ int g_count;
__device__ int g_need [N_NODES];
__device__ int g_nidx [N_NODES];
__device__ int g_nlist[N_NODES];
__device__ int g_ncount;

// scan block sums
__device__ int g_bs_deg [SCAN_NB];
__device__ int g_bs_mark[SCAN_NB];
__device__ int g_bs_need[SCAN_NB];

// ---------------------------------------------------------------------------
__device__ __forceinline__ void split1(float v, __nv_bfloat16& h, __nv_bfloat16& l) {
    h = __float2bfloat16_rn(v);
    l = __float2bfloat16_rn(v - __bfloat162float(h));
}
__device__ __forceinline__ uint32_t pack2(__nv_bfloat16 lo, __nv_bfloat16 hi) {
    __nv_bfloat162 p;
    p.x = lo; p.y = hi;
    return *reinterpret_cast<uint32_t*>(&p);
}

// ---------------------------------------------------------------------------
__global__ void csr_zero_kernel() {
    int i = blockIdx.x * blockDim.x + threadIdx.x;
    if (i < N_NODES) { g_deg[i] = 0; g_mark[i] = 0; g_need[i] = 0; }
}
// count in-degree + mark pair nodes (mark also seeds need)
__global__ void csr_count_mark_kernel(const int* __restrict__ dst,
                                      const int* __restrict__ v1,
                                      const int* __restrict__ v2) {
    int e = blockIdx.x * blockDim.x + threadIdx.x;
    if (e < N_EDGES) atomicAdd(&g_deg[dst[e]], 1);
    if (e < N_PAIRS) {
        int a = v1[e], b = v2[e];
        g_mark[a] = 1; g_mark[b] = 1;
        g_need[a] = 1; g_need[b] = 1;
    }
}
// need[src] |= mark[dst] (after marks complete)
__global__ void need_edge_kernel(const int* __restrict__ src,
                                 const int* __restrict__ dst) {
    int e = blockIdx.x * blockDim.x + threadIdx.x;
    if (e >= N_EDGES) return;
    if (g_mark[dst[e]]) g_need[src[e]] = 1;
}

// phase 1: per-block sums of deg/mark/need
__global__ void scan_partial_kernel() {
    __shared__ int wsum_d[8], wsum_m[8], wsum_n[8];
    int tid = threadIdx.x, lane = tid & 31, w = tid >> 5;
    int i = blockIdx.x * SCAN_B + tid;
    int vd = (i < N_NODES) ? g_deg[i] : 0;
    int vm = (i < N_NODES) ? g_mark[i] : 0;
    int vn = (i < N_NODES) ? g_need[i] : 0;
    #pragma unroll
    for (int o = 16; o; o >>= 1) {
        vd += __shfl_xor_sync(0xFFFFFFFFu, vd, o);
        vm += __shfl_xor_sync(0xFFFFFFFFu, vm, o);
        vn += __shfl_xor_sync(0xFFFFFFFFu, vn, o);
    }
    if (lane == 0) { wsum_d[w] = vd; wsum_m[w] = vm; wsum_n[w] = vn; }
    __syncthreads();
    if (tid == 0) {
        int sd = 0, sm = 0, sn = 0;
        #pragma unroll
        for (int j = 0; j < 8; j++) { sd += wsum_d[j]; sm += wsum_m[j]; sn += wsum_n[j]; }
        g_bs_deg[blockIdx.x] = sd;
        g_bs_mark[blockIdx.x] = sm;
        g_bs_need[blockIdx.x] = sn;
    }
}

// phase 2: exclusive scan of block sums (single block)
__global__ void scan_blocksums_kernel() {
    __shared__ int wt_d[8], wt_m[8], wt_n[8];
    int tid = threadIdx.x, lane = tid & 31, w = tid >> 5;
    int vd = (tid < SCAN_NB) ? g_bs_deg[tid] : 0;
    int vm = (tid < SCAN_NB) ? g_bs_mark[tid] : 0;
    int vn = (tid < SCAN_NB) ? g_bs_need[tid] : 0;
    int sd = vd, sm = vm, sn = vn;
    #pragma unroll
    for (int o = 1; o < 32; o <<= 1) {
        int td = __shfl_up_sync(0xFFFFFFFFu, sd, o);
        int tm = __shfl_up_sync(0xFFFFFFFFu, sm, o);
        int tn = __shfl_up_sync(0xFFFFFFFFu, sn, o);
        if (lane >= o) { sd += td; sm += tm; sn += tn; }
    }
    if (lane == 31) { wt_d[w] = sd; wt_m[w] = sm; wt_n[w] = sn; }
    __syncthreads();
    if (w == 0) {
        int td = (lane < 8) ? wt_d[lane] : 0;
        int tm = (lane < 8) ? wt_m[lane] : 0;
        int tn = (lane < 8) ? wt_n[lane] : 0;
        int sd2 = td, sm2 = tm, sn2 = tn;
        #pragma unroll
        for (int o = 1; o < 8; o <<= 1) {
            int ud = __shfl_up_sync(0xFFFFFFFFu, sd2, o);
            int um = __shfl_up_sync(0xFFFFFFFFu, sm2, o);
            int un = __shfl_up_sync(0xFFFFFFFFu, sn2, o);
            if (lane >= o) { sd2 += ud; sm2 += um; sn2 += un; }
        }
        if (lane < 8) { wt_d[lane] = sd2 - td; wt_m[lane] = sm2 - tm; wt_n[lane] = sn2 - tn; }
    }
    __syncthreads();
    if (tid < SCAN_NB) {
        g_bs_deg[tid]  = sd - vd + wt_d[w];
        g_bs_mark[tid] = sm - vm + wt_m[w];
        g_bs_need[tid] = sn - vn + wt_n[w];
    }
    if (tid == SCAN_NB - 1) {
        g_count  = sm + wt_m[w];
        g_ncount = sn + wt_n[w];
    }
}

// phase 3: per-block scans + emit outputs
__global__ void scan_final_kernel() {
    __shared__ int wt_d[8], wt_m[8], wt_n[8];
    int tid = threadIdx.x, lane = tid & 31, w = tid >> 5;
    int i = blockIdx.x * SCAN_B + tid;
    int vd = (i < N_NODES) ? g_deg[i] : 0;
    int vm = (i < N_NODES) ? g_mark[i] : 0;
    int vn = (i < N_NODES) ? g_need[i] : 0;
    int sd = vd, sm = vm, sn = vn;
    #pragma unroll
    for (int o = 1; o < 32; o <<= 1) {
        int td = __shfl_up_sync(0xFFFFFFFFu, sd, o);
        int tm = __shfl_up_sync(0xFFFFFFFFu, sm, o);
        int tn = __shfl_up_sync(0xFFFFFFFFu, sn, o);
        if (lane >= o) { sd += td; sm += tm; sn += tn; }
    }
    if (lane == 31) { wt_d[w] = sd; wt_m[w] = sm; wt_n[w] = sn; }
    __syncthreads();
    if (w == 0) {
        int td = (lane < 8) ? wt_d[lane] : 0;
        int tm = (lane < 8) ? wt_m[lane] : 0;
        int tn = (lane < 8) ? wt_n[lane] : 0;
        int sd2 = td, sm2 = tm, sn2 = tn;
        #pragma unroll
        for (int o = 1; o < 8; o <<= 1) {
            int ud = __shfl_up_sync(0xFFFFFFFFu, sd2, o);
            int um = __shfl_up_sync(0xFFFFFFFFu, sm2, o);
            int un = __shfl_up_sync(0xFFFFFFFFu, sn2, o);
            if (lane >= o) { sd2 += ud; sm2 += um; sn2 += un; }
        }
        if (lane < 8) { wt_d[lane] = sd2 - td; wt_m[lane] = sm2 - tm; wt_n[lane] = sn2 - tn; }
    }
    __syncthreads();
    if (i < N_NODES) {
        int off_d = g_bs_deg[blockIdx.x]  + sd - vd + wt_d[w];
        int off_m = g_bs_mark[blockIdx.x] + sm - vm + wt_m[w];
        int off_n = g_bs_need[blockIdx.x] + sn - vn + wt_n[w];
        g_off[i] = off_d;
        g_pos[i] = off_d;
        g_newidx[i] = off_m;
        if (vm) g_list[off_m] = i;
        g_nidx[i] = off_n;
        if (vn) g_nlist[off_n] = i;
    }
}

__global__ void csr_fill_kernel(const int* __restrict__ src,
                                const int* __restrict__ dst) {
    int e = blockIdx.x * blockDim.x + threadIdx.x;
    if (e >= N_EDGES) return;
    int idx = atomicAdd(&g_pos[dst[e]], 1);
    g_srcs[idx] = src[e];
}

// ---------------------------------------------------------------------------
// gather core: agg(outrow) = x[row(node)] + sum_in x[row(src)], bf16-split out.
// remap==0: row(id)=id (x indexed by original node id).
// remap==1: row(id)=g_nidx[id] (x is compact h1).
__device__ __forceinline__ void gather_one(const float* __restrict__ x,
                                           int node, int outrow,
                                           int half, int lane, int remap) {
    int off = g_off[node];
    int deg = g_deg[node];

    int base4 = half * 46;
    int cnt   = half ? 45 : 46;
    int i0 = base4 + lane;
    int i1 = base4 + 32 + lane;
    bool p1 = (32 + lane) < cnt;

    int drow = remap ? g_nidx[node] : node;
    const float4* xd = reinterpret_cast<const float4*>(x + (size_t)drow * D_FEAT);
    float4 a0 = xd[i0];
    float4 a1 = p1 ? xd[i1] : make_float4(0.f, 0.f, 0.f, 0.f);

    for (int e = 0; e < deg; e++) {
        int s = g_srcs[off + e];
        int srow = remap ? g_nidx[s] : s;
        const float4* xs = reinterpret_cast<const float4*>(x + (size_t)srow * D_FEAT);
        float4 v0 = xs[i0];
        a0.x += v0.x; a0.y += v0.y; a0.z += v0.z; a0.w += v0.w;
        if (p1) {
            float4 v1 = xs[i1];
            a1.x += v1.x; a1.y += v1.y; a1.z += v1.z; a1.w += v1.w;
        }
    }

    uint32_t* oh = g_agg_h + (size_t)outrow * AKP;
    uint32_t* ol = g_agg_l + (size_t)outrow * AKP;
    {
        __nv_bfloat16 hx, lx, hy, ly, hz, lz, hw, lw;
        split1(a0.x, hx, lx); split1(a0.y, hy, ly);
        split1(a0.z, hz, lz); split1(a0.w, hw, lw);
        *reinterpret_cast<uint2*>(oh + 2 * i0) = make_uint2(pack2(hx, hy), pack2(hz, hw));
        *reinterpret_cast<uint2*>(ol + 2 * i0) = make_uint2(pack2(lx, ly), pack2(lz, lw));
    }
    if (p1) {
        __nv_bfloat16 hx, lx, hy, ly, hz, lz, hw, lw;
        split1(a1.x, hx, lx); split1(a1.y, hy, ly);
        split1(a1.z, hz, lz); split1(a1.w, hw, lw);
        *reinterpret_cast<uint2*>(oh + 2 * i1) = make_uint2(pack2(hx, hy), pack2(hz, hw));
        *reinterpret_cast<uint2*>(ol + 2 * i1) = make_uint2(pack2(lx, ly), pack2(lz, lw));
    }
    if (half && lane >= 13 && lane <= 17) {   // zero-pad k4 91..95
        *reinterpret_cast<uint2*>(oh + 2 * i1) = make_uint2(0u, 0u);
        *reinterpret_cast<uint2*>(ol + 2 * i1) = make_uint2(0u, 0u);
    }
}

// layer 1: needed nodes only; x = features (original ids); outrow compact
__global__ void gather_kernel(const float* __restrict__ x_ext) {
    int gw = (blockIdx.x * blockDim.x + threadIdx.x) >> 5;
    int lane = threadIdx.x & 31;
    int i = gw >> 1;
    int half = gw & 1;
    if (i >= g_ncount) return;
    gather_one(x_ext, g_nlist[i], i, half, lane, /*remap=*/0);
}
// layer 2: pair nodes; x = compact h1 (remap via g_nidx); outrow pair-compact
__global__ void gather2_kernel() {
    int gw = (blockIdx.x * blockDim.x + threadIdx.x) >> 5;
    int lane = threadIdx.x & 31;
    int i = gw >> 1;
    int half = gw & 1;
    if (i >= g_count) return;
    gather_one(g_h1, g_list[i], i, half, lane, /*remap=*/1);
}

// ---------------------------------------------------------------------------
// convert W [K x N] fp32 -> g_wb_h/l
__global__ void convert_w_kernel(const float* __restrict__ W, int Ncols) {
    int idx = blockIdx.x * blockDim.x + threadIdx.x;
    int kp = idx / (WB_NS / 4);
    int nq = idx % (WB_NS / 4);
    if (kp >= AKP) return;
    int n0 = nq * 4;
    uint32_t oh[4], ol[4];
    #pragma unroll
    for (int j = 0; j < 4; j++) {
        int n = n0 + j;
        float v0 = 0.f, v1 = 0.f;
        if (2 * kp < D_FEAT && n < Ncols) {
            v0 = W[(size_t)(2 * kp) * Ncols + n];
            v1 = W[(size_t)(2 * kp + 1) * Ncols + n];
        }
        __nv_bfloat16 h0, l0, h1, l1;
        split1(v0, h0, l0);
        split1(v1, h1, l1);
        oh[j] = pack2(h0, h1);
        ol[j] = pack2(l0, l1);
    }
    size_t o = (size_t)kp * WB_NS + n0;
    *reinterpret_cast<uint4*>(g_wb_h + o) = make_uint4(oh[0], oh[1], oh[2], oh[3]);
    *reinterpret_cast<uint4*>(g_wb_l + o) = make_uint4(ol[0], ol[1], ol[2], ol[3]);
}

// ---------------------------------------------------------------------------
__device__ __forceinline__ void mma16(float d[4], const uint32_t a[4], const uint32_t b[2]) {
    asm volatile(
        "mma.sync.aligned.m16n8k16.row.col.f32.bf16.bf16.f32 "
        "{%0,%1,%2,%3}, {%4,%5,%6,%7}, {%8,%9}, {%0,%1,%2,%3};\n"
        : "+f"(d[0]), "+f"(d[1]), "+f"(d[2]), "+f"(d[3])
        : "r"(a[0]), "r"(a[1]), "r"(a[2]), "r"(a[3]), "r"(b[0]), "r"(b[1]));
}
__device__ __forceinline__ void cp_async16(uint32_t smem_addr, const void* gptr, int src_bytes) {
    asm volatile("cp.async.cg.shared.global [%0], [%1], 16, %2;"
                 :: "r"(smem_addr), "l"(gptr), "r"(src_bytes) : "memory");
}
__device__ __forceinline__ void cp_async_commit() {
    asm volatile("cp.async.commit_group;" ::: "memory");
}
__device__ __forceinline__ void cp_async_wait0() {
    asm volatile("cp.async.wait_group 0;" ::: "memory");
}

// ---------------------------------------------------------------------------
// node GEMM: bf16x3, cp.async double buffer, 2 CTAs/SM.
// m_mode 0: M=g_ncount (needed compact), out fp32 g_h1 (compact).
// m_mode 1: M=g_count (pair compact), out bf16-split g_p_h/l.
#define TC_BM 128
#define TC_BN 128
#define AS2 36
#define BS2 136
#define A_U32 (TC_BM * AS2)
#define B_U32 (16 * BS2)
#define STAGE_U32 (2 * A_U32 + 2 * B_U32)   // 13568
#define NUM_KT 12

__global__ __launch_bounds__(256, 2) void gemm_nodes_tc(
        const float* __restrict__ bias, int m_mode) {
    const int N = D_FEAT;
    int M = m_mode ? g_count : g_ncount;

    int bm = blockIdx.y * TC_BM;
    if (bm >= M) return;
    int bn = blockIdx.x * TC_BN;

    extern __shared__ uint32_t smu[];
    uint32_t smem_base = (uint32_t)__cvta_generic_to_shared(smu);

    int tid = threadIdx.x;
    int lane = tid & 31;
    int wid = tid >> 5;
    int wm = (wid & 1) * 64;
    int wn = (wid >> 1) * 32;
    int r = lane >> 2;
    int c = lane & 3;

    float acc[4][4][4];
    #pragma unroll
    for (int i = 0; i < 4; i++)
        #pragma unroll
        for (int j = 0; j < 4; j++)
            #pragma unroll
            for (int q = 0; q < 4; q++) acc[i][j][q] = 0.f;

    int a_row = tid >> 2;
    int a_q4  = tid & 3;
    int b_kp = tid >> 5;
    int b_n4 = tid & 31;

    auto copy_tile = [&](int t, int stage) {
        int kp0 = t * 16;
        uint32_t sbase = smem_base + (uint32_t)(stage * STAGE_U32 * 4);
        uint32_t As_h = sbase;
        uint32_t As_l = sbase + (uint32_t)(A_U32 * 4);
        uint32_t Bs_h = sbase + (uint32_t)(2 * A_U32 * 4);
        uint32_t Bs_l = Bs_h + (uint32_t)(B_U32 * 4);
        #pragma unroll
        for (int p = 0; p < 2; p++) {
            int m = p * 64 + a_row;
            int gm = bm + m;
            int ok = (gm < M) ? 16 : 0;
            size_t go = (size_t)gm * AKP + kp0 + a_q4 * 4;
            uint32_t so = (uint32_t)((m * AS2 + a_q4 * 4) * 4);
            cp_async16(As_h + so, g_agg_h + go, ok);
            cp_async16(As_l + so, g_agg_l + go, ok);
        }
        #pragma unroll
        for (int p = 0; p < 2; p++) {
            int kp = p * 8 + b_kp;
            size_t go = (size_t)(kp0 + kp) * WB_NS + bn + b_n4 * 4;
            uint32_t so = (uint32_t)((kp * BS2 + b_n4 * 4) * 4);
            cp_async16(Bs_h + so, g_wb_h + go, 16);
            cp_async16(Bs_l + so, g_wb_l + go, 16);
        }
        cp_async_commit();
    };

    copy_tile(0, 0);
    cp_async_wait0();
    __syncthreads();

    for (int t = 0; t < NUM_KT; t++) {
        if (t + 1 < NUM_KT) copy_tile(t + 1, (t + 1) & 1);

        {
            const uint32_t* base = smu + (t & 1) * STAGE_U32;
            const uint32_t* As_h = base;
            const uint32_t* As_l = base + A_U32;
            const uint32_t* Bs_h = base + 2 * A_U32;
            const uint32_t* Bs_l = Bs_h + B_U32;

            #pragma unroll
            for (int kk = 0; kk < 2; kk++) {
                uint32_t ah[4][4], al[4][4], bh[4][2], bl[4][2];
                #pragma unroll
                for (int mt = 0; mt < 4; mt++) {
                    int row = wm + mt * 16 + r;
                    const uint32_t* ph = As_h + row * AS2 + kk * 8 + c;
                    const uint32_t* pl = As_l + row * AS2 + kk * 8 + c;
                    ah[mt][0] = ph[0];
                    ah[mt][1] = ph[8 * AS2];
                    ah[mt][2] = ph[4];
                    ah[mt][3] = ph[8 * AS2 + 4];
                    al[mt][0] = pl[0];
                    al[mt][1] = pl[8 * AS2];
                    al[mt][2] = pl[4];
                    al[mt][3] = pl[8 * AS2 + 4];
                }
                #pragma unroll
                for (int nt = 0; nt < 4; nt++) {
                    int col = wn + nt * 8 + r;
                    const uint32_t* qh = Bs_h + (kk * 8 + c) * BS2 + col;
                    const uint32_t* ql = Bs_l + (kk * 8 + c) * BS2 + col;
                    bh[nt][0] = qh[0];
                    bh[nt][1] = qh[4 * BS2];
                    bl[nt][0] = ql[0];
                    bl[nt][1] = ql[4 * BS2];
                }
                #pragma unroll
                for (int mt = 0; mt < 4; mt++)
                    #pragma unroll
                    for (int nt = 0; nt < 4; nt++) {
                        mma16(acc[mt][nt], ah[mt], bh[nt]);
                        mma16(acc[mt][nt], al[mt], bh[nt]);
                        mma16(acc[mt][nt], ah[mt], bl[nt]);
                    }
            }
        }

        if (t + 1 < NUM_KT) cp_async_wait0();
        __syncthreads();
    }

    #pragma unroll
    for (int mt = 0; mt < 4; mt++) {
        int gm0 = bm + wm + mt * 16 + r;
        #pragma unroll
        for (int nt = 0; nt < 4; nt++) {
            int gn = bn + wn + nt * 8 + 2 * c;
            if (m_mode == 0) {
                if (gn >= N) continue;
                float b0 = bias[gn], b1 = bias[gn + 1];
                float v0 = acc[mt][nt][0] + b0;
                float v1 = acc[mt][nt][1] + b1;
                float v2 = acc[mt][nt][2] + b0;
                float v3 = acc[mt][nt][3] + b1;
                v0 = v0 > 0.f ? v0 : NEG_SLOPE * v0;
                v1 = v1 > 0.f ? v1 : NEG_SLOPE * v1;
                v2 = v2 > 0.f ? v2 : NEG_SLOPE * v2;
                v3 = v3 > 0.f ? v3 : NEG_SLOPE * v3;
                if (gm0 < M)
                    *reinterpret_cast<float2*>(g_h1 + (size_t)gm0 * N + gn) = make_float2(v0, v1);
                if (gm0 + 8 < M)
                    *reinterpret_cast<float2*>(g_h1 + (size_t)(gm0 + 8) * N + gn) = make_float2(v2, v3);
            } else {
                bool valid = gn < N;
                float b0 = valid ? bias[gn] : 0.f;
                float b1 = valid ? bias[gn + 1] : 0.f;
                float v0 = valid ? acc[mt][nt][0] + b0 : 0.f;
                float v1 = valid ? acc[mt][nt][1] + b1 : 0.f;
                float v2 = valid ? acc[mt][nt][2] + b0 : 0.f;
                float v3 = valid ? acc[mt][nt][3] + b1 : 0.f;
                v0 = v0 > 0.f ? v0 : NEG_SLOPE * v0;
                v1 = v1 > 0.f ? v1 : NEG_SLOPE * v1;
                v2 = v2 > 0.f ? v2 : NEG_SLOPE * v2;
                v3 = v3 > 0.f ? v3 : NEG_SLOPE * v3;
                int kp = gn >> 1;
                if (gm0 < M) {
                    __nv_bfloat16 h0, l0, h1, l1;
                    split1(v0, h0, l0);
                    split1(v1, h1, l1);
                    g_p_h[(size_t)gm0 * AKP + kp] = pack2(h0, h1);
                    g_p_l[(size_t)gm0 * AKP + kp] = pack2(l0, l1);
                }
                if (gm0 + 8 < M) {
                    __nv_bfloat16 h2, l2, h3, l3;
                    split1(v2, h2, l2);
                    split1(v3, h3, l3);
                    g_p_h[(size_t)(gm0 + 8) * AKP + kp] = pack2(h2, h3);
                    g_p_l[(size_t)(gm0 + 8) * AKP + kp] = pack2(l2, l3);
                }
            }
        }
    }
}

// ---------------------------------------------------------------------------
// pairs GEMM: bf16x3, g_z = lrelu(p[rows] @ W3 + b3).
__global__ __launch_bounds__(256, 2) void gemm_pairs_bf16(
        const int* __restrict__ v1, const int* __restrict__ v2,
        const float* __restrict__ bias) {
    const int N = D_OUT;   // 150

    int bm = blockIdx.y * TC_BM;
    int bn = blockIdx.x * TC_BN;

    extern __shared__ uint32_t smu[];
    uint32_t smem_base = (uint32_t)__cvta_generic_to_shared(smu);
    __shared__ int rows_sh[TC_BM];

    int tid = threadIdx.x;
    int lane = tid & 31;
    int wid = tid >> 5;
    int wm = (wid & 1) * 64;
    int wn = (wid >> 1) * 32;
    int r = lane >> 2;
    int c = lane & 3;

    if (tid < TC_BM) {
        int gm = bm + tid;
        int v = (gm < N_PAIRS) ? v1[gm] : v2[gm - N_PAIRS];
        rows_sh[tid] = g_newidx[v];
    }
    __syncthreads();

    float acc[4][4][4];
    #pragma unroll
    for (int i = 0; i < 4; i++)
        #pragma unroll
        for (int j = 0; j < 4; j++)
            #pragma unroll
            for (int q = 0; q < 4; q++) acc[i][j][q] = 0.f;

    int a_row = tid >> 2;
    int a_q4  = tid & 3;
    int b_kp = tid >> 5;
    int b_n4 = tid & 31;

    auto copy_tile = [&](int t, int stage) {
        int kp0 = t * 16;
        uint32_t sbase = smem_base + (uint32_t)(stage * STAGE_U32 * 4);
        uint32_t As_h = sbase;
        uint32_t As_l = sbase + (uint32_t)(A_U32 * 4);
        uint32_t Bs_h = sbase + (uint32_t)(2 * A_U32 * 4);
        uint32_t Bs_l = Bs_h + (uint32_t)(B_U32 * 4);
        #pragma unroll
        for (int p = 0; p < 2; p++) {
            int m = p * 64 + a_row;
            int row = rows_sh[m];
            size_t go = (size_t)row * AKP + kp0 + a_q4 * 4;
            uint32_t so = (uint32_t)((m * AS2 + a_q4 * 4) * 4);
            cp_async16(As_h + so, g_p_h + go, 16);
            cp_async16(As_l + so, g_p_l + go, 16);
        }
        #pragma unroll
        for (int p = 0; p < 2; p++) {
            int kp = p * 8 + b_kp;
            size_t go = (size_t)(kp0 + kp) * WB_NS + bn + b_n4 * 4;
            uint32_t so = (uint32_t)((kp * BS2 + b_n4 * 4) * 4);
            cp_async16(Bs_h + so, g_wb_h + go, 16);
            cp_async16(Bs_l + so, g_wb_l + go, 16);
        }
        cp_async_commit();
    };

    copy_tile(0, 0);
    cp_async_wait0();
    __syncthreads();

    for (int t = 0; t < NUM_KT; t++) {
        if (t + 1 < NUM_KT) copy_tile(t + 1, (t + 1) & 1);

        {
            const uint32_t* base = smu + (t & 1) * STAGE_U32;
            const uint32_t* As_h = base;
            const uint32_t* As_l = base + A_U32;
            const uint32_t* Bs_h = base + 2 * A_U32;
            const uint32_t* Bs_l = Bs_h + B_U32;

            #pragma unroll
            for (int kk = 0; kk < 2; kk++) {
                uint32_t ah[4][4], al[4][4], bh[4][2], bl[4][2];
                #pragma unroll
                for (int mt = 0; mt < 4; mt++) {
                    int row = wm + mt * 16 + r;
                    const uint32_t* ph = As_h + row * AS2 + kk * 8 + c;
                    const uint32_t* pl = As_l + row * AS2 + kk * 8 + c;
                    ah[mt][0] = ph[0];
                    ah[mt][1] = ph[8 * AS2];
                    ah[mt][2] = ph[4];
                    ah[mt][3] = ph[8 * AS2 + 4];
                    al[mt][0] = pl[0];
                    al[mt][1] = pl[8 * AS2];
                    al[mt][2] = pl[4];
                    al[mt][3] = pl[8 * AS2 + 4];
                }
                #pragma unroll
                for (int nt = 0; nt < 4; nt++) {
                    int col = wn + nt * 8 + r;
                    const uint32_t* qh = Bs_h + (kk * 8 + c) * BS2 + col;
                    const uint32_t* ql = Bs_l + (kk * 8 + c) * BS2 + col;
                    bh[nt][0] = qh[0];
                    bh[nt][1] = qh[4 * BS2];
                    bl[nt][0] = ql[0];
                    bl[nt][1] = ql[4 * BS2];
                }
                #pragma unroll
                for (int mt = 0; mt < 4; mt++)
                    #pragma unroll
                    for (int nt = 0; nt < 4; nt++) {
                        mma16(acc[mt][nt], ah[mt], bh[nt]);
                        mma16(acc[mt][nt], al[mt], bh[nt]);
                        mma16(acc[mt][nt], ah[mt], bl[nt]);
                    }
            }
        }

        if (t + 1 < NUM_KT) cp_async_wait0();
        __syncthreads();
    }

    #pragma unroll
    for (int mt = 0; mt < 4; mt++) {
        int gm0 = bm + wm + mt * 16 + r;
        #pragma unroll
        for (int nt = 0; nt < 4; nt++) {
            int gn = bn + wn + nt * 8 + 2 * c;
            if (gn + 1 >= N) continue;
            float b0 = bias[gn], b1 = bias[gn + 1];
            float v0 = acc[mt][nt][0] + b0;
            float v1 = acc[mt][nt][1] + b1;
            float v2 = acc[mt][nt][2] + b0;
            float v3 = acc[mt][nt][3] + b1;
            v0 = v0 > 0.f ? v0 : NEG_SLOPE * v0;
            v1 = v1 > 0.f ? v1 : NEG_SLOPE * v1;
            v2 = v2 > 0.f ? v2 : NEG_SLOPE * v2;
            v3 = v3 > 0.f ? v3 : NEG_SLOPE * v3;
            *reinterpret_cast<float2*>(g_z + (size_t)gm0 * N + gn) = make_float2(v0, v1);
            *reinterpret_cast<float2*>(g_z + (size_t)(gm0 + 8) * N + gn) = make_float2(v2, v3);
        }
    }
}

// ---------------------------------------------------------------------------
__global__ void normalize_kernel(float* __restrict__ out) {
    int row  = (blockIdx.x * blockDim.x + threadIdx.x) >> 5;
    int lane = threadIdx.x & 31;
    if (row >= 2 * N_PAIRS) return;
    const float* zr = g_z + (size_t)row * D_OUT;
    float ss = 0.f;
    for (int i = lane; i < D_OUT; i += 32) { float v = zr[i]; ss += v * v; }
    #pragma unroll
    for (int o = 16; o; o >>= 1) ss += __shfl_xor_sync(0xFFFFFFFFu, ss, o);
    float norm = sqrtf(ss);
    float inv = 1.f / fmaxf(norm, 1e-12f);
    for (int i = lane; i < D_OUT; i += 32) out[(size_t)row * D_OUT + i] = zr[i] * inv;
}

// ---------------------------------------------------------------------------
extern "C" void kernel_launch(void* const* d_in, const int* in_sizes, int n_in,
                              void* d_out, int out_size) {
    const float* features = (const float*)d_in[0];
    const int*   src      = (const int*)  d_in[1];
    const int*   dst      = (const int*)  d_in[2];
    const int*   v1       = (const int*)  d_in[3];
    const int*   v2       = (const int*)  d_in[4];
    const float* W1       = (const float*)d_in[5];
    const float* b1       = (const float*)d_in[6];
    const float* W2       = (const float*)d_in[7];
    const float* b2       = (const float*)d_in[8];
    const float* W3       = (const float*)d_in[9];
    const float* b3       = (const float*)d_in[10];
    float* out = (float*)d_out;
    (void)in_sizes; (void)n_in; (void)out_size;

    size_t tc_smem = (size_t)2 * STAGE_U32 * sizeof(uint32_t);      // 108544 B
    cudaFuncSetAttribute(gemm_nodes_tc, cudaFuncAttributeMaxDynamicSharedMemorySize,
                         (int)tc_smem);
    cudaFuncSetAttribute(gemm_pairs_bf16, cudaFuncAttributeMaxDynamicSharedMemorySize,
                         (int)tc_smem);

    dim3 tc_grid1((D_FEAT + TC_BN - 1) / TC_BN, (N_NODES + TC_BM - 1) / TC_BM);
    dim3 tc_grid2((D_FEAT + TC_BN - 1) / TC_BN, (2 * N_PAIRS) / TC_BM);
    dim3 pairs_grid((D_OUT + TC_BN - 1) / TC_BN, (2 * N_PAIRS) / TC_BM);
    int gather1_blocks = (N_NODES * 64 + 255) / 256;      // worst case
    int gather2_blocks = (2 * N_PAIRS * 64 + 255) / 256;
    int convw_blocks = (AKP * (WB_NS / 4) + 255) / 256;

    // CSR + pair-mark + needed-set compaction
    csr_zero_kernel<<<(N_NODES + 255) / 256, 256>>>();
    csr_count_mark_kernel<<<(N_EDGES + 255) / 256, 256>>>(dst, v1, v2);
    need_edge_kernel<<<(N_EDGES + 255) / 256, 256>>>(src, dst);
    scan_partial_kernel<<<SCAN_NB, SCAN_B>>>();
    scan_blocksums_kernel<<<1, 256>>>();
    scan_final_kernel<<<SCAN_NB, SCAN_B>>>();
    csr_fill_kernel<<<(N_EDGES + 255) / 256, 256>>>(src, dst);

    // layer 1 (needed nodes only) -> compact fp32 h1
    convert_w_kernel<<<convw_blocks, 256>>>(W1, D_FEAT);
    gather_kernel<<<gather1_blocks, 256>>>(features);
    gemm_nodes_tc<<<tc_grid1, 256, tc_smem>>>(b1, /*m_mode=*/0);

    // layer 2 (pair nodes) -> bf16-split h2
    convert_w_kernel<<<convw_blocks, 256>>>(W2, D_FEAT);
    gather2_kernel<<<gather2_blocks, 256>>>();
    gemm_nodes_tc<<<tc_grid2, 256, tc_smem>>>(b2, /*m_mode=*/1);

    // pair projection (bf16) + normalize
    convert_w_kernel<<<convw_blocks, 256>>>(W3, D_OUT);
    gemm_pairs_bf16<<<pairs_grid, 256, tc_smem>>>(v1, v2, b3);
    normalize_kernel<<<(2 * N_PAIRS * 32 + 255) / 256, 256>>>(out);
}

// round 16
// speedup vs baseline: 1.8676x; 1.0536x over previous
#include <cuda_runtime.h>
#include <cuda_bf16.h>
#include <math.h>
#include <stdint.h>

#define N_NODES 50000
#define D_FEAT  364
#define D_OUT   150
#define N_PAIRS 8192
#define N_EDGES 200000
#define NEG_SLOPE 0.01f

#define AKP 192
#define WB_NS 384

#define SCAN_B 256
#define SCAN_NB ((N_NODES + SCAN_B - 1) / SCAN_B)   // 196

// Scratch (no cudaMalloc allowed).
__device__ __align__(16) float g_h1 [(size_t)N_NODES * D_FEAT];   // compact (needed set)
__device__ __align__(16) uint32_t g_agg_h[(size_t)N_NODES * AKP];
__device__ __align__(16) uint32_t g_agg_l[(size_t)N_NODES * AKP];
// bf16-split weights (all 3, converted once)
__device__ __align__(16) uint32_t g_wb1_h[(size_t)AKP * WB_NS];
__device__ __align__(16) uint32_t g_wb1_l[(size_t)AKP * WB_NS];
__device__ __align__(16) uint32_t g_wb2_h[(size_t)AKP * WB_NS];
__device__ __align__(16) uint32_t g_wb2_l[(size_t)AKP * WB_NS];
__device__ __align__(16) uint32_t g_wb3_h[(size_t)AKP * WB_NS];
__device__ __align__(16) uint32_t g_wb3_l[(size_t)AKP * WB_NS];
// bf16-split compact h2
__device__ __align__(16) uint32_t g_p_h [(size_t)2 * N_PAIRS * AKP];
__device__ __align__(16) uint32_t g_p_l [(size_t)2 * N_PAIRS * AKP];

// CSR-by-dst scratch
__device__ int g_deg [N_NODES];
__device__ int g_off [N_NODES];
__device__ int g_pos [N_NODES];
__device__ int g_srcs[N_EDGES];

// compactions
__device__ int g_mark  [N_NODES];
__device__ int g_newidx[N_NODES];
__device__ int g_list  [2 * N_PAIRS];
__device__ int g_count;
__device__ int g_need [N_NODES];
__device__ int g_nidx [N_NODES];
__device__ int g_nlist[N_NODES];
__device__ int g_ncount;

// scan block sums
__device__ int g_bs_deg [SCAN_NB];
__device__ int g_bs_mark[SCAN_NB];
__device__ int g_bs_need[SCAN_NB];

// ---------------------------------------------------------------------------
__device__ __forceinline__ void split1(float v, __nv_bfloat16& h, __nv_bfloat16& l) {
    h = __float2bfloat16_rn(v);
    l = __float2bfloat16_rn(v - __bfloat162float(h));
}
__device__ __forceinline__ uint32_t pack2(__nv_bfloat16 lo, __nv_bfloat16 hi) {
    __nv_bfloat162 p;
    p.x = lo; p.y = hi;
    return *reinterpret_cast<uint32_t*>(&p);
}

// ---------------------------------------------------------------------------
__global__ void csr_zero_kernel() {
    int i = blockIdx.x * blockDim.x + threadIdx.x;
    if (i < N_NODES) { g_deg[i] = 0; g_mark[i] = 0; g_need[i] = 0; }
}
__global__ void csr_count_mark_kernel(const int* __restrict__ dst,
                                      const int* __restrict__ v1,
                                      const int* __restrict__ v2) {
    int e = blockIdx.x * blockDim.x + threadIdx.x;
    if (e < N_EDGES) atomicAdd(&g_deg[dst[e]], 1);
    if (e < N_PAIRS) {
        int a = v1[e], b = v2[e];
        g_mark[a] = 1; g_mark[b] = 1;
        g_need[a] = 1; g_need[b] = 1;
    }
}
__global__ void need_edge_kernel(const int* __restrict__ src,
                                 const int* __restrict__ dst) {
    int e = blockIdx.x * blockDim.x + threadIdx.x;
    if (e >= N_EDGES) return;
    if (g_mark[dst[e]]) g_need[src[e]] = 1;
}

__global__ void scan_partial_kernel() {
    __shared__ int wsum_d[8], wsum_m[8], wsum_n[8];
    int tid = threadIdx.x, lane = tid & 31, w = tid >> 5;
    int i = blockIdx.x * SCAN_B + tid;
    int vd = (i < N_NODES) ? g_deg[i] : 0;
    int vm = (i < N_NODES) ? g_mark[i] : 0;
    int vn = (i < N_NODES) ? g_need[i] : 0;
    #pragma unroll
    for (int o = 16; o; o >>= 1) {
        vd += __shfl_xor_sync(0xFFFFFFFFu, vd, o);
        vm += __shfl_xor_sync(0xFFFFFFFFu, vm, o);
        vn += __shfl_xor_sync(0xFFFFFFFFu, vn, o);
    }
    if (lane == 0) { wsum_d[w] = vd; wsum_m[w] = vm; wsum_n[w] = vn; }
    __syncthreads();
    if (tid == 0) {
        int sd = 0, sm = 0, sn = 0;
        #pragma unroll
        for (int j = 0; j < 8; j++) { sd += wsum_d[j]; sm += wsum_m[j]; sn += wsum_n[j]; }
        g_bs_deg[blockIdx.x] = sd;
        g_bs_mark[blockIdx.x] = sm;
        g_bs_need[blockIdx.x] = sn;
    }
}

__global__ void scan_blocksums_kernel() {
    __shared__ int wt_d[8], wt_m[8], wt_n[8];
    int tid = threadIdx.x, lane = tid & 31, w = tid >> 5;
    int vd = (tid < SCAN_NB) ? g_bs_deg[tid] : 0;
    int vm = (tid < SCAN_NB) ? g_bs_mark[tid] : 0;
    int vn = (tid < SCAN_NB) ? g_bs_need[tid] : 0;
    int sd = vd, sm = vm, sn = vn;
    #pragma unroll
    for (int o = 1; o < 32; o <<= 1) {
        int td = __shfl_up_sync(0xFFFFFFFFu, sd, o);
        int tm = __shfl_up_sync(0xFFFFFFFFu, sm, o);
        int tn = __shfl_up_sync(0xFFFFFFFFu, sn, o);
        if (lane >= o) { sd += td; sm += tm; sn += tn; }
    }
    if (lane == 31) { wt_d[w] = sd; wt_m[w] = sm; wt_n[w] = sn; }
    __syncthreads();
    if (w == 0) {
        int td = (lane < 8) ? wt_d[lane] : 0;
        int tm = (lane < 8) ? wt_m[lane] : 0;
        int tn = (lane < 8) ? wt_n[lane] : 0;
        int sd2 = td, sm2 = tm, sn2 = tn;
        #pragma unroll
        for (int o = 1; o < 8; o <<= 1) {
            int ud = __shfl_up_sync(0xFFFFFFFFu, sd2, o);
            int um = __shfl_up_sync(0xFFFFFFFFu, sm2, o);
            int un = __shfl_up_sync(0xFFFFFFFFu, sn2, o);
            if (lane >= o) { sd2 += ud; sm2 += um; sn2 += un; }
        }
        if (lane < 8) { wt_d[lane] = sd2 - td; wt_m[lane] = sm2 - tm; wt_n[lane] = sn2 - tn; }
    }
    __syncthreads();
    if (tid < SCAN_NB) {
        g_bs_deg[tid]  = sd - vd + wt_d[w];
        g_bs_mark[tid] = sm - vm + wt_m[w];
        g_bs_need[tid] = sn - vn + wt_n[w];
    }
    if (tid == SCAN_NB - 1) {
        g_count  = sm + wt_m[w];
        g_ncount = sn + wt_n[w];
    }
}

__global__ void scan_final_kernel() {
    __shared__ int wt_d[8], wt_m[8], wt_n[8];
    int tid = threadIdx.x, lane = tid & 31, w = tid >> 5;
    int i = blockIdx.x * SCAN_B + tid;
    int vd = (i < N_NODES) ? g_deg[i] : 0;
    int vm = (i < N_NODES) ? g_mark[i] : 0;
    int vn = (i < N_NODES) ? g_need[i] : 0;
    int sd = vd, sm = vm, sn = vn;
    #pragma unroll
    for (int o = 1; o < 32; o <<= 1) {
        int td = __shfl_up_sync(0xFFFFFFFFu, sd, o);
        int tm = __shfl_up_sync(0xFFFFFFFFu, sm, o);
        int tn = __shfl_up_sync(0xFFFFFFFFu, sn, o);
        if (lane >= o) { sd += td; sm += tm; sn += tn; }
    }
    if (lane == 31) { wt_d[w] = sd; wt_m[w] = sm; wt_n[w] = sn; }
    __syncthreads();
    if (w == 0) {
        int td = (lane < 8) ? wt_d[lane] : 0;
        int tm = (lane < 8) ? wt_m[lane] : 0;
        int tn = (lane < 8) ? wt_n[lane] : 0;
        int sd2 = td, sm2 = tm, sn2 = tn;
        #pragma unroll
        for (int o = 1; o < 8; o <<= 1) {
            int ud = __shfl_up_sync(0xFFFFFFFFu, sd2, o);
            int um = __shfl_up_sync(0xFFFFFFFFu, sm2, o);
            int un = __shfl_up_sync(0xFFFFFFFFu, sn2, o);
            if (lane >= o) { sd2 += ud; sm2 += um; sn2 += un; }
        }
        if (lane < 8) { wt_d[lane] = sd2 - td; wt_m[lane] = sm2 - tm; wt_n[lane] = sn2 - tn; }
    }
    __syncthreads();
    if (i < N_NODES) {
        int off_d = g_bs_deg[blockIdx.x]  + sd - vd + wt_d[w];
        int off_m = g_bs_mark[blockIdx.x] + sm - vm + wt_m[w];
        int off_n = g_bs_need[blockIdx.x] + sn - vn + wt_n[w];
        g_off[i] = off_d;
        g_pos[i] = off_d;
        g_newidx[i] = off_m;
        if (vm) g_list[off_m] = i;
        g_nidx[i] = off_n;
        if (vn) g_nlist[off_n] = i;
    }
}

__global__ void csr_fill_kernel(const int* __restrict__ src,
                                const int* __restrict__ dst) {
    int e = blockIdx.x * blockDim.x + threadIdx.x;
    if (e >= N_EDGES) return;
    int idx = atomicAdd(&g_pos[dst[e]], 1);
    g_srcs[idx] = src[e];
}

// ---------------------------------------------------------------------------
// gather core (unchanged from R15)
__device__ __forceinline__ void gather_one(const float* __restrict__ x,
                                           int node, int outrow,
                                           int half, int lane, int remap) {
    int off = g_off[node];
    int deg = g_deg[node];

    int base4 = half * 46;
    int cnt   = half ? 45 : 46;
    int i0 = base4 + lane;
    int i1 = base4 + 32 + lane;
    bool p1 = (32 + lane) < cnt;

    int drow = remap ? g_nidx[node] : node;
    const float4* xd = reinterpret_cast<const float4*>(x + (size_t)drow * D_FEAT);
    float4 a0 = xd[i0];
    float4 a1 = p1 ? xd[i1] : make_float4(0.f, 0.f, 0.f, 0.f);

    for (int e = 0; e < deg; e++) {
        int s = g_srcs[off + e];
        int srow = remap ? g_nidx[s] : s;
        const float4* xs = reinterpret_cast<const float4*>(x + (size_t)srow * D_FEAT);
        float4 v0 = xs[i0];
        a0.x += v0.x; a0.y += v0.y; a0.z += v0.z; a0.w += v0.w;
        if (p1) {
            float4 v1 = xs[i1];
            a1.x += v1.x; a1.y += v1.y; a1.z += v1.z; a1.w += v1.w;
        }
    }

    uint32_t* oh = g_agg_h + (size_t)outrow * AKP;
    uint32_t* ol = g_agg_l + (size_t)outrow * AKP;
    {
        __nv_bfloat16 hx, lx, hy, ly, hz, lz, hw, lw;
        split1(a0.x, hx, lx); split1(a0.y, hy, ly);
        split1(a0.z, hz, lz); split1(a0.w, hw, lw);
        *reinterpret_cast<uint2*>(oh + 2 * i0) = make_uint2(pack2(hx, hy), pack2(hz, hw));
        *reinterpret_cast<uint2*>(ol + 2 * i0) = make_uint2(pack2(lx, ly), pack2(lz, lw));
    }
    if (p1) {
        __nv_bfloat16 hx, lx, hy, ly, hz, lz, hw, lw;
        split1(a1.x, hx, lx); split1(a1.y, hy, ly);
        split1(a1.z, hz, lz); split1(a1.w, hw, lw);
        *reinterpret_cast<uint2*>(oh + 2 * i1) = make_uint2(pack2(hx, hy), pack2(hz, hw));
        *reinterpret_cast<uint2*>(ol + 2 * i1) = make_uint2(pack2(lx, ly), pack2(lz, lw));
    }
    if (half && lane >= 13 && lane <= 17) {
        *reinterpret_cast<uint2*>(oh + 2 * i1) = make_uint2(0u, 0u);
        *reinterpret_cast<uint2*>(ol + 2 * i1) = make_uint2(0u, 0u);
    }
}

__global__ void gather_kernel(const float* __restrict__ x_ext) {
    int gw = (blockIdx.x * blockDim.x + threadIdx.x) >> 5;
    int lane = threadIdx.x & 31;
    int i = gw >> 1;
    int half = gw & 1;
    if (i >= g_ncount) return;
    gather_one(x_ext, g_nlist[i], i, half, lane, 0);
}
__global__ void gather2_kernel() {
    int gw = (blockIdx.x * blockDim.x + threadIdx.x) >> 5;
    int lane = threadIdx.x & 31;
    int i = gw >> 1;
    int half = gw & 1;
    if (i >= g_count) return;
    gather_one(g_h1, g_list[i], i, half, lane, 1);
}

// ---------------------------------------------------------------------------
// fused convert of all three weights
__global__ void convert_w_all_kernel(const float* __restrict__ W1,
                                     const float* __restrict__ W2,
                                     const float* __restrict__ W3) {
    const int PER = AKP * (WB_NS / 4);
    int idx = blockIdx.x * blockDim.x + threadIdx.x;
    int wsel = idx / PER;
    int rem  = idx % PER;
    if (wsel >= 3) return;
    int kp = rem / (WB_NS / 4);
    int nq = rem % (WB_NS / 4);
    int Ncols = (wsel == 2) ? D_OUT : D_FEAT;
    const float* W = (wsel == 0) ? W1 : (wsel == 1) ? W2 : W3;
    uint32_t* outh = (wsel == 0) ? g_wb1_h : (wsel == 1) ? g_wb2_h : g_wb3_h;
    uint32_t* outl = (wsel == 0) ? g_wb1_l : (wsel == 1) ? g_wb2_l : g_wb3_l;
    int n0 = nq * 4;
    uint32_t oh[4], ol[4];
    #pragma unroll
    for (int j = 0; j < 4; j++) {
        int n = n0 + j;
        float v0 = 0.f, v1 = 0.f;
        if (2 * kp < D_FEAT && n < Ncols) {
            v0 = W[(size_t)(2 * kp) * Ncols + n];
            v1 = W[(size_t)(2 * kp + 1) * Ncols + n];
        }
        __nv_bfloat16 h0, l0, h1, l1;
        split1(v0, h0, l0);
        split1(v1, h1, l1);
        oh[j] = pack2(h0, h1);
        ol[j] = pack2(l0, l1);
    }
    size_t o = (size_t)kp * WB_NS + n0;
    *reinterpret_cast<uint4*>(outh + o) = make_uint4(oh[0], oh[1], oh[2], oh[3]);
    *reinterpret_cast<uint4*>(outl + o) = make_uint4(ol[0], ol[1], ol[2], ol[3]);
}

// ---------------------------------------------------------------------------
__device__ __forceinline__ void mma16(float d[4], const uint32_t a[4], const uint32_t b[2]) {
    asm volatile(
        "mma.sync.aligned.m16n8k16.row.col.f32.bf16.bf16.f32 "
        "{%0,%1,%2,%3}, {%4,%5,%6,%7}, {%8,%9}, {%0,%1,%2,%3};\n"
        : "+f"(d[0]), "+f"(d[1]), "+f"(d[2]), "+f"(d[3])
        : "r"(a[0]), "r"(a[1]), "r"(a[2]), "r"(a[3]), "r"(b[0]), "r"(b[1]));
}
__device__ __forceinline__ void cp_async16(uint32_t smem_addr, const void* gptr, int src_bytes) {
    asm volatile("cp.async.cg.shared.global [%0], [%1], 16, %2;"
                 :: "r"(smem_addr), "l"(gptr), "r"(src_bytes) : "memory");
}
__device__ __forceinline__ void cp_async_commit() {
    asm volatile("cp.async.commit_group;" ::: "memory");
}
__device__ __forceinline__ void cp_async_wait0() {
    asm volatile("cp.async.wait_group 0;" ::: "memory");
}

// ---------------------------------------------------------------------------
// node GEMM (as R15) with weight selector.
#define TC_BM 128
#define TC_BN 128
#define AS2 36
#define BS2 136
#define A_U32 (TC_BM * AS2)
#define B_U32 (16 * BS2)
#define STAGE_U32 (2 * A_U32 + 2 * B_U32)   // 13568
#define NUM_KT 12

__global__ __launch_bounds__(256, 2) void gemm_nodes_tc(
        const float* __restrict__ bias, int m_mode) {
    const int N = D_FEAT;
    int M = m_mode ? g_count : g_ncount;
    const uint32_t* __restrict__ wb_h = m_mode ? g_wb2_h : g_wb1_h;
    const uint32_t* __restrict__ wb_l = m_mode ? g_wb2_l : g_wb1_l;

    int bm = blockIdx.y * TC_BM;
    if (bm >= M) return;
    int bn = blockIdx.x * TC_BN;

    extern __shared__ uint32_t smu[];
    uint32_t smem_base = (uint32_t)__cvta_generic_to_shared(smu);

    int tid = threadIdx.x;
    int lane = tid & 31;
    int wid = tid >> 5;
    int wm = (wid & 1) * 64;
    int wn = (wid >> 1) * 32;
    int r = lane >> 2;
    int c = lane & 3;

    float acc[4][4][4];
    #pragma unroll
    for (int i = 0; i < 4; i++)
        #pragma unroll
        for (int j = 0; j < 4; j++)
            #pragma unroll
            for (int q = 0; q < 4; q++) acc[i][j][q] = 0.f;

    int a_row = tid >> 2;
    int a_q4  = tid & 3;
    int b_kp = tid >> 5;
    int b_n4 = tid & 31;

    auto copy_tile = [&](int t, int stage) {
        int kp0 = t * 16;
        uint32_t sbase = smem_base + (uint32_t)(stage * STAGE_U32 * 4);
        uint32_t As_h = sbase;
        uint32_t As_l = sbase + (uint32_t)(A_U32 * 4);
        uint32_t Bs_h = sbase + (uint32_t)(2 * A_U32 * 4);
        uint32_t Bs_l = Bs_h + (uint32_t)(B_U32 * 4);
        #pragma unroll
        for (int p = 0; p < 2; p++) {
            int m = p * 64 + a_row;
            int gm = bm + m;
            int ok = (gm < M) ? 16 : 0;
            size_t go = (size_t)gm * AKP + kp0 + a_q4 * 4;
            uint32_t so = (uint32_t)((m * AS2 + a_q4 * 4) * 4);
            cp_async16(As_h + so, g_agg_h + go, ok);
            cp_async16(As_l + so, g_agg_l + go, ok);
        }
        #pragma unroll
        for (int p = 0; p < 2; p++) {
            int kp = p * 8 + b_kp;
            size_t go = (size_t)(kp0 + kp) * WB_NS + bn + b_n4 * 4;
            uint32_t so = (uint32_t)((kp * BS2 + b_n4 * 4) * 4);
            cp_async16(Bs_h + so, wb_h + go, 16);
            cp_async16(Bs_l + so, wb_l + go, 16);
        }
        cp_async_commit();
    };

    copy_tile(0, 0);
    cp_async_wait0();
    __syncthreads();

    for (int t = 0; t < NUM_KT; t++) {
        if (t + 1 < NUM_KT) copy_tile(t + 1, (t + 1) & 1);

        {
            const uint32_t* base = smu + (t & 1) * STAGE_U32;
            const uint32_t* As_h = base;
            const uint32_t* As_l = base + A_U32;
            const uint32_t* Bs_h = base + 2 * A_U32;
            const uint32_t* Bs_l = Bs_h + B_U32;

            #pragma unroll
            for (int kk = 0; kk < 2; kk++) {
                uint32_t ah[4][4], al[4][4], bh[4][2], bl[4][2];
                #pragma unroll
                for (int mt = 0; mt < 4; mt++) {
                    int row = wm + mt * 16 + r;
                    const uint32_t* ph = As_h + row * AS2 + kk * 8 + c;
                    const uint32_t* pl = As_l + row * AS2 + kk * 8 + c;
                    ah[mt][0] = ph[0];
                    ah[mt][1] = ph[8 * AS2];
                    ah[mt][2] = ph[4];
                    ah[mt][3] = ph[8 * AS2 + 4];
                    al[mt][0] = pl[0];
                    al[mt][1] = pl[8 * AS2];
                    al[mt][2] = pl[4];
                    al[mt][3] = pl[8 * AS2 + 4];
                }
                #pragma unroll
                for (int nt = 0; nt < 4; nt++) {
                    int col = wn + nt * 8 + r;
                    const uint32_t* qh = Bs_h + (kk * 8 + c) * BS2 + col;
                    const uint32_t* ql = Bs_l + (kk * 8 + c) * BS2 + col;
                    bh[nt][0] = qh[0];
                    bh[nt][1] = qh[4 * BS2];
                    bl[nt][0] = ql[0];
                    bl[nt][1] = ql[4 * BS2];
                }
                #pragma unroll
                for (int mt = 0; mt < 4; mt++)
                    #pragma unroll
                    for (int nt = 0; nt < 4; nt++) {
                        mma16(acc[mt][nt], ah[mt], bh[nt]);
                        mma16(acc[mt][nt], al[mt], bh[nt]);
                        mma16(acc[mt][nt], ah[mt], bl[nt]);
                    }
            }
        }

        if (t + 1 < NUM_KT) cp_async_wait0();
        __syncthreads();
    }

    #pragma unroll
    for (int mt = 0; mt < 4; mt++) {
        int gm0 = bm + wm + mt * 16 + r;
        #pragma unroll
        for (int nt = 0; nt < 4; nt++) {
            int gn = bn + wn + nt * 8 + 2 * c;
            if (m_mode == 0) {
                if (gn >= N) continue;
                float b0 = bias[gn], b1 = bias[gn + 1];
                float v0 = acc[mt][nt][0] + b0;
                float v1 = acc[mt][nt][1] + b1;
                float v2 = acc[mt][nt][2] + b0;
                float v3 = acc[mt][nt][3] + b1;
                v0 = v0 > 0.f ? v0 : NEG_SLOPE * v0;
                v1 = v1 > 0.f ? v1 : NEG_SLOPE * v1;
                v2 = v2 > 0.f ? v2 : NEG_SLOPE * v2;
                v3 = v3 > 0.f ? v3 : NEG_SLOPE * v3;
                if (gm0 < M)
                    *reinterpret_cast<float2*>(g_h1 + (size_t)gm0 * N + gn) = make_float2(v0, v1);
                if (gm0 + 8 < M)
                    *reinterpret_cast<float2*>(g_h1 + (size_t)(gm0 + 8) * N + gn) = make_float2(v2, v3);
            } else {
                bool valid = gn < N;
                float b0 = valid ? bias[gn] : 0.f;
                float b1 = valid ? bias[gn + 1] : 0.f;
                float v0 = valid ? acc[mt][nt][0] + b0 : 0.f;
                float v1 = valid ? acc[mt][nt][1] + b1 : 0.f;
                float v2 = valid ? acc[mt][nt][2] + b0 : 0.f;
                float v3 = valid ? acc[mt][nt][3] + b1 : 0.f;
                v0 = v0 > 0.f ? v0 : NEG_SLOPE * v0;
                v1 = v1 > 0.f ? v1 : NEG_SLOPE * v1;
                v2 = v2 > 0.f ? v2 : NEG_SLOPE * v2;
                v3 = v3 > 0.f ? v3 : NEG_SLOPE * v3;
                int kp = gn >> 1;
                if (gm0 < M) {
                    __nv_bfloat16 h0, l0, h1, l1;
                    split1(v0, h0, l0);
                    split1(v1, h1, l1);
                    g_p_h[(size_t)gm0 * AKP + kp] = pack2(h0, h1);
                    g_p_l[(size_t)gm0 * AKP + kp] = pack2(l0, l1);
                }
                if (gm0 + 8 < M) {
                    __nv_bfloat16 h2, l2, h3, l3;
                    split1(v2, h2, l2);
                    split1(v3, h3, l3);
                    g_p_h[(size_t)(gm0 + 8) * AKP + kp] = pack2(h2, h3);
                    g_p_l[(size_t)(gm0 + 8) * AKP + kp] = pack2(l2, l3);
                }
            }
        }
    }
}

// ---------------------------------------------------------------------------
// pairs GEMM + fused L2 normalize. 8 warps x (16m x 160n). One CTA covers the
// full output row -> row norm via quad shfl. Writes final `out` directly.
#define P_NT 20            // 20 x n8 = 160 columns (150 valid + 10 zero pad)
#define PBS3 168           // u32 stride, == 8 mod 32 -> conflict-free
#define PB_U32 (16 * PBS3)                       // 2688
#define P_STAGE_U32 (2 * A_U32 + 2 * PB_U32)     // 14592

__global__ __launch_bounds__(256) void gemm_pairs_norm(
        const int* __restrict__ v1, const int* __restrict__ v2,
        const float* __restrict__ bias, float* __restrict__ out) {
    const int N = D_OUT;   // 150

    int bm = blockIdx.x * TC_BM;

    extern __shared__ uint32_t smu[];
    uint32_t smem_base = (uint32_t)__cvta_generic_to_shared(smu);
    __shared__ int rows_sh[TC_BM];

    int tid = threadIdx.x;
    int lane = tid & 31;
    int wid = tid >> 5;
    int wm = wid * 16;        // 8 warps x 16 rows = 128
    int r = lane >> 2;
    int c = lane & 3;

    if (tid < TC_BM) {
        int gm = bm + tid;
        int v = (gm < N_PAIRS) ? v1[gm] : v2[gm - N_PAIRS];
        rows_sh[tid] = g_newidx[v];
    }
    __syncthreads();

    float acc[P_NT][4];
    #pragma unroll
    for (int j = 0; j < P_NT; j++)
        #pragma unroll
        for (int q = 0; q < 4; q++) acc[j][q] = 0.f;

    int a_row = tid >> 2;
    int a_q4  = tid & 3;

    auto copy_tile = [&](int t, int stage) {
        int kp0 = t * 16;
        uint32_t sbase = smem_base + (uint32_t)(stage * P_STAGE_U32 * 4);
        uint32_t As_h = sbase;
        uint32_t As_l = sbase + (uint32_t)(A_U32 * 4);
        uint32_t Bs_h = sbase + (uint32_t)(2 * A_U32 * 4);
        uint32_t Bs_l = Bs_h + (uint32_t)(PB_U32 * 4);
        #pragma unroll
        for (int p = 0; p < 2; p++) {
            int m = p * 64 + a_row;
            int row = rows_sh[m];
            size_t go = (size_t)row * AKP + kp0 + a_q4 * 4;
            uint32_t so = (uint32_t)((m * AS2 + a_q4 * 4) * 4);
            cp_async16(As_h + so, g_p_h + go, 16);
            cp_async16(As_l + so, g_p_l + go, 16);
        }
        // B: 16 kp x 160 n -> 16*40 uint4 slots, 256 threads, 2-3 iters
        for (int i = tid; i < 16 * 40; i += 256) {
            int kp = i / 40;
            int n4 = i % 40;
            size_t go = (size_t)(kp0 + kp) * WB_NS + n4 * 4;
            uint32_t so = (uint32_t)((kp * PBS3 + n4 * 4) * 4);
            cp_async16(Bs_h + so, g_wb3_h + go, 16);
            cp_async16(Bs_l + so, g_wb3_l + go, 16);
        }
        cp_async_commit();
    };

    copy_tile(0, 0);
    cp_async_wait0();
    __syncthreads();

    for (int t = 0; t < NUM_KT; t++) {
        if (t + 1 < NUM_KT) copy_tile(t + 1, (t + 1) & 1);

        {
            const uint32_t* base = smu + (t & 1) * P_STAGE_U32;
            const uint32_t* As_h = base;
            const uint32_t* As_l = base + A_U32;
            const uint32_t* Bs_h = base + 2 * A_U32;
            const uint32_t* Bs_l = Bs_h + PB_U32;

            #pragma unroll
            for (int kk = 0; kk < 2; kk++) {
                uint32_t ah[4], al[4];
                {
                    int row = wm + r;
                    const uint32_t* ph = As_h + row * AS2 + kk * 8 + c;
                    const uint32_t* pl = As_l + row * AS2 + kk * 8 + c;
                    ah[0] = ph[0];
                    ah[1] = ph[8 * AS2];
                    ah[2] = ph[4];
                    ah[3] = ph[8 * AS2 + 4];
                    al[0] = pl[0];
                    al[1] = pl[8 * AS2];
                    al[2] = pl[4];
                    al[3] = pl[8 * AS2 + 4];
                }
                #pragma unroll
                for (int nt = 0; nt < P_NT; nt++) {
                    int col = nt * 8 + r;
                    const uint32_t* qh = Bs_h + (kk * 8 + c) * PBS3 + col;
                    const uint32_t* ql = Bs_l + (kk * 8 + c) * PBS3 + col;
                    uint32_t bh[2], bl[2];
                    bh[0] = qh[0];
                    bh[1] = qh[4 * PBS3];
                    bl[0] = ql[0];
                    bl[1] = ql[4 * PBS3];
                    mma16(acc[nt], ah, bh);
                    mma16(acc[nt], al, bh);
                    mma16(acc[nt], ah, bl);
                }
            }
        }

        if (t + 1 < NUM_KT) cp_async_wait0();
        __syncthreads();
    }

    // epilogue: bias + lrelu (zero pad cols), row sumsq via quad shfl, write.
    float ss0 = 0.f, ss8 = 0.f;
    #pragma unroll
    for (int nt = 0; nt < P_NT; nt++) {
        int gn = nt * 8 + 2 * c;
        bool valid = (gn + 1) < N;   // gn even; gn=148 valid (148,149), gn>=150 invalid
        float b0 = valid ? bias[gn] : 0.f;
        float b1 = valid ? bias[gn + 1] : 0.f;
        float v0 = valid ? acc[nt][0] + b0 : 0.f;
        float v1 = valid ? acc[nt][1] + b1 : 0.f;
        float v2 = valid ? acc[nt][2] + b0 : 0.f;
        float v3 = valid ? acc[nt][3] + b1 : 0.f;
        v0 = v0 > 0.f ? v0 : NEG_SLOPE * v0;
        v1 = v1 > 0.f ? v1 : NEG_SLOPE * v1;
        v2 = v2 > 0.f ? v2 : NEG_SLOPE * v2;
        v3 = v3 > 0.f ? v3 : NEG_SLOPE * v3;
        acc[nt][0] = v0; acc[nt][1] = v1; acc[nt][2] = v2; acc[nt][3] = v3;
        ss0 += v0 * v0 + v1 * v1;
        ss8 += v2 * v2 + v3 * v3;
    }
    // reduce over quad (lanes sharing r: lane = 4r + c)
    ss0 += __shfl_xor_sync(0xFFFFFFFFu, ss0, 1);
    ss0 += __shfl_xor_sync(0xFFFFFFFFu, ss0, 2);
    ss8 += __shfl_xor_sync(0xFFFFFFFFu, ss8, 1);
    ss8 += __shfl_xor_sync(0xFFFFFFFFu, ss8, 2);
    float inv0 = 1.f / fmaxf(sqrtf(ss0), 1e-12f);
    float inv8 = 1.f / fmaxf(sqrtf(ss8), 1e-12f);

    int gm0 = bm + wm + r;
    #pragma unroll
    for (int nt = 0; nt < P_NT; nt++) {
        int gn = nt * 8 + 2 * c;
        if (gn + 1 >= N) continue;
        *reinterpret_cast<float2*>(out + (size_t)gm0 * N + gn) =
            make_float2(acc[nt][0] * inv0, acc[nt][1] * inv0);
        *reinterpret_cast<float2*>(out + (size_t)(gm0 + 8) * N + gn) =
            make_float2(acc[nt][2] * inv8, acc[nt][3] * inv8);
    }
}

// ---------------------------------------------------------------------------
extern "C" void kernel_launch(void* const* d_in, const int* in_sizes, int n_in,
                              void* d_out, int out_size) {
    const float* features = (const float*)d_in[0];
    const int*   src      = (const int*)  d_in[1];
    const int*   dst      = (const int*)  d_in[2];
    const int*   v1       = (const int*)  d_in[3];
    const int*   v2       = (const int*)  d_in[4];
    const float* W1       = (const float*)d_in[5];
    const float* b1       = (const float*)d_in[6];
    const float* W2       = (const float*)d_in[7];
    const float* b2       = (const float*)d_in[8];
    const float* W3       = (const float*)d_in[9];
    const float* b3       = (const float*)d_in[10];
    float* out = (float*)d_out;
    (void)in_sizes; (void)n_in; (void)out_size;

    size_t tc_smem = (size_t)2 * STAGE_U32 * sizeof(uint32_t);        // 108544 B
    cudaFuncSetAttribute(gemm_nodes_tc, cudaFuncAttributeMaxDynamicSharedMemorySize,
                         (int)tc_smem);
    size_t p_smem = (size_t)2 * P_STAGE_U32 * sizeof(uint32_t);       // 116736 B
    cudaFuncSetAttribute(gemm_pairs_norm, cudaFuncAttributeMaxDynamicSharedMemorySize,
                         (int)p_smem);

    dim3 tc_grid1((D_FEAT + TC_BN - 1) / TC_BN, (N_NODES + TC_BM - 1) / TC_BM);
    dim3 tc_grid2((D_FEAT + TC_BN - 1) / TC_BN, (2 * N_PAIRS) / TC_BM);
    int pairs_grid = (2 * N_PAIRS) / TC_BM;    // 128 CTAs, full row per CTA
    int gather1_blocks = (N_NODES * 64 + 255) / 256;
    int gather2_blocks = (2 * N_PAIRS * 64 + 255) / 256;
    int convw_blocks = (3 * AKP * (WB_NS / 4) + 255) / 256;

    // weights (no deps) + CSR + compactions
    convert_w_all_kernel<<<convw_blocks, 256>>>(W1, W2, W3);
    csr_zero_kernel<<<(N_NODES + 255) / 256, 256>>>();
    csr_count_mark_kernel<<<(N_EDGES + 255) / 256, 256>>>(dst, v1, v2);
    need_edge_kernel<<<(N_EDGES + 255) / 256, 256>>>(src, dst);
    scan_partial_kernel<<<SCAN_NB, SCAN_B>>>();
    scan_blocksums_kernel<<<1, 256>>>();
    scan_final_kernel<<<SCAN_NB, SCAN_B>>>();
    csr_fill_kernel<<<(N_EDGES + 255) / 256, 256>>>(src, dst);

    // layer 1 (needed nodes) -> compact fp32 h1
    gather_kernel<<<gather1_blocks, 256>>>(features);
    gemm_nodes_tc<<<tc_grid1, 256, tc_smem>>>(b1, /*m_mode=*/0);

    // layer 2 (pair nodes) -> bf16-split h2
    gather2_kernel<<<gather2_blocks, 256>>>();
    gemm_nodes_tc<<<tc_grid2, 256, tc_smem>>>(b2, /*m_mode=*/1);

    // pair projection + fused normalize -> out
    gemm_pairs_norm<<<pairs_grid, 256, p_smem>>>(v1, v2, b3, out);
}

// round 17
// speedup vs baseline: 1.8761x; 1.0046x over previous
#include <cuda_runtime.h>
#include <cuda_bf16.h>
#include <math.h>
#include <stdint.h>

#define N_NODES 50000
#define D_FEAT  364
#define D_OUT   150
#define N_PAIRS 8192
#define N_EDGES 200000
#define NEG_SLOPE 0.01f

#define AKP 192
#define WB_NS 384

#define SCAN_B 256
#define SCAN_NB ((N_NODES + SCAN_B - 1) / SCAN_B)   // 196

// Scratch (no cudaMalloc allowed).
__device__ __align__(16) float g_h1 [(size_t)N_NODES * D_FEAT];   // compact (needed set)
__device__ __align__(16) uint32_t g_agg_h[(size_t)N_NODES * AKP];
__device__ __align__(16) uint32_t g_agg_l[(size_t)N_NODES * AKP];
__device__ __align__(16) uint32_t g_wb1_h[(size_t)AKP * WB_NS];
__device__ __align__(16) uint32_t g_wb1_l[(size_t)AKP * WB_NS];
__device__ __align__(16) uint32_t g_wb2_h[(size_t)AKP * WB_NS];
__device__ __align__(16) uint32_t g_wb2_l[(size_t)AKP * WB_NS];
__device__ __align__(16) uint32_t g_wb3_h[(size_t)AKP * WB_NS];
__device__ __align__(16) uint32_t g_wb3_l[(size_t)AKP * WB_NS];
__device__ __align__(16) uint32_t g_p_h [(size_t)2 * N_PAIRS * AKP];
__device__ __align__(16) uint32_t g_p_l [(size_t)2 * N_PAIRS * AKP];

// CSR-by-dst scratch
__device__ int g_deg [N_NODES];
__device__ int g_off [N_NODES];
__device__ int g_pos [N_NODES];
__device__ int g_srcs[N_EDGES];

// compactions
__device__ int g_mark  [N_NODES];
__device__ int g_newidx[N_NODES];
__device__ int g_list  [2 * N_PAIRS];
__device__ int g_count;
__device__ int g_need [N_NODES];
__device__ int g_nidx [N_NODES];
__device__ int g_nlist[N_NODES];
__device__ int g_ncount;

// scan block sums + single-pass sync words
__device__ int g_bs_deg [SCAN_NB];
__device__ int g_bs_mark[SCAN_NB];
__device__ int g_bs_need[SCAN_NB];
__device__ int g_scan_arrive;
__device__ int g_scan_ready;

// ---------------------------------------------------------------------------
__device__ __forceinline__ void split1(float v, __nv_bfloat16& h, __nv_bfloat16& l) {
    h = __float2bfloat16_rn(v);
    l = __float2bfloat16_rn(v - __bfloat162float(h));
}
__device__ __forceinline__ uint32_t pack2(__nv_bfloat16 lo, __nv_bfloat16 hi) {
    __nv_bfloat162 p;
    p.x = lo; p.y = hi;
    return *reinterpret_cast<uint32_t*>(&p);
}

// ---------------------------------------------------------------------------
// fused: convert all 3 weights + zero deg/mark/need + reset scan sync words
__global__ void convert_w_zero_kernel(const float* __restrict__ W1,
                                      const float* __restrict__ W2,
                                      const float* __restrict__ W3) {
    const int PER = AKP * (WB_NS / 4);
    int idx = blockIdx.x * blockDim.x + threadIdx.x;
    if (idx == 0) { g_scan_arrive = 0; g_scan_ready = 0; }
    if (idx < N_NODES) { g_deg[idx] = 0; g_mark[idx] = 0; g_need[idx] = 0; }
    if (idx >= 3 * PER) return;
    int wsel = idx / PER;
    int rem  = idx % PER;
    int kp = rem / (WB_NS / 4);
    int nq = rem % (WB_NS / 4);
    int Ncols = (wsel == 2) ? D_OUT : D_FEAT;
    const float* W = (wsel == 0) ? W1 : (wsel == 1) ? W2 : W3;
    uint32_t* outh = (wsel == 0) ? g_wb1_h : (wsel == 1) ? g_wb2_h : g_wb3_h;
    uint32_t* outl = (wsel == 0) ? g_wb1_l : (wsel == 1) ? g_wb2_l : g_wb3_l;
    int n0 = nq * 4;
    uint32_t oh[4], ol[4];
    #pragma unroll
    for (int j = 0; j < 4; j++) {
        int n = n0 + j;
        float v0 = 0.f, v1 = 0.f;
        if (2 * kp < D_FEAT && n < Ncols) {
            v0 = W[(size_t)(2 * kp) * Ncols + n];
            v1 = W[(size_t)(2 * kp + 1) * Ncols + n];
        }
        __nv_bfloat16 h0, l0, h1, l1;
        split1(v0, h0, l0);
        split1(v1, h1, l1);
        oh[j] = pack2(h0, h1);
        ol[j] = pack2(l0, l1);
    }
    size_t o = (size_t)kp * WB_NS + n0;
    *reinterpret_cast<uint4*>(outh + o) = make_uint4(oh[0], oh[1], oh[2], oh[3]);
    *reinterpret_cast<uint4*>(outl + o) = make_uint4(ol[0], ol[1], ol[2], ol[3]);
}

__global__ void csr_count_mark_kernel(const int* __restrict__ dst,
                                      const int* __restrict__ v1,
                                      const int* __restrict__ v2) {
    int e = blockIdx.x * blockDim.x + threadIdx.x;
    if (e < N_EDGES) atomicAdd(&g_deg[dst[e]], 1);
    if (e < N_PAIRS) {
        int a = v1[e], b = v2[e];
        g_mark[a] = 1; g_mark[b] = 1;
        g_need[a] = 1; g_need[b] = 1;
    }
}
__global__ void need_edge_kernel(const int* __restrict__ src,
                                 const int* __restrict__ dst) {
    int e = blockIdx.x * blockDim.x + threadIdx.x;
    if (e >= N_EDGES) return;
    if (g_mark[dst[e]]) g_need[src[e]] = 1;
}

// ---------------------------------------------------------------------------
// Single-pass triple scan (all SCAN_NB blocks co-resident; threadfence pattern).
__global__ void scan_all_kernel() {
    __shared__ int wt_d[8], wt_m[8], wt_n[8];
    __shared__ int s_islast;
    int tid = threadIdx.x, lane = tid & 31, w = tid >> 5;
    int i = blockIdx.x * SCAN_B + tid;
    int vd = (i < N_NODES) ? g_deg[i] : 0;
    int vm = (i < N_NODES) ? g_mark[i] : 0;
    int vn = (i < N_NODES) ? g_need[i] : 0;
    int sd = vd, sm = vm, sn = vn;
    #pragma unroll
    for (int o = 1; o < 32; o <<= 1) {
        int td = __shfl_up_sync(0xFFFFFFFFu, sd, o);
        int tm = __shfl_up_sync(0xFFFFFFFFu, sm, o);
        int tn = __shfl_up_sync(0xFFFFFFFFu, sn, o);
        if (lane >= o) { sd += td; sm += tm; sn += tn; }
    }
    if (lane == 31) { wt_d[w] = sd; wt_m[w] = sm; wt_n[w] = sn; }
    __syncthreads();
    if (w == 0) {
        int td = (lane < 8) ? wt_d[lane] : 0;
        int tm = (lane < 8) ? wt_m[lane] : 0;
        int tn = (lane < 8) ? wt_n[lane] : 0;
        int sd2 = td, sm2 = tm, sn2 = tn;
        #pragma unroll
        for (int o = 1; o < 8; o <<= 1) {
            int ud = __shfl_up_sync(0xFFFFFFFFu, sd2, o);
            int um = __shfl_up_sync(0xFFFFFFFFu, sm2, o);
            int un = __shfl_up_sync(0xFFFFFFFFu, sn2, o);
            if (lane >= o) { sd2 += ud; sm2 += um; sn2 += un; }
        }
        if (lane < 8) { wt_d[lane] = sd2 - td; wt_m[lane] = sm2 - tm; wt_n[lane] = sn2 - tn; }
    }
    __syncthreads();
    // local exclusive offsets within block (keep in regs)
    int ld = sd - vd + wt_d[w];
    int lm = sm - vm + wt_m[w];
    int ln = sn - vn + wt_n[w];
    // block totals published by last thread
    if (tid == SCAN_B - 1) {
        g_bs_deg[blockIdx.x]  = sd + wt_d[w];
        g_bs_mark[blockIdx.x] = sm + wt_m[w];
        g_bs_need[blockIdx.x] = sn + wt_n[w];
        __threadfence();
    }
    __syncthreads();
    if (tid == 0) {
        int old = atomicAdd(&g_scan_arrive, 1);
        s_islast = (old == SCAN_NB - 1);
    }
    __syncthreads();
    if (s_islast) {
        // exclusive-scan the SCAN_NB block totals in-place (256 thr >= 196)
        int bd = (tid < SCAN_NB) ? g_bs_deg[tid] : 0;
        int bmm = (tid < SCAN_NB) ? g_bs_mark[tid] : 0;
        int bnn = (tid < SCAN_NB) ? g_bs_need[tid] : 0;
        int cd = bd, cm = bmm, cn = bnn;
        #pragma unroll
        for (int o = 1; o < 32; o <<= 1) {
            int ud = __shfl_up_sync(0xFFFFFFFFu, cd, o);
            int um = __shfl_up_sync(0xFFFFFFFFu, cm, o);
            int un = __shfl_up_sync(0xFFFFFFFFu, cn, o);
            if (lane >= o) { cd += ud; cm += um; cn += un; }
        }
        __syncthreads();   // wt_* reuse safe
        if (lane == 31) { wt_d[w] = cd; wt_m[w] = cm; wt_n[w] = cn; }
        __syncthreads();
        if (w == 0) {
            int td = (lane < 8) ? wt_d[lane] : 0;
            int tm = (lane < 8) ? wt_m[lane] : 0;
            int tn = (lane < 8) ? wt_n[lane] : 0;
            int sd2 = td, sm2 = tm, sn2 = tn;
            #pragma unroll
            for (int o = 1; o < 8; o <<= 1) {
                int ud = __shfl_up_sync(0xFFFFFFFFu, sd2, o);
                int um = __shfl_up_sync(0xFFFFFFFFu, sm2, o);
                int un = __shfl_up_sync(0xFFFFFFFFu, sn2, o);
                if (lane >= o) { sd2 += ud; sm2 += um; sn2 += un; }
            }
            if (lane < 8) { wt_d[lane] = sd2 - td; wt_m[lane] = sm2 - tm; wt_n[lane] = sn2 - tn; }
        }
        __syncthreads();
        if (tid < SCAN_NB) {
            g_bs_deg[tid]  = cd - bd + wt_d[w];
            g_bs_mark[tid] = cm - bmm + wt_m[w];
            g_bs_need[tid] = cn - bnn + wt_n[w];
        }
        if (tid == SCAN_NB - 1) {
            g_count  = cm + wt_m[w];
            g_ncount = cn + wt_n[w];
        }
        __threadfence();
        __syncthreads();
        if (tid == 0) atomicExch(&g_scan_ready, 1);
    }
    // all blocks wait for offsets
    if (tid == 0) {
        while (atomicAdd(&g_scan_ready, 0) == 0) {}
    }
    __syncthreads();
    // volatile: bypass potentially-stale L1 lines from this block's own stores
    int bo_d = ((volatile int*)g_bs_deg)[blockIdx.x];
    int bo_m = ((volatile int*)g_bs_mark)[blockIdx.x];
    int bo_n = ((volatile int*)g_bs_need)[blockIdx.x];
    if (i < N_NODES) {
        int off_d = bo_d + ld;
        g_off[i] = off_d;
        g_pos[i] = off_d;
        g_newidx[i] = bo_m + lm;
        if (vm) g_list[bo_m + lm] = i;
        g_nidx[i] = bo_n + ln;
        if (vn) g_nlist[bo_n + ln] = i;
    }
}

__global__ void csr_fill_kernel(const int* __restrict__ src,
                                const int* __restrict__ dst) {
    int e = blockIdx.x * blockDim.x + threadIdx.x;
    if (e >= N_EDGES) return;
    int idx = atomicAdd(&g_pos[dst[e]], 1);
    g_srcs[idx] = src[e];
}

// ---------------------------------------------------------------------------
// gather core (unchanged)
__device__ __forceinline__ void gather_one(const float* __restrict__ x,
                                           int node, int outrow,
                                           int half, int lane, int remap) {
    int off = g_off[node];
    int deg = g_deg[node];

    int base4 = half * 46;
    int cnt   = half ? 45 : 46;
    int i0 = base4 + lane;
    int i1 = base4 + 32 + lane;
    bool p1 = (32 + lane) < cnt;

    int drow = remap ? g_nidx[node] : node;
    const float4* xd = reinterpret_cast<const float4*>(x + (size_t)drow * D_FEAT);
    float4 a0 = xd[i0];
    float4 a1 = p1 ? xd[i1] : make_float4(0.f, 0.f, 0.f, 0.f);

    for (int e = 0; e < deg; e++) {
        int s = g_srcs[off + e];
        int srow = remap ? g_nidx[s] : s;
        const float4* xs = reinterpret_cast<const float4*>(x + (size_t)srow * D_FEAT);
        float4 v0 = xs[i0];
        a0.x += v0.x; a0.y += v0.y; a0.z += v0.z; a0.w += v0.w;
        if (p1) {
            float4 v1 = xs[i1];
            a1.x += v1.x; a1.y += v1.y; a1.z += v1.z; a1.w += v1.w;
        }
    }

    uint32_t* oh = g_agg_h + (size_t)outrow * AKP;
    uint32_t* ol = g_agg_l + (size_t)outrow * AKP;
    {
        __nv_bfloat16 hx, lx, hy, ly, hz, lz, hw, lw;
        split1(a0.x, hx, lx); split1(a0.y, hy, ly);
        split1(a0.z, hz, lz); split1(a0.w, hw, lw);
        *reinterpret_cast<uint2*>(oh + 2 * i0) = make_uint2(pack2(hx, hy), pack2(hz, hw));
        *reinterpret_cast<uint2*>(ol + 2 * i0) = make_uint2(pack2(lx, ly), pack2(lz, lw));
    }
    if (p1) {
        __nv_bfloat16 hx, lx, hy, ly, hz, lz, hw, lw;
        split1(a1.x, hx, lx); split1(a1.y, hy, ly);
        split1(a1.z, hz, lz); split1(a1.w, hw, lw);
        *reinterpret_cast<uint2*>(oh + 2 * i1) = make_uint2(pack2(hx, hy), pack2(hz, hw));
        *reinterpret_cast<uint2*>(ol + 2 * i1) = make_uint2(pack2(lx, ly), pack2(lz, lw));
    }
    if (half && lane >= 13 && lane <= 17) {
        *reinterpret_cast<uint2*>(oh + 2 * i1) = make_uint2(0u, 0u);
        *reinterpret_cast<uint2*>(ol + 2 * i1) = make_uint2(0u, 0u);
    }
}

__global__ void gather_kernel(const float* __restrict__ x_ext) {
    int gw = (blockIdx.x * blockDim.x + threadIdx.x) >> 5;
    int lane = threadIdx.x & 31;
    int i = gw >> 1;
    int half = gw & 1;
    if (i >= g_ncount) return;
    gather_one(x_ext, g_nlist[i], i, half, lane, 0);
}
__global__ void gather2_kernel() {
    int gw = (blockIdx.x * blockDim.x + threadIdx.x) >> 5;
    int lane = threadIdx.x & 31;
    int i = gw >> 1;
    int half = gw & 1;
    if (i >= g_count) return;
    gather_one(g_h1, g_list[i], i, half, lane, 1);
}

// ---------------------------------------------------------------------------
__device__ __forceinline__ void mma16(float d[4], const uint32_t a[4], const uint32_t b[2]) {
    asm volatile(
        "mma.sync.aligned.m16n8k16.row.col.f32.bf16.bf16.f32 "
        "{%0,%1,%2,%3}, {%4,%5,%6,%7}, {%8,%9}, {%0,%1,%2,%3};\n"
        : "+f"(d[0]), "+f"(d[1]), "+f"(d[2]), "+f"(d[3])
        : "r"(a[0]), "r"(a[1]), "r"(a[2]), "r"(a[3]), "r"(b[0]), "r"(b[1]));
}
__device__ __forceinline__ void cp_async16(uint32_t smem_addr, const void* gptr, int src_bytes) {
    asm volatile("cp.async.cg.shared.global [%0], [%1], 16, %2;"
                 :: "r"(smem_addr), "l"(gptr), "r"(src_bytes) : "memory");
}
__device__ __forceinline__ void cp_async_commit() {
    asm volatile("cp.async.commit_group;" ::: "memory");
}
__device__ __forceinline__ void cp_async_wait0() {
    asm volatile("cp.async.wait_group 0;" ::: "memory");
}

// ---------------------------------------------------------------------------
#define TC_BM 128
#define TC_BN 128
#define AS2 36
#define BS2 136
#define A_U32 (TC_BM * AS2)
#define B_U32 (16 * BS2)
#define STAGE_U32 (2 * A_U32 + 2 * B_U32)   // 13568
#define NUM_KT 12

__global__ __launch_bounds__(256, 2) void gemm_nodes_tc(
        const float* __restrict__ bias, int m_mode) {
    const int N = D_FEAT;
    int M = m_mode ? g_count : g_ncount;
    const uint32_t* __restrict__ wb_h = m_mode ? g_wb2_h : g_wb1_h;
    const uint32_t* __restrict__ wb_l = m_mode ? g_wb2_l : g_wb1_l;

    int bm = blockIdx.y * TC_BM;
    if (bm >= M) return;
    int bn = blockIdx.x * TC_BN;

    extern __shared__ uint32_t smu[];
    uint32_t smem_base = (uint32_t)__cvta_generic_to_shared(smu);

    int tid = threadIdx.x;
    int lane = tid & 31;
    int wid = tid >> 5;
    int wm = (wid & 1) * 64;
    int wn = (wid >> 1) * 32;
    int r = lane >> 2;
    int c = lane & 3;

    float acc[4][4][4];
    #pragma unroll
    for (int i = 0; i < 4; i++)
        #pragma unroll
        for (int j = 0; j < 4; j++)
            #pragma unroll
            for (int q = 0; q < 4; q++) acc[i][j][q] = 0.f;

    int a_row = tid >> 2;
    int a_q4  = tid & 3;
    int b_kp = tid >> 5;
    int b_n4 = tid & 31;

    auto copy_tile = [&](int t, int stage) {
        int kp0 = t * 16;
        uint32_t sbase = smem_base + (uint32_t)(stage * STAGE_U32 * 4);
        uint32_t As_h = sbase;
        uint32_t As_l = sbase + (uint32_t)(A_U32 * 4);
        uint32_t Bs_h = sbase + (uint32_t)(2 * A_U32 * 4);
        uint32_t Bs_l = Bs_h + (uint32_t)(B_U32 * 4);
        #pragma unroll
        for (int p = 0; p < 2; p++) {
            int m = p * 64 + a_row;
            int gm = bm + m;
            int ok = (gm < M) ? 16 : 0;
            size_t go = (size_t)gm * AKP + kp0 + a_q4 * 4;
            uint32_t so = (uint32_t)((m * AS2 + a_q4 * 4) * 4);
            cp_async16(As_h + so, g_agg_h + go, ok);
            cp_async16(As_l + so, g_agg_l + go, ok);
        }
        #pragma unroll
        for (int p = 0; p < 2; p++) {
            int kp = p * 8 + b_kp;
            size_t go = (size_t)(kp0 + kp) * WB_NS + bn + b_n4 * 4;
            uint32_t so = (uint32_t)((kp * BS2 + b_n4 * 4) * 4);
            cp_async16(Bs_h + so, wb_h + go, 16);
            cp_async16(Bs_l + so, wb_l + go, 16);
        }
        cp_async_commit();
    };

    copy_tile(0, 0);
    cp_async_wait0();
    __syncthreads();

    for (int t = 0; t < NUM_KT; t++) {
        if (t + 1 < NUM_KT) copy_tile(t + 1, (t + 1) & 1);

        {
            const uint32_t* base = smu + (t & 1) * STAGE_U32;
            const uint32_t* As_h = base;
            const uint32_t* As_l = base + A_U32;
            const uint32_t* Bs_h = base + 2 * A_U32;
            const uint32_t* Bs_l = Bs_h + B_U32;

            #pragma unroll
            for (int kk = 0; kk < 2; kk++) {
                uint32_t ah[4][4], al[4][4], bh[4][2], bl[4][2];
                #pragma unroll
                for (int mt = 0; mt < 4; mt++) {
                    int row = wm + mt * 16 + r;
                    const uint32_t* ph = As_h + row * AS2 + kk * 8 + c;
                    const uint32_t* pl = As_l + row * AS2 + kk * 8 + c;
                    ah[mt][0] = ph[0];
                    ah[mt][1] = ph[8 * AS2];
                    ah[mt][2] = ph[4];
                    ah[mt][3] = ph[8 * AS2 + 4];
                    al[mt][0] = pl[0];
                    al[mt][1] = pl[8 * AS2];
                    al[mt][2] = pl[4];
                    al[mt][3] = pl[8 * AS2 + 4];
                }
                #pragma unroll
                for (int nt = 0; nt < 4; nt++) {
                    int col = wn + nt * 8 + r;
                    const uint32_t* qh = Bs_h + (kk * 8 + c) * BS2 + col;
                    const uint32_t* ql = Bs_l + (kk * 8 + c) * BS2 + col;
                    bh[nt][0] = qh[0];
                    bh[nt][1] = qh[4 * BS2];
                    bl[nt][0] = ql[0];
                    bl[nt][1] = ql[4 * BS2];
                }
                #pragma unroll
                for (int mt = 0; mt < 4; mt++)
                    #pragma unroll
                    for (int nt = 0; nt < 4; nt++) {
                        mma16(acc[mt][nt], ah[mt], bh[nt]);
                        mma16(acc[mt][nt], al[mt], bh[nt]);
                        mma16(acc[mt][nt], ah[mt], bl[nt]);
                    }
            }
        }

        if (t + 1 < NUM_KT) cp_async_wait0();
        __syncthreads();
    }

    #pragma unroll
    for (int mt = 0; mt < 4; mt++) {
        int gm0 = bm + wm + mt * 16 + r;
        #pragma unroll
        for (int nt = 0; nt < 4; nt++) {
            int gn = bn + wn + nt * 8 + 2 * c;
            if (m_mode == 0) {
                if (gn >= N) continue;
                float b0 = bias[gn], b1 = bias[gn + 1];
                float v0 = acc[mt][nt][0] + b0;
                float v1 = acc[mt][nt][1] + b1;
                float v2 = acc[mt][nt][2] + b0;
                float v3 = acc[mt][nt][3] + b1;
                v0 = v0 > 0.f ? v0 : NEG_SLOPE * v0;
                v1 = v1 > 0.f ? v1 : NEG_SLOPE * v1;
                v2 = v2 > 0.f ? v2 : NEG_SLOPE * v2;
                v3 = v3 > 0.f ? v3 : NEG_SLOPE * v3;
                if (gm0 < M)
                    *reinterpret_cast<float2*>(g_h1 + (size_t)gm0 * N + gn) = make_float2(v0, v1);
                if (gm0 + 8 < M)
                    *reinterpret_cast<float2*>(g_h1 + (size_t)(gm0 + 8) * N + gn) = make_float2(v2, v3);
            } else {
                bool valid = gn < N;
                float b0 = valid ? bias[gn] : 0.f;
                float b1 = valid ? bias[gn + 1] : 0.f;
                float v0 = valid ? acc[mt][nt][0] + b0 : 0.f;
                float v1 = valid ? acc[mt][nt][1] + b1 : 0.f;
                float v2 = valid ? acc[mt][nt][2] + b0 : 0.f;
                float v3 = valid ? acc[mt][nt][3] + b1 : 0.f;
                v0 = v0 > 0.f ? v0 : NEG_SLOPE * v0;
                v1 = v1 > 0.f ? v1 : NEG_SLOPE * v1;
                v2 = v2 > 0.f ? v2 : NEG_SLOPE * v2;
                v3 = v3 > 0.f ? v3 : NEG_SLOPE * v3;
                int kp = gn >> 1;
                if (gm0 < M) {
                    __nv_bfloat16 h0, l0, h1, l1;
                    split1(v0, h0, l0);
                    split1(v1, h1, l1);
                    g_p_h[(size_t)gm0 * AKP + kp] = pack2(h0, h1);
                    g_p_l[(size_t)gm0 * AKP + kp] = pack2(l0, l1);
                }
                if (gm0 + 8 < M) {
                    __nv_bfloat16 h2, l2, h3, l3;
                    split1(v2, h2, l2);
                    split1(v3, h3, l3);
                    g_p_h[(size_t)(gm0 + 8) * AKP + kp] = pack2(h2, h3);
                    g_p_l[(size_t)(gm0 + 8) * AKP + kp] = pack2(l2, l3);
                }
            }
        }
    }
}

// ---------------------------------------------------------------------------
// pairs GEMM + fused L2 normalize (unchanged from R16)
#define P_NT 20
#define PBS3 168
#define PB_U32 (16 * PBS3)
#define P_STAGE_U32 (2 * A_U32 + 2 * PB_U32)

__global__ __launch_bounds__(256) void gemm_pairs_norm(
        const int* __restrict__ v1, const int* __restrict__ v2,
        const float* __restrict__ bias, float* __restrict__ out) {
    const int N = D_OUT;

    int bm = blockIdx.x * TC_BM;

    extern __shared__ uint32_t smu[];
    uint32_t smem_base = (uint32_t)__cvta_generic_to_shared(smu);
    __shared__ int rows_sh[TC_BM];

    int tid = threadIdx.x;
    int lane = tid & 31;
    int wid = tid >> 5;
    int wm = wid * 16;
    int r = lane >> 2;
    int c = lane & 3;

    if (tid < TC_BM) {
        int gm = bm + tid;
        int v = (gm < N_PAIRS) ? v1[gm] : v2[gm - N_PAIRS];
        rows_sh[tid] = g_newidx[v];
    }
    __syncthreads();

    float acc[P_NT][4];
    #pragma unroll
    for (int j = 0; j < P_NT; j++)
        #pragma unroll
        for (int q = 0; q < 4; q++) acc[j][q] = 0.f;

    int a_row = tid >> 2;
    int a_q4  = tid & 3;

    auto copy_tile = [&](int t, int stage) {
        int kp0 = t * 16;
        uint32_t sbase = smem_base + (uint32_t)(stage * P_STAGE_U32 * 4);
        uint32_t As_h = sbase;
        uint32_t As_l = sbase + (uint32_t)(A_U32 * 4);
        uint32_t Bs_h = sbase + (uint32_t)(2 * A_U32 * 4);
        uint32_t Bs_l = Bs_h + (uint32_t)(PB_U32 * 4);
        #pragma unroll
        for (int p = 0; p < 2; p++) {
            int m = p * 64 + a_row;
            int row = rows_sh[m];
            size_t go = (size_t)row * AKP + kp0 + a_q4 * 4;
            uint32_t so = (uint32_t)((m * AS2 + a_q4 * 4) * 4);
            cp_async16(As_h + so, g_p_h + go, 16);
            cp_async16(As_l + so, g_p_l + go, 16);
        }
        for (int i = tid; i < 16 * 40; i += 256) {
            int kp = i / 40;
            int n4 = i % 40;
            size_t go = (size_t)(kp0 + kp) * WB_NS + n4 * 4;
            uint32_t so = (uint32_t)((kp * PBS3 + n4 * 4) * 4);
            cp_async16(Bs_h + so, g_wb3_h + go, 16);
            cp_async16(Bs_l + so, g_wb3_l + go, 16);
        }
        cp_async_commit();
    };

    copy_tile(0, 0);
    cp_async_wait0();
    __syncthreads();

    for (int t = 0; t < NUM_KT; t++) {
        if (t + 1 < NUM_KT) copy_tile(t + 1, (t + 1) & 1);

        {
            const uint32_t* base = smu + (t & 1) * P_STAGE_U32;
            const uint32_t* As_h = base;
            const uint32_t* As_l = base + A_U32;
            const uint32_t* Bs_h = base + 2 * A_U32;
            const uint32_t* Bs_l = Bs_h + PB_U32;

            #pragma unroll
            for (int kk = 0; kk < 2; kk++) {
                uint32_t ah[4], al[4];
                {
                    int row = wm + r;
                    const uint32_t* ph = As_h + row * AS2 + kk * 8 + c;
                    const uint32_t* pl = As_l + row * AS2 + kk * 8 + c;
                    ah[0] = ph[0];
                    ah[1] = ph[8 * AS2];
                    ah[2] = ph[4];
                    ah[3] = ph[8 * AS2 + 4];
                    al[0] = pl[0];
                    al[1] = pl[8 * AS2];
                    al[2] = pl[4];
                    al[3] = pl[8 * AS2 + 4];
                }
                #pragma unroll
                for (int nt = 0; nt < P_NT; nt++) {
                    int col = nt * 8 + r;
                    const uint32_t* qh = Bs_h + (kk * 8 + c) * PBS3 + col;
                    const uint32_t* ql = Bs_l + (kk * 8 + c) * PBS3 + col;
                    uint32_t bh[2], bl[2];
                    bh[0] = qh[0];
                    bh[1] = qh[4 * PBS3];
                    bl[0] = ql[0];
                    bl[1] = ql[4 * PBS3];
                    mma16(acc[nt], ah, bh);
                    mma16(acc[nt], al, bh);
                    mma16(acc[nt], ah, bl);
                }
            }
        }

        if (t + 1 < NUM_KT) cp_async_wait0();
        __syncthreads();
    }

    float ss0 = 0.f, ss8 = 0.f;
    #pragma unroll
    for (int nt = 0; nt < P_NT; nt++) {
        int gn = nt * 8 + 2 * c;
        bool valid = (gn + 1) < N;
        float b0 = valid ? bias[gn] : 0.f;
        float b1 = valid ? bias[gn + 1] : 0.f;
        float v0 = valid ? acc[nt][0] + b0 : 0.f;
        float v1 = valid ? acc[nt][1] + b1 : 0.f;
        float v2 = valid ? acc[nt][2] + b0 : 0.f;
        float v3 = valid ? acc[nt][3] + b1 : 0.f;
        v0 = v0 > 0.f ? v0 : NEG_SLOPE * v0;
        v1 = v1 > 0.f ? v1 : NEG_SLOPE * v1;
        v2 = v2 > 0.f ? v2 : NEG_SLOPE * v2;
        v3 = v3 > 0.f ? v3 : NEG_SLOPE * v3;
        acc[nt][0] = v0; acc[nt][1] = v1; acc[nt][2] = v2; acc[nt][3] = v3;
        ss0 += v0 * v0 + v1 * v1;
        ss8 += v2 * v2 + v3 * v3;
    }
    ss0 += __shfl_xor_sync(0xFFFFFFFFu, ss0, 1);
    ss0 += __shfl_xor_sync(0xFFFFFFFFu, ss0, 2);
    ss8 += __shfl_xor_sync(0xFFFFFFFFu, ss8, 1);
    ss8 += __shfl_xor_sync(0xFFFFFFFFu, ss8, 2);
    float inv0 = 1.f / fmaxf(sqrtf(ss0), 1e-12f);
    float inv8 = 1.f / fmaxf(sqrtf(ss8), 1e-12f);

    int gm0 = bm + wm + r;
    #pragma unroll
    for (int nt = 0; nt < P_NT; nt++) {
        int gn = nt * 8 + 2 * c;
        if (gn + 1 >= N) continue;
        *reinterpret_cast<float2*>(out + (size_t)gm0 * N + gn) =
            make_float2(acc[nt][0] * inv0, acc[nt][1] * inv0);
        *reinterpret_cast<float2*>(out + (size_t)(gm0 + 8) * N + gn) =
            make_float2(acc[nt][2] * inv8, acc[nt][3] * inv8);
    }
}

// ---------------------------------------------------------------------------
extern "C" void kernel_launch(void* const* d_in, const int* in_sizes, int n_in,
                              void* d_out, int out_size) {
    const float* features = (const float*)d_in[0];
    const int*   src      = (const int*)  d_in[1];
    const int*   dst      = (const int*)  d_in[2];
    const int*   v1       = (const int*)  d_in[3];
    const int*   v2       = (const int*)  d_in[4];
    const float* W1       = (const float*)d_in[5];
    const float* b1       = (const float*)d_in[6];
    const float* W2       = (const float*)d_in[7];
    const float* b2       = (const float*)d_in[8];
    const float* W3       = (const float*)d_in[9];
    const float* b3       = (const float*)d_in[10];
    float* out = (float*)d_out;
    (void)in_sizes; (void)n_in; (void)out_size;

    size_t tc_smem = (size_t)2 * STAGE_U32 * sizeof(uint32_t);        // 108544 B
    cudaFuncSetAttribute(gemm_nodes_tc, cudaFuncAttributeMaxDynamicSharedMemorySize,
                         (int)tc_smem);
    size_t p_smem = (size_t)2 * P_STAGE_U32 * sizeof(uint32_t);       // 116736 B
    cudaFuncSetAttribute(gemm_pairs_norm, cudaFuncAttributeMaxDynamicSharedMemorySize,
                         (int)p_smem);

    dim3 tc_grid1((D_FEAT + TC_BN - 1) / TC_BN, (N_NODES + TC_BM - 1) / TC_BM);
    dim3 tc_grid2((D_FEAT + TC_BN - 1) / TC_BN, (2 * N_PAIRS) / TC_BM);
    int pairs_grid = (2 * N_PAIRS) / TC_BM;
    int gather1_blocks = (N_NODES * 64 + 255) / 256;
    int gather2_blocks = (2 * N_PAIRS * 64 + 255) / 256;
    int convw_blocks = (3 * AKP * (WB_NS / 4) + 255) / 256;   // 216 blocks >= 196 for zeroing

    // fused weights-convert + zero + sync-word reset; then CSR + compactions
    convert_w_zero_kernel<<<convw_blocks, 256>>>(W1, W2, W3);
    csr_count_mark_kernel<<<(N_EDGES + 255) / 256, 256>>>(dst, v1, v2);
    need_edge_kernel<<<(N_EDGES + 255) / 256, 256>>>(src, dst);
    scan_all_kernel<<<SCAN_NB, SCAN_B>>>();
    csr_fill_kernel<<<(N_EDGES + 255) / 256, 256>>>(src, dst);

    // layer 1 (needed nodes) -> compact fp32 h1
    gather_kernel<<<gather1_blocks, 256>>>(features);
    gemm_nodes_tc<<<tc_grid1, 256, tc_smem>>>(b1, /*m_mode=*/0);

    // layer 2 (pair nodes) -> bf16-split h2
    gather2_kernel<<<gather2_blocks, 256>>>();
    gemm_nodes_tc<<<tc_grid2, 256, tc_smem>>>(b2, /*m_mode=*/1);

    // pair projection + fused normalize -> out
    gemm_pairs_norm<<<pairs_grid, 256, p_smem>>>(v1, v2, b3, out);
}